// round 8
// baseline (speedup 1.0000x reference)
#include <cuda_runtime.h>
#include <math.h>
#include <stdint.h>

// ---------------------------------------------------------------------------
// Problem constants
// ---------------------------------------------------------------------------
constexpr int Bn = 8, Cc = 96, Dd = 8, Hh = 32, Ww = 32;
constexpr int HW = Hh * Ww;          // 1024
constexpr int DIM = Cc * Dd;         // 768
constexpr int NH = 4;
constexpr int DHd = DIM / NH;        // 192
constexpr int SEQROWS = Bn * HW;     // 8192
constexpr int BH = Bn * NH;          // 32

// ---------------------------------------------------------------------------
// Scratch (device globals -- no allocations allowed)
// ---------------------------------------------------------------------------
__device__ float g_t[SEQROWS * DIM];
__device__ float g_wq[3 * DIM * DIM];                   // qkv_w, tf32-rounded
__device__ float g_wp[DIM * DIM];                       // proj_w, tf32-rounded
__device__ float g_q[BH * HW * DHd];
__device__ float g_k[BH * HW * DHd];
__device__ float g_vt[BH * DHd * HW];                   // V transposed: [z][dh][seq]
__device__ float g_om[SEQROWS * DIM];
__device__ float g_proj[SEQROWS * DIM];
__device__ float g_y[Bn * Cc * Dd * HW];
__device__ float g_z[Bn * Cc * Dd * HW];
__device__ float g_inv[2 * BH * DHd];                   // l2norm 1/||.||
__device__ float g_mu[SEQROWS];
__device__ float g_rs[SEQROWS];

// ---------------------------------------------------------------------------
// Helpers (baseline PTX only)
// ---------------------------------------------------------------------------
__device__ __forceinline__ uint32_t f2tf(float x) {
    uint32_t r; asm("cvt.rna.tf32.f32 %0, %1;" : "=r"(r) : "f"(x)); return r;
}
__device__ __forceinline__ float tfr(float x) { return __uint_as_float(f2tf(x)); }
__device__ __forceinline__ void mma_tf32(float* d, const uint32_t* a,
                                         const uint32_t* b) {
    asm volatile(
        "mma.sync.aligned.m16n8k8.row.col.f32.tf32.tf32.f32 "
        "{%0,%1,%2,%3}, {%4,%5,%6,%7}, {%8,%9}, {%0,%1,%2,%3};"
        : "+f"(d[0]), "+f"(d[1]), "+f"(d[2]), "+f"(d[3])
        : "r"(a[0]), "r"(a[1]), "r"(a[2]), "r"(a[3]), "r"(b[0]), "r"(b[1]));
}
__device__ __forceinline__ void cp_async16(uint32_t dst, const void* src) {
    asm volatile("cp.async.cg.shared.global [%0], [%1], 16;"
                 :: "r"(dst), "l"(src) : "memory");
}
__device__ __forceinline__ void cp_commit() {
    asm volatile("cp.async.commit_group;" ::: "memory");
}
template <int N>
__device__ __forceinline__ void cp_wait() {
    asm volatile("cp.async.wait_group %0;" :: "n"(N) : "memory");
}

// ---------------------------------------------------------------------------
// tf32 GEMM for QKV / PROJ:  C[M,N] = A[M,K] * B[N,K]^T, K=768.
// Block tile 128 x 256 x 32, 512 threads, warp tile 32x64, 3-stage cp.async.
// MODE 0: QKV   A=g_t(8192,768)  B=g_wq(2304,768)  -> scatter q/k/vt via smem
// MODE 3: PROJ  A=g_om(8192,768) B=g_wp(768,768)   -> g_proj (+bias)
// ---------------------------------------------------------------------------
template <int MODE>
__global__ __launch_bounds__(512, 1) void tc_gemm(const float* __restrict__ bias) {
    constexpr int BK  = 32;
    constexpr int NB  = 256;
    constexpr int KK  = 768;
    constexpr int LD  = 768;
    constexpr int T   = KK / BK;
    constexpr int AW  = 128 * BK;            // 4096 words
    constexpr int BWD = NB * BK;             // 8192 words
    constexpr int STG = AW + BWD;
    constexpr int WN  = 64;
    constexpr int NT  = 8;

    extern __shared__ float sm[];
    const uint32_t smBase = (uint32_t)__cvta_generic_to_shared(sm);

    const int tid  = threadIdx.x;
    const int lane = tid & 31;
    const int w    = tid >> 5;
    const int wm   = w & 3;
    const int wn   = w >> 2;
    const int q    = lane >> 2;
    const int lq   = lane & 3;
    const int m0   = blockIdx.y * 128;
    const int n0   = blockIdx.x * NB;

    const float* gA = (MODE == 0) ? g_t  : g_om;
    const float* gB = (MODE == 0) ? g_wq : g_wp;

    const float* aRow = gA + (size_t)m0 * LD;
    const float* bRow = gB + (size_t)n0 * LD;

    auto loadStage = [&](int it, int s) {
        const float* aP = aRow + it * BK;
        const float* bP = bRow + it * BK;
        uint32_t sA = smBase + (uint32_t)(s * STG) * 4u;
        uint32_t sB = sA + AW * 4u;
#pragma unroll
        for (int i = 0; i < 2; i++) {
            int idx = tid + 512 * i;
            int r = idx >> 3, c4 = idx & 7;
            uint32_t dst = sA + (uint32_t)(r * 32 + ((c4 * 4) ^ (4 * (r & 7)))) * 4u;
            cp_async16(dst, aP + (size_t)r * LD + c4 * 4);
        }
#pragma unroll
        for (int i = 0; i < 4; i++) {
            int idx = tid + 512 * i;
            int r = idx >> 3, c4 = idx & 7;
            uint32_t dst = sB + (uint32_t)(r * 32 + ((c4 * 4) ^ (4 * (r & 7)))) * 4u;
            cp_async16(dst, bP + (size_t)r * LD + c4 * 4);
        }
    };

    float acc[2][NT][4];
#pragma unroll
    for (int mt = 0; mt < 2; mt++)
#pragma unroll
        for (int nt = 0; nt < NT; nt++)
#pragma unroll
            for (int k = 0; k < 4; k++) acc[mt][nt][k] = 0.f;

#pragma unroll
    for (int s = 0; s < 3; s++) { loadStage(s, s); cp_commit(); }

    const int sw = 4 * q;

    for (int it = 0; it < T; ++it) {
        cp_wait<2>();
        __syncthreads();

        const int st = it % 3;
        const uint32_t* A_ = reinterpret_cast<const uint32_t*>(sm + st * STG);
        const uint32_t* B_ = A_ + AW;
#pragma unroll
        for (int ks = 0; ks < 4; ks++) {
            const int k0 = ks * 8;
            const int c0 = (k0 + lq) ^ sw;
            const int c1 = (k0 + 4 + lq) ^ sw;
            uint32_t a[2][4];
#pragma unroll
            for (int mt = 0; mt < 2; mt++) {
                int rb = (wm * 32 + mt * 16 + q) * 32;
                a[mt][0] = A_[rb + c0];
                a[mt][1] = A_[rb + 256 + c0];
                a[mt][2] = A_[rb + c1];
                a[mt][3] = A_[rb + 256 + c1];
            }
            uint32_t b[NT][2];
#pragma unroll
            for (int nt = 0; nt < NT; nt++) {
                int nb = (wn * WN + nt * 8 + q) * 32;
                b[nt][0] = B_[nb + c0];
                b[nt][1] = B_[nb + c1];
            }
#pragma unroll
            for (int mt = 0; mt < 2; mt++)
#pragma unroll
                for (int nt = 0; nt < NT; nt++)
                    mma_tf32(acc[mt][nt], a[mt], b[nt]);
        }
        __syncthreads();
        if (it + 3 < T) loadStage(it + 3, st);
        cp_commit();
    }

    // ---------------- epilogue ----------------
    if constexpr (MODE == 3) {
#pragma unroll
        for (int mt = 0; mt < 2; mt++)
#pragma unroll
            for (int nt = 0; nt < NT; nt++) {
                int r = m0 + wm * 32 + mt * 16 + q;
                int c = n0 + wn * WN + nt * 8 + lq * 2;
                float2 bb = *reinterpret_cast<const float2*>(bias + c);
                float2 v0 = {acc[mt][nt][0] + bb.x, acc[mt][nt][1] + bb.y};
                float2 v1 = {acc[mt][nt][2] + bb.x, acc[mt][nt][3] + bb.y};
                *reinterpret_cast<float2*>(g_proj + (size_t)r * DIM + c) = v0;
                *reinterpret_cast<float2*>(g_proj + (size_t)(r + 8) * DIM + c) = v1;
            }
    } else {
        // stage C tile (128 x 256) in smem with stride 257 (odd -> scalar
        // stores only; float2 at odd word stride traps on misalignment)
        constexpr int LDO = 257;
        float* stg = sm;
        __syncthreads();
#pragma unroll
        for (int mt = 0; mt < 2; mt++)
#pragma unroll
            for (int nt = 0; nt < NT; nt++) {
                int r = wm * 32 + mt * 16 + q;
                int c = wn * WN + nt * 8 + lq * 2;
                stg[r * LDO + c]           = acc[mt][nt][0];
                stg[r * LDO + c + 1]       = acc[mt][nt][1];
                stg[(r + 8) * LDO + c]     = acc[mt][nt][2];
                stg[(r + 8) * LDO + c + 1] = acc[mt][nt][3];
            }
        __syncthreads();
        const int s0 = n0 / 768;                 // 0=q, 1=k, 2=v
        if (s0 == 2) {
            // g_vt[z][dh][seq]: iterate rows fastest -> consecutive seq
            for (int idx = tid; idx < 128 * 256; idx += 512) {
                int r = idx & 127, c = idx >> 7;
                int m = m0 + r, b = m >> 10, seq = m & 1023;
                int nl = n0 - 1536 + c;
                int h = nl / 192, dh = nl % 192;
                g_vt[((size_t)(b * 4 + h) * 192 + dh) * 1024 + seq] =
                    tfr(stg[r * LDO + c]);
            }
        } else {
            float* dst = (s0 == 0) ? g_q : g_k;
            for (int idx = tid; idx < 128 * 256; idx += 512) {
                int c = idx & 255, r = idx >> 8;
                int m = m0 + r, b = m >> 10, seq = m & 1023;
                int nl = n0 - s0 * 768 + c;
                int h = nl / 192, dh = nl % 192;
                dst[((size_t)(b * 4 + h) * 1024 + seq) * 192 + dh] = stg[r * LDO + c];
            }
        }
    }
}

// ---------------------------------------------------------------------------
// Flash attention: per CTA 64 query rows x one (b,h). 512 threads, 16 warps
// (wm 2 x wn 8). Phase 1: S = Q K^T (warp tile 32x16); online softmax;
// P -> smem (tf32); Phase 2: O += P V (warp tile 32x24). cp.async chain with
// 3 rotating KV buffers, prefetch depth 2, unconditional commits.
// smem words: Q 6*2048 | KV 3*6144 | P 4*2048 | red 512  = 39424 (154 KB)
// ---------------------------------------------------------------------------
constexpr int FS_Q   = 0;
constexpr int FS_KV  = 12288;
constexpr int FS_P   = 30720;
constexpr int FS_RED = 38912;
constexpr int FS_TOT = 39424;

__global__ __launch_bounds__(512, 1) void flash_attn(const float* __restrict__ temp) {
    extern __shared__ float sm[];
    const uint32_t smBase = (uint32_t)__cvta_generic_to_shared(sm);

    const int tid  = threadIdx.x;
    const int lane = tid & 31;
    const int w    = tid >> 5;       // 0..15
    const int wm   = w & 1;
    const int wn   = w >> 1;         // 0..7
    const int q    = lane >> 2;
    const int lq   = lane & 3;
    const int z    = blockIdx.y;
    const int m0   = blockIdx.x * 64;

    const float* Qz = g_q  + (size_t)z * HW * DHd;
    const float* Kz = g_k  + (size_t)z * HW * DHd;
    const float* Vz = g_vt + (size_t)z * DHd * HW;
    const float ts = temp[z & 3];

    // Q load: 6 panels [64][32] swizzled (3072 float4)
#pragma unroll
    for (int i = 0; i < 6; i++) {
        int idx = tid + 512 * i;
        int c4 = idx & 7, r = (idx >> 3) & 63, p = idx >> 9;
        uint32_t dst = smBase + (uint32_t)(FS_Q + p * 2048 + r * 32 +
                                           ((c4 * 4) ^ (4 * (r & 7)))) * 4u;
        cp_async16(dst, Qz + (size_t)(m0 + r) * 192 + p * 32 + c4 * 4);
    }
    cp_commit();

    auto issuePanel = [&](int g) {
        int t = g / 10, i = g % 10, buf = g % 3;
        uint32_t base = smBase + (uint32_t)(FS_KV + buf * 6144) * 4u;
        if (i < 6) {               // K panel: 128 rows x 32 dh (1024 float4)
#pragma unroll
            for (int j = 0; j < 2; j++) {
                int idx = tid + 512 * j;
                int c4 = idx & 7, r = idx >> 3;
                cp_async16(base + (uint32_t)(r * 32 + ((c4 * 4) ^ (4 * (r & 7)))) * 4u,
                           Kz + (size_t)(t * 128 + r) * 192 + i * 32 + c4 * 4);
            }
        } else {                   // V panel: 192 dh rows x 32 keys (1536 float4)
            int pv = i - 6;
#pragma unroll
            for (int j = 0; j < 3; j++) {
                int idx = tid + 512 * j;
                int c4 = idx & 7, r = idx >> 3;
                cp_async16(base + (uint32_t)(r * 32 + ((c4 * 4) ^ (4 * (r & 7)))) * 4u,
                           Vz + (size_t)r * 1024 + t * 128 + pv * 32 + c4 * 4);
            }
        }
    };
    issuePanel(0); cp_commit();
    issuePanel(1); cp_commit();

    constexpr float L2E = 1.4426950408889634f;
    float m_run[2][2] = {{-1e30f, -1e30f}, {-1e30f, -1e30f}};
    float l_run[2][2] = {{0.f, 0.f}, {0.f, 0.f}};
    float acc_o[2][3][4];
#pragma unroll
    for (int mt = 0; mt < 2; mt++)
#pragma unroll
        for (int nt = 0; nt < 3; nt++)
#pragma unroll
            for (int k = 0; k < 4; k++) acc_o[mt][nt][k] = 0.f;

    const int sw = 4 * q;
    float* sRed = sm + FS_RED;

    for (int t = 0; t < 8; t++) {
        float acc_s[2][2][4];
#pragma unroll
        for (int mt = 0; mt < 2; mt++)
#pragma unroll
            for (int nt = 0; nt < 2; nt++)
#pragma unroll
                for (int k = 0; k < 4; k++) acc_s[mt][nt][k] = 0.f;

        // ---------- phase 1: S = Q K^T ----------
        for (int p = 0; p < 6; p++) {
            int g = t * 10 + p;
            cp_wait<1>();
            __syncthreads();
            if (g + 2 < 80) issuePanel(g + 2);
            cp_commit();
            const uint32_t* Ap = reinterpret_cast<const uint32_t*>(sm + FS_Q + p * 2048);
            const uint32_t* Bp = reinterpret_cast<const uint32_t*>(sm + FS_KV + (g % 3) * 6144);
#pragma unroll
            for (int ks = 0; ks < 4; ks++) {
                const int c0 = (ks * 8 + lq) ^ sw;
                const int c1 = (ks * 8 + 4 + lq) ^ sw;
                uint32_t a[2][4];
#pragma unroll
                for (int mt = 0; mt < 2; mt++) {
                    int rb = (wm * 32 + mt * 16 + q) * 32;
                    a[mt][0] = Ap[rb + c0];
                    a[mt][1] = Ap[rb + 256 + c0];
                    a[mt][2] = Ap[rb + c1];
                    a[mt][3] = Ap[rb + 256 + c1];
                }
#pragma unroll
                for (int nt = 0; nt < 2; nt++) {
                    uint32_t b[2];
                    int nb = (wn * 16 + nt * 8 + q) * 32;
                    b[0] = Bp[nb + c0];
                    b[1] = Bp[nb + c1];
#pragma unroll
                    for (int mt = 0; mt < 2; mt++)
                        mma_tf32(acc_s[mt][nt], a[mt], b);
                }
            }
        }

        // ---------- online softmax ----------
        float tmax[2][2], corr[2][2], rsum[2][2];
        {
            float rmax[2][2] = {{-1e30f, -1e30f}, {-1e30f, -1e30f}};
#pragma unroll
            for (int mt = 0; mt < 2; mt++)
#pragma unroll
                for (int nt = 0; nt < 2; nt++)
#pragma unroll
                    for (int j = 0; j < 4; j++) {
                        float v = acc_s[mt][nt][j] * ts;
                        acc_s[mt][nt][j] = v;
                        rmax[mt][j >> 1] = fmaxf(rmax[mt][j >> 1], v);
                    }
#pragma unroll
            for (int mt = 0; mt < 2; mt++)
#pragma unroll
                for (int h2 = 0; h2 < 2; h2++) {
                    float v = rmax[mt][h2];
                    v = fmaxf(v, __shfl_xor_sync(0xFFFFFFFF, v, 1));
                    v = fmaxf(v, __shfl_xor_sync(0xFFFFFFFF, v, 2));
                    rmax[mt][h2] = v;
                }
            if (lq == 0) {
#pragma unroll
                for (int mt = 0; mt < 2; mt++)
#pragma unroll
                    for (int h2 = 0; h2 < 2; h2++)
                        sRed[wn * 64 + wm * 32 + mt * 16 + q + h2 * 8] = rmax[mt][h2];
            }
            __syncthreads();
#pragma unroll
            for (int mt = 0; mt < 2; mt++)
#pragma unroll
                for (int h2 = 0; h2 < 2; h2++) {
                    int rr = wm * 32 + mt * 16 + q + h2 * 8;
                    float v = sRed[rr];
#pragma unroll
                    for (int ww = 1; ww < 8; ww++) v = fmaxf(v, sRed[ww * 64 + rr]);
                    tmax[mt][h2] = v;
                }
        }
#pragma unroll
        for (int mt = 0; mt < 2; mt++)
#pragma unroll
            for (int h2 = 0; h2 < 2; h2++) {
                float nm = fmaxf(m_run[mt][h2], tmax[mt][h2]);
                corr[mt][h2] = exp2f((m_run[mt][h2] - nm) * L2E);
                m_run[mt][h2] = nm;
                rsum[mt][h2] = 0.f;
            }
#pragma unroll
        for (int mt = 0; mt < 2; mt++)
#pragma unroll
            for (int nt = 0; nt < 2; nt++)
#pragma unroll
                for (int j = 0; j < 4; j++) {
                    float pv = exp2f((acc_s[mt][nt][j] - m_run[mt][j >> 1]) * L2E);
                    acc_s[mt][nt][j] = pv;
                    rsum[mt][j >> 1] += pv;
                }
#pragma unroll
        for (int mt = 0; mt < 2; mt++)
#pragma unroll
            for (int h2 = 0; h2 < 2; h2++) {
                float v = rsum[mt][h2];
                v += __shfl_xor_sync(0xFFFFFFFF, v, 1);
                v += __shfl_xor_sync(0xFFFFFFFF, v, 2);
                rsum[mt][h2] = v;
            }
        __syncthreads();                       // sRed reuse (max -> sum)
        if (lq == 0) {
#pragma unroll
            for (int mt = 0; mt < 2; mt++)
#pragma unroll
                for (int h2 = 0; h2 < 2; h2++)
                    sRed[wn * 64 + wm * 32 + mt * 16 + q + h2 * 8] = rsum[mt][h2];
        }
        __syncthreads();
#pragma unroll
        for (int mt = 0; mt < 2; mt++)
#pragma unroll
            for (int h2 = 0; h2 < 2; h2++) {
                int rr = wm * 32 + mt * 16 + q + h2 * 8;
                float tsum = sRed[rr];
#pragma unroll
                for (int ww = 1; ww < 8; ww++) tsum += sRed[ww * 64 + rr];
                l_run[mt][h2] = l_run[mt][h2] * corr[mt][h2] + tsum;
            }
        // rescale O
#pragma unroll
        for (int mt = 0; mt < 2; mt++)
#pragma unroll
            for (int nt = 0; nt < 3; nt++) {
                acc_o[mt][nt][0] *= corr[mt][0];
                acc_o[mt][nt][1] *= corr[mt][0];
                acc_o[mt][nt][2] *= corr[mt][1];
                acc_o[mt][nt][3] *= corr[mt][1];
            }
        // store P (tf32): panel pv = wn>>1, in-panel col (wn&1)*16 + nt*8 + 2lq
#pragma unroll
        for (int mt = 0; mt < 2; mt++)
#pragma unroll
            for (int nt = 0; nt < 2; nt++) {
                int r0 = wm * 32 + mt * 16 + q;
                int c  = (wn & 1) * 16 + nt * 8 + 2 * lq;
                float2 p0 = {__uint_as_float(f2tf(acc_s[mt][nt][0])),
                             __uint_as_float(f2tf(acc_s[mt][nt][1]))};
                float2 p1 = {__uint_as_float(f2tf(acc_s[mt][nt][2])),
                             __uint_as_float(f2tf(acc_s[mt][nt][3]))};
                float* pp = sm + FS_P + (wn >> 1) * 2048;
                *reinterpret_cast<float2*>(pp + r0 * 32 + (c ^ sw)) = p0;
                *reinterpret_cast<float2*>(pp + (r0 + 8) * 32 + (c ^ sw)) = p1;
            }
        __syncthreads();

        // ---------- phase 2: O += P V ----------
        for (int pv = 0; pv < 4; pv++) {
            int g = t * 10 + 6 + pv;
            cp_wait<1>();
            __syncthreads();
            if (g + 2 < 80) issuePanel(g + 2);
            cp_commit();
            const uint32_t* Ap = reinterpret_cast<const uint32_t*>(sm + FS_P + pv * 2048);
            const uint32_t* Bp = reinterpret_cast<const uint32_t*>(sm + FS_KV + (g % 3) * 6144);
#pragma unroll
            for (int ks = 0; ks < 4; ks++) {
                const int c0 = (ks * 8 + lq) ^ sw;
                const int c1 = (ks * 8 + 4 + lq) ^ sw;
                uint32_t a[2][4];
#pragma unroll
                for (int mt = 0; mt < 2; mt++) {
                    int rb = (wm * 32 + mt * 16 + q) * 32;
                    a[mt][0] = Ap[rb + c0];
                    a[mt][1] = Ap[rb + 256 + c0];
                    a[mt][2] = Ap[rb + c1];
                    a[mt][3] = Ap[rb + 256 + c1];
                }
#pragma unroll
                for (int nt = 0; nt < 3; nt++) {
                    uint32_t b[2];
                    int nb = (wn * 24 + nt * 8 + q) * 32;
                    b[0] = Bp[nb + c0];
                    b[1] = Bp[nb + c1];
#pragma unroll
                    for (int mt = 0; mt < 2; mt++)
                        mma_tf32(acc_o[mt][nt], a[mt], b);
                }
            }
        }
    }

    // ---------- epilogue: O /= l, merged-head store ----------
    int b = z >> 2, h = z & 3;
    float inv[2][2];
#pragma unroll
    for (int mt = 0; mt < 2; mt++)
#pragma unroll
        for (int h2 = 0; h2 < 2; h2++) inv[mt][h2] = 1.f / l_run[mt][h2];
#pragma unroll
    for (int mt = 0; mt < 2; mt++)
#pragma unroll
        for (int nt = 0; nt < 3; nt++) {
            int rl = wm * 32 + mt * 16 + q;
            int col = wn * 24 + nt * 8 + 2 * lq;
            float2 v0 = {tfr(acc_o[mt][nt][0] * inv[mt][0]),
                         tfr(acc_o[mt][nt][1] * inv[mt][0])};
            float2 v1 = {tfr(acc_o[mt][nt][2] * inv[mt][1]),
                         tfr(acc_o[mt][nt][3] * inv[mt][1])};
            *reinterpret_cast<float2*>(
                g_om + ((size_t)(b * HW + m0 + rl)) * DIM + h * DHd + col) = v0;
            *reinterpret_cast<float2*>(
                g_om + ((size_t)(b * HW + m0 + rl + 8)) * DIM + h * DHd + col) = v1;
        }
}

// ---------------------------------------------------------------------------
// Producers / elementwise
// ---------------------------------------------------------------------------
__global__ void permute_t(const float* __restrict__ x,
                          const float* __restrict__ pos) {
    __shared__ float tile[32][33];
    int bz = blockIdx.z, hw0 = blockIdx.y * 32, cd0 = blockIdx.x * 32;
    int tx = threadIdx.x, ty = threadIdx.y;
#pragma unroll
    for (int k = 0; k < 4; k++) {
        int cd = cd0 + ty + 8 * k;
        tile[ty + 8 * k][tx] = x[((size_t)bz * 768 + cd) * 1024 + hw0 + tx];
    }
    __syncthreads();
#pragma unroll
    for (int k = 0; k < 4; k++) {
        int hw = hw0 + ty + 8 * k;
        int cd = cd0 + tx;
        g_t[((size_t)bz * 1024 + hw) * 768 + cd] =
            tfr(tile[tx][ty + 8 * k] + pos[(size_t)hw * 768 + cd]);
    }
}

__global__ void cvt_weights(const float* __restrict__ qkv_w,
                            const float* __restrict__ proj_w) {
    int i = blockIdx.x * 256 + threadIdx.x;
    if (i < 3 * DIM * DIM) g_wq[i] = tfr(qkv_w[i]);
    if (i < DIM * DIM)     g_wp[i] = tfr(proj_w[i]);
}

// l2 norm over seq axis: one block per (which,z), 384 threads (2 halves x 192)
__global__ void l2_norm1() {
    __shared__ float red[192];
    int which = blockIdx.x >> 5, z = blockIdx.x & 31;
    const float* p = (which ? g_k : g_q) + (size_t)z * HW * DHd;
    int col = threadIdx.x % 192, half = threadIdx.x / 192;
    float ss = 0.f;
    int r0 = half * 512;
#pragma unroll 4
    for (int r = r0; r < r0 + 512; r++) {
        float v = p[(size_t)r * DHd + col];
        ss += v * v;
    }
    if (half == 1) red[col] = ss;
    __syncthreads();
    if (half == 0) {
        float tot = ss + red[col];
        g_inv[((size_t)which * BH + z) * DHd + col] =
            1.f / fmaxf(sqrtf(tot), 1e-12f);
    }
}

__global__ void l2_scale() {
    int which = blockIdx.z, z = blockIdx.y;
    int i = blockIdx.x * 256 + threadIdx.x;
    int seq = i / 48, c4 = i % 48;
    float* p = (which ? g_k : g_q) + ((size_t)z * HW + seq) * DHd + c4 * 4;
    float4 v  = *reinterpret_cast<float4*>(p);
    float4 iv = *reinterpret_cast<const float4*>(g_inv + ((size_t)which * BH + z) * DHd + c4 * 4);
    v.x = tfr(v.x * iv.x); v.y = tfr(v.y * iv.y);
    v.z = tfr(v.z * iv.z); v.w = tfr(v.w * iv.w);
    *reinterpret_cast<float4*>(p) = v;
}

__global__ void ln_stats() {
    __shared__ float red[256];
    int row = blockIdx.x;
    int tid = threadIdx.x;
    const float* basep = g_proj + (size_t)row * DIM;

    float v[3];
    float s = 0.f;
#pragma unroll
    for (int j = 0; j < 3; j++) { v[j] = basep[tid + 256 * j]; s += v[j]; }
    red[tid] = s; __syncthreads();
    for (int st = 128; st > 0; st >>= 1) {
        if (tid < st) red[tid] += red[tid + st];
        __syncthreads();
    }
    float mu = red[0] * (1.f / DIM); __syncthreads();

    float s2 = 0.f;
#pragma unroll
    for (int j = 0; j < 3; j++) { float d = v[j] - mu; s2 += d * d; }
    red[tid] = s2; __syncthreads();
    for (int st = 128; st > 0; st >>= 1) {
        if (tid < st) red[tid] += red[tid + st];
        __syncthreads();
    }
    if (tid == 0) {
        g_mu[row] = mu;
        g_rs[row] = rsqrtf(red[0] * (1.f / DIM) + 1e-5f);
    }
}

__global__ void ln_apply(const float* __restrict__ x,
                         const float* __restrict__ gamma,
                         const float* __restrict__ beta) {
    __shared__ float tile[32][33];
    int bz = blockIdx.z, hw0 = blockIdx.y * 32, cd0 = blockIdx.x * 32;
    int tx = threadIdx.x, ty = threadIdx.y;
#pragma unroll
    for (int k = 0; k < 4; k++) {
        int hw = hw0 + ty + 8 * k;
        int row = bz * 1024 + hw;
        int cd = cd0 + tx;
        float v = g_proj[(size_t)row * 768 + cd];
        tile[ty + 8 * k][tx] = (v - g_mu[row]) * g_rs[row] * gamma[cd] + beta[cd];
    }
    __syncthreads();
#pragma unroll
    for (int k = 0; k < 4; k++) {
        int cd = cd0 + ty + 8 * k;
        int hw = hw0 + tx;
        size_t oi = ((size_t)bz * 768 + cd) * 1024 + hw;
        g_y[oi] = tile[tx][ty + 8 * k] + x[oi];
    }
}

__global__ __launch_bounds__(1024) void dwconv(const float* __restrict__ dw_w,
                                               const float* __restrict__ dw_b) {
    __shared__ float tile[3][34][34];
    __shared__ float wsh[27];
    int bcd = blockIdx.x;
    int d  = bcd & 7;
    int bc = bcd >> 3;
    int c  = bc % Cc;
    int tid = threadIdx.x;

    if (tid < 27) wsh[tid] = dw_w[c * 27 + tid];

    for (int idx = tid; idx < 3 * 34 * 34; idx += 1024) {
        int pl = idx / 1156;
        int r  = (idx - pl * 1156) / 34;
        int cc = idx - pl * 1156 - r * 34;
        int dd = d - 1 + pl, hh = r - 1, ww = cc - 1;
        float val = 0.f;
        if (dd >= 0 && dd < Dd && hh >= 0 && hh < Hh && ww >= 0 && ww < Ww)
            val = g_y[(bc * Dd + dd) * HW + hh * Ww + ww];
        tile[pl][r][cc] = val;
    }
    __syncthreads();

    int h = tid >> 5, w = tid & 31;
    float s = 0.f;
#pragma unroll
    for (int pl = 0; pl < 3; pl++)
#pragma unroll
        for (int i = 0; i < 3; i++)
#pragma unroll
            for (int j = 0; j < 3; j++)
                s += tile[pl][h + i][w + j] * wsh[pl * 9 + i * 3 + j];
    g_z[bcd * HW + tid] = s + dw_b[c];
}

__global__ __launch_bounds__(128) void pwconv(const float* __restrict__ pw_w,
                                              const float* __restrict__ pw_b,
                                              float* __restrict__ out) {
    __shared__ float wsh[Cc * Cc];
    int b = blockIdx.y;
    int pos = blockIdx.x * 128 + threadIdx.x;
    constexpr int SP = Dd * HW;

    for (int i = threadIdx.x; i < Cc * Cc; i += 128) wsh[i] = pw_w[i];
    __syncthreads();

    float acc[Cc];
#pragma unroll
    for (int co = 0; co < Cc; co++) acc[co] = 0.f;

    const float* zb = g_z + b * Cc * SP + pos;
    for (int ci = 0; ci < Cc; ci++) {
        float zv = zb[ci * SP];
#pragma unroll
        for (int co = 0; co < Cc; co++) acc[co] += zv * wsh[co * Cc + ci];
    }

    const float* yb = g_y + b * Cc * SP + pos;
    float* ob = out + b * Cc * SP + pos;
#pragma unroll
    for (int co = 0; co < Cc; co++)
        ob[co * SP] = yb[co * SP] + acc[co] + pw_b[co];
}

// ---------------------------------------------------------------------------
// Launch
// ---------------------------------------------------------------------------
extern "C" void kernel_launch(void* const* d_in, const int* in_sizes, int n_in,
                              void* d_out, int out_size) {
    const float* x      = (const float*)d_in[0];
    const float* pos    = (const float*)d_in[1];
    const float* qkv_w  = (const float*)d_in[2];
    const float* proj_w = (const float*)d_in[3];
    const float* proj_b = (const float*)d_in[4];
    const float* temp   = (const float*)d_in[5];
    const float* ln_g   = (const float*)d_in[6];
    const float* ln_b   = (const float*)d_in[7];
    const float* dw_w   = (const float*)d_in[8];
    const float* dw_b   = (const float*)d_in[9];
    const float* pw_w   = (const float*)d_in[10];
    const float* pw_b   = (const float*)d_in[11];
    float* out = (float*)d_out;

    constexpr int SMEM256 = 3 * (4096 + 8192) * 4;   // 144 KB
    constexpr int FSMEM   = FS_TOT * 4;              // 154 KB
    cudaFuncSetAttribute(tc_gemm<0>, cudaFuncAttributeMaxDynamicSharedMemorySize, SMEM256);
    cudaFuncSetAttribute(tc_gemm<3>, cudaFuncAttributeMaxDynamicSharedMemorySize, SMEM256);
    cudaFuncSetAttribute(flash_attn, cudaFuncAttributeMaxDynamicSharedMemorySize, FSMEM);

    permute_t<<<dim3(24, 32, 8), dim3(32, 8)>>>(x, pos);
    cvt_weights<<<(3 * DIM * DIM + 255) / 256, 256>>>(qkv_w, proj_w);
    tc_gemm<0><<<dim3(9, 64, 1), 512, SMEM256>>>(nullptr);
    l2_norm1<<<64, 384>>>();
    l2_scale<<<dim3(192, 32, 2), 256>>>();
    flash_attn<<<dim3(16, 32), 512, FSMEM>>>(temp);
    tc_gemm<3><<<dim3(3, 64, 1), 512, SMEM256>>>(proj_b);
    ln_stats<<<SEQROWS, 256>>>();
    ln_apply<<<dim3(24, 32, 8), dim3(32, 8)>>>(x, ln_g, ln_b);
    dwconv<<<Bn * Cc * Dd, 1024>>>(dw_w, dw_b);
    pwconv<<<dim3(64, Bn, 1), 128>>>(pw_w, pw_b, out);
}

// round 9
// speedup vs baseline: 1.1514x; 1.1514x over previous
#include <cuda_runtime.h>
#include <math.h>
#include <stdint.h>

// ---------------------------------------------------------------------------
// Problem constants
// ---------------------------------------------------------------------------
constexpr int Bn = 8, Cc = 96, Dd = 8, Hh = 32, Ww = 32;
constexpr int HW = Hh * Ww;          // 1024
constexpr int DIM = Cc * Dd;         // 768
constexpr int NH = 4;
constexpr int DHd = DIM / NH;        // 192
constexpr int SEQROWS = Bn * HW;     // 8192
constexpr int BH = Bn * NH;          // 32

// ---------------------------------------------------------------------------
// Scratch (device globals -- no allocations allowed)
// ---------------------------------------------------------------------------
__device__ float g_t[SEQROWS * DIM];
__device__ float g_wq[3 * DIM * DIM];                   // qkv_w, tf32-rounded
__device__ float g_wp[DIM * DIM];                       // proj_w, tf32-rounded
__device__ float g_q[BH * HW * DHd];
__device__ float g_k[BH * HW * DHd];
__device__ float g_vt[BH * DHd * HW];                   // V transposed: [z][dh][seq]
__device__ float g_om[SEQROWS * DIM];
__device__ float g_proj[SEQROWS * DIM];
__device__ float g_y[Bn * Cc * Dd * HW];
__device__ float g_z[Bn * Cc * Dd * HW];
__device__ float g_part[2 * BH * 8 * DHd];              // l2norm partials
__device__ float g_inv[2 * BH * DHd];                   // l2norm 1/||.||
__device__ float g_mu[SEQROWS];
__device__ float g_rs[SEQROWS];

// ---------------------------------------------------------------------------
// Helpers (baseline PTX only)
// ---------------------------------------------------------------------------
__device__ __forceinline__ uint32_t f2tf(float x) {
    uint32_t r; asm("cvt.rna.tf32.f32 %0, %1;" : "=r"(r) : "f"(x)); return r;
}
__device__ __forceinline__ float tfr(float x) { return __uint_as_float(f2tf(x)); }
__device__ __forceinline__ void mma_tf32(float* d, const uint32_t* a,
                                         const uint32_t* b) {
    asm volatile(
        "mma.sync.aligned.m16n8k8.row.col.f32.tf32.tf32.f32 "
        "{%0,%1,%2,%3}, {%4,%5,%6,%7}, {%8,%9}, {%0,%1,%2,%3};"
        : "+f"(d[0]), "+f"(d[1]), "+f"(d[2]), "+f"(d[3])
        : "r"(a[0]), "r"(a[1]), "r"(a[2]), "r"(a[3]), "r"(b[0]), "r"(b[1]));
}
__device__ __forceinline__ void cp_async16(uint32_t dst, const void* src) {
    asm volatile("cp.async.cg.shared.global [%0], [%1], 16;"
                 :: "r"(dst), "l"(src) : "memory");
}
__device__ __forceinline__ void cp_commit() {
    asm volatile("cp.async.commit_group;" ::: "memory");
}
template <int N>
__device__ __forceinline__ void cp_wait() {
    asm volatile("cp.async.wait_group %0;" :: "n"(N) : "memory");
}

// ---------------------------------------------------------------------------
// tf32 GEMM for QKV / PROJ:  C[M,N] = A[M,K] * B[N,K]^T, K=768.
// Block tile 128 x 256 x 32, 512 threads, warp tile 32x64, 3-stage cp.async.
// MODE 0: QKV   A=g_t(8192,768)  B=g_wq(2304,768)  -> scatter q/k/vt via smem
// MODE 3: PROJ  A=g_om(8192,768) B=g_wp(768,768)   -> g_proj (+bias)
// ---------------------------------------------------------------------------
template <int MODE>
__global__ __launch_bounds__(512, 1) void tc_gemm(const float* __restrict__ bias) {
    constexpr int BK  = 32;
    constexpr int NB  = 256;
    constexpr int KK  = 768;
    constexpr int LD  = 768;
    constexpr int T   = KK / BK;
    constexpr int AW  = 128 * BK;            // 4096 words
    constexpr int BWD = NB * BK;             // 8192 words
    constexpr int STG = AW + BWD;
    constexpr int WN  = 64;
    constexpr int NT  = 8;

    extern __shared__ float sm[];
    const uint32_t smBase = (uint32_t)__cvta_generic_to_shared(sm);

    const int tid  = threadIdx.x;
    const int lane = tid & 31;
    const int w    = tid >> 5;
    const int wm   = w & 3;
    const int wn   = w >> 2;
    const int q    = lane >> 2;
    const int lq   = lane & 3;
    const int m0   = blockIdx.y * 128;
    const int n0   = blockIdx.x * NB;

    const float* gA = (MODE == 0) ? g_t  : g_om;
    const float* gB = (MODE == 0) ? g_wq : g_wp;

    const float* aRow = gA + (size_t)m0 * LD;
    const float* bRow = gB + (size_t)n0 * LD;

    auto loadStage = [&](int it, int s) {
        const float* aP = aRow + it * BK;
        const float* bP = bRow + it * BK;
        uint32_t sA = smBase + (uint32_t)(s * STG) * 4u;
        uint32_t sB = sA + AW * 4u;
#pragma unroll
        for (int i = 0; i < 2; i++) {
            int idx = tid + 512 * i;
            int r = idx >> 3, c4 = idx & 7;
            uint32_t dst = sA + (uint32_t)(r * 32 + ((c4 * 4) ^ (4 * (r & 7)))) * 4u;
            cp_async16(dst, aP + (size_t)r * LD + c4 * 4);
        }
#pragma unroll
        for (int i = 0; i < 4; i++) {
            int idx = tid + 512 * i;
            int r = idx >> 3, c4 = idx & 7;
            uint32_t dst = sB + (uint32_t)(r * 32 + ((c4 * 4) ^ (4 * (r & 7)))) * 4u;
            cp_async16(dst, bP + (size_t)r * LD + c4 * 4);
        }
    };

    float acc[2][NT][4];
#pragma unroll
    for (int mt = 0; mt < 2; mt++)
#pragma unroll
        for (int nt = 0; nt < NT; nt++)
#pragma unroll
            for (int k = 0; k < 4; k++) acc[mt][nt][k] = 0.f;

#pragma unroll
    for (int s = 0; s < 3; s++) { loadStage(s, s); cp_commit(); }

    const int sw = 4 * q;

    for (int it = 0; it < T; ++it) {
        cp_wait<2>();
        __syncthreads();

        const int st = it % 3;
        const uint32_t* A_ = reinterpret_cast<const uint32_t*>(sm + st * STG);
        const uint32_t* B_ = A_ + AW;
#pragma unroll
        for (int ks = 0; ks < 4; ks++) {
            const int k0 = ks * 8;
            const int c0 = (k0 + lq) ^ sw;
            const int c1 = (k0 + 4 + lq) ^ sw;
            uint32_t a[2][4];
#pragma unroll
            for (int mt = 0; mt < 2; mt++) {
                int rb = (wm * 32 + mt * 16 + q) * 32;
                a[mt][0] = A_[rb + c0];
                a[mt][1] = A_[rb + 256 + c0];
                a[mt][2] = A_[rb + c1];
                a[mt][3] = A_[rb + 256 + c1];
            }
            uint32_t b[NT][2];
#pragma unroll
            for (int nt = 0; nt < NT; nt++) {
                int nb = (wn * WN + nt * 8 + q) * 32;
                b[nt][0] = B_[nb + c0];
                b[nt][1] = B_[nb + c1];
            }
#pragma unroll
            for (int mt = 0; mt < 2; mt++)
#pragma unroll
                for (int nt = 0; nt < NT; nt++)
                    mma_tf32(acc[mt][nt], a[mt], b[nt]);
        }
        __syncthreads();
        if (it + 3 < T) loadStage(it + 3, st);
        cp_commit();
    }

    // ---------------- epilogue ----------------
    if constexpr (MODE == 3) {
#pragma unroll
        for (int mt = 0; mt < 2; mt++)
#pragma unroll
            for (int nt = 0; nt < NT; nt++) {
                int r = m0 + wm * 32 + mt * 16 + q;
                int c = n0 + wn * WN + nt * 8 + lq * 2;
                float2 bb = *reinterpret_cast<const float2*>(bias + c);
                float2 v0 = {acc[mt][nt][0] + bb.x, acc[mt][nt][1] + bb.y};
                float2 v1 = {acc[mt][nt][2] + bb.x, acc[mt][nt][3] + bb.y};
                *reinterpret_cast<float2*>(g_proj + (size_t)r * DIM + c) = v0;
                *reinterpret_cast<float2*>(g_proj + (size_t)(r + 8) * DIM + c) = v1;
            }
    } else {
        // stage C tile (128 x 256) in smem, stride 257 (odd -> scalar stores)
        constexpr int LDO = 257;
        float* stg = sm;
        __syncthreads();
#pragma unroll
        for (int mt = 0; mt < 2; mt++)
#pragma unroll
            for (int nt = 0; nt < NT; nt++) {
                int r = wm * 32 + mt * 16 + q;
                int c = wn * WN + nt * 8 + lq * 2;
                stg[r * LDO + c]           = acc[mt][nt][0];
                stg[r * LDO + c + 1]       = acc[mt][nt][1];
                stg[(r + 8) * LDO + c]     = acc[mt][nt][2];
                stg[(r + 8) * LDO + c + 1] = acc[mt][nt][3];
            }
        __syncthreads();
        const int s0 = n0 / 768;                 // 0=q, 1=k, 2=v
        if (s0 == 2) {
            // g_vt[z][dh][seq]: iterate rows fastest -> consecutive seq
            for (int idx = tid; idx < 128 * 256; idx += 512) {
                int r = idx & 127, c = idx >> 7;
                int m = m0 + r, b = m >> 10, seq = m & 1023;
                int nl = n0 - 1536 + c;
                int h = nl / 192, dh = nl % 192;
                g_vt[((size_t)(b * 4 + h) * 192 + dh) * 1024 + seq] =
                    tfr(stg[r * LDO + c]);
            }
        } else {
            float* dst = (s0 == 0) ? g_q : g_k;
            for (int idx = tid; idx < 128 * 256; idx += 512) {
                int c = idx & 255, r = idx >> 8;
                int m = m0 + r, b = m >> 10, seq = m & 1023;
                int nl = n0 - s0 * 768 + c;
                int h = nl / 192, dh = nl % 192;
                dst[((size_t)(b * 4 + h) * 1024 + seq) * 192 + dh] = stg[r * LDO + c];
            }
        }
    }
}

// ---------------------------------------------------------------------------
// Flash attention (R6 config): per CTA 64 query rows x one (b,h). 256 threads,
// 8 warps (wm 2 x wn 4). Phase 1 warp tile 32x32; Phase 2 warp tile 32x48.
// smem words: Q 6*2048 | KV 3*6144 | P 4*2048 | red 256  = 39168 (153 KB)
// ---------------------------------------------------------------------------
constexpr int FS_Q   = 0;
constexpr int FS_KV  = 12288;
constexpr int FS_P   = 30720;
constexpr int FS_RED = 38912;
constexpr int FS_TOT = 39168;

__global__ __launch_bounds__(256, 1) void flash_attn(const float* __restrict__ temp) {
    extern __shared__ float sm[];
    const uint32_t smBase = (uint32_t)__cvta_generic_to_shared(sm);

    const int tid  = threadIdx.x;
    const int lane = tid & 31;
    const int w    = tid >> 5;       // 0..7
    const int wm   = w & 1;
    const int wn   = w >> 1;         // 0..3
    const int q    = lane >> 2;
    const int lq   = lane & 3;
    const int z    = blockIdx.y;
    const int m0   = blockIdx.x * 64;

    const float* Qz = g_q  + (size_t)z * HW * DHd;
    const float* Kz = g_k  + (size_t)z * HW * DHd;
    const float* Vz = g_vt + (size_t)z * DHd * HW;
    const float ts = temp[z & 3];

    // Q load: 6 panels [64][32] swizzled
#pragma unroll
    for (int i = 0; i < 12; i++) {
        int idx = tid + 256 * i;
        int c4 = idx & 7, r = (idx >> 3) & 63, p = idx >> 9;
        uint32_t dst = smBase + (uint32_t)(FS_Q + p * 2048 + r * 32 +
                                           ((c4 * 4) ^ (4 * (r & 7)))) * 4u;
        cp_async16(dst, Qz + (size_t)(m0 + r) * 192 + p * 32 + c4 * 4);
    }
    cp_commit();

    auto issuePanel = [&](int g) {
        int t = g / 10, i = g % 10, buf = g % 3;
        uint32_t base = smBase + (uint32_t)(FS_KV + buf * 6144) * 4u;
        if (i < 6) {               // K panel: 128 rows x 32 dh
#pragma unroll
            for (int j = 0; j < 4; j++) {
                int idx = tid + 256 * j;
                int c4 = idx & 7, r = idx >> 3;
                cp_async16(base + (uint32_t)(r * 32 + ((c4 * 4) ^ (4 * (r & 7)))) * 4u,
                           Kz + (size_t)(t * 128 + r) * 192 + i * 32 + c4 * 4);
            }
        } else {                   // V panel: 192 dh rows x 32 keys
            int pv = i - 6;
#pragma unroll
            for (int j = 0; j < 6; j++) {
                int idx = tid + 256 * j;
                int c4 = idx & 7, r = idx >> 3;
                cp_async16(base + (uint32_t)(r * 32 + ((c4 * 4) ^ (4 * (r & 7)))) * 4u,
                           Vz + (size_t)r * 1024 + t * 128 + pv * 32 + c4 * 4);
            }
        }
    };
    issuePanel(0); cp_commit();
    issuePanel(1); cp_commit();

    constexpr float L2E = 1.4426950408889634f;
    float m_run[2][2] = {{-1e30f, -1e30f}, {-1e30f, -1e30f}};
    float l_run[2][2] = {{0.f, 0.f}, {0.f, 0.f}};
    float acc_o[2][6][4];
#pragma unroll
    for (int mt = 0; mt < 2; mt++)
#pragma unroll
        for (int nt = 0; nt < 6; nt++)
#pragma unroll
            for (int k = 0; k < 4; k++) acc_o[mt][nt][k] = 0.f;

    const int sw = 4 * q;
    float* sRed = sm + FS_RED;

    for (int t = 0; t < 8; t++) {
        float acc_s[2][4][4];
#pragma unroll
        for (int mt = 0; mt < 2; mt++)
#pragma unroll
            for (int nt = 0; nt < 4; nt++)
#pragma unroll
                for (int k = 0; k < 4; k++) acc_s[mt][nt][k] = 0.f;

        // ---------- phase 1: S = Q K^T ----------
        for (int p = 0; p < 6; p++) {
            int g = t * 10 + p;
            cp_wait<1>();
            __syncthreads();
            if (g + 2 < 80) issuePanel(g + 2);
            cp_commit();
            const uint32_t* Ap = reinterpret_cast<const uint32_t*>(sm + FS_Q + p * 2048);
            const uint32_t* Bp = reinterpret_cast<const uint32_t*>(sm + FS_KV + (g % 3) * 6144);
#pragma unroll
            for (int ks = 0; ks < 4; ks++) {
                const int c0 = (ks * 8 + lq) ^ sw;
                const int c1 = (ks * 8 + 4 + lq) ^ sw;
                uint32_t a[2][4];
#pragma unroll
                for (int mt = 0; mt < 2; mt++) {
                    int rb = (wm * 32 + mt * 16 + q) * 32;
                    a[mt][0] = Ap[rb + c0];
                    a[mt][1] = Ap[rb + 256 + c0];
                    a[mt][2] = Ap[rb + c1];
                    a[mt][3] = Ap[rb + 256 + c1];
                }
#pragma unroll
                for (int nt = 0; nt < 4; nt++) {
                    uint32_t b[2];
                    int nb = (wn * 32 + nt * 8 + q) * 32;
                    b[0] = Bp[nb + c0];
                    b[1] = Bp[nb + c1];
#pragma unroll
                    for (int mt = 0; mt < 2; mt++)
                        mma_tf32(acc_s[mt][nt], a[mt], b);
                }
            }
        }

        // ---------- online softmax ----------
        float tmax[2][2], corr[2][2], rsum[2][2];
        {
            float rmax[2][2] = {{-1e30f, -1e30f}, {-1e30f, -1e30f}};
#pragma unroll
            for (int mt = 0; mt < 2; mt++)
#pragma unroll
                for (int nt = 0; nt < 4; nt++)
#pragma unroll
                    for (int j = 0; j < 4; j++) {
                        float v = acc_s[mt][nt][j] * ts;
                        acc_s[mt][nt][j] = v;
                        rmax[mt][j >> 1] = fmaxf(rmax[mt][j >> 1], v);
                    }
#pragma unroll
            for (int mt = 0; mt < 2; mt++)
#pragma unroll
                for (int h2 = 0; h2 < 2; h2++) {
                    float v = rmax[mt][h2];
                    v = fmaxf(v, __shfl_xor_sync(0xFFFFFFFF, v, 1));
                    v = fmaxf(v, __shfl_xor_sync(0xFFFFFFFF, v, 2));
                    rmax[mt][h2] = v;
                }
            if (lq == 0) {
#pragma unroll
                for (int mt = 0; mt < 2; mt++)
#pragma unroll
                    for (int h2 = 0; h2 < 2; h2++)
                        sRed[wn * 64 + wm * 32 + mt * 16 + q + h2 * 8] = rmax[mt][h2];
            }
            __syncthreads();
#pragma unroll
            for (int mt = 0; mt < 2; mt++)
#pragma unroll
                for (int h2 = 0; h2 < 2; h2++) {
                    int rr = wm * 32 + mt * 16 + q + h2 * 8;
                    tmax[mt][h2] = fmaxf(fmaxf(sRed[rr], sRed[64 + rr]),
                                         fmaxf(sRed[128 + rr], sRed[192 + rr]));
                }
        }
#pragma unroll
        for (int mt = 0; mt < 2; mt++)
#pragma unroll
            for (int h2 = 0; h2 < 2; h2++) {
                float nm = fmaxf(m_run[mt][h2], tmax[mt][h2]);
                corr[mt][h2] = exp2f((m_run[mt][h2] - nm) * L2E);
                m_run[mt][h2] = nm;
                rsum[mt][h2] = 0.f;
            }
#pragma unroll
        for (int mt = 0; mt < 2; mt++)
#pragma unroll
            for (int nt = 0; nt < 4; nt++)
#pragma unroll
                for (int j = 0; j < 4; j++) {
                    float pv = exp2f((acc_s[mt][nt][j] - m_run[mt][j >> 1]) * L2E);
                    acc_s[mt][nt][j] = pv;
                    rsum[mt][j >> 1] += pv;
                }
#pragma unroll
        for (int mt = 0; mt < 2; mt++)
#pragma unroll
            for (int h2 = 0; h2 < 2; h2++) {
                float v = rsum[mt][h2];
                v += __shfl_xor_sync(0xFFFFFFFF, v, 1);
                v += __shfl_xor_sync(0xFFFFFFFF, v, 2);
                rsum[mt][h2] = v;
            }
        __syncthreads();                       // sRed reuse (max -> sum)
        if (lq == 0) {
#pragma unroll
            for (int mt = 0; mt < 2; mt++)
#pragma unroll
                for (int h2 = 0; h2 < 2; h2++)
                    sRed[wn * 64 + wm * 32 + mt * 16 + q + h2 * 8] = rsum[mt][h2];
        }
        __syncthreads();
#pragma unroll
        for (int mt = 0; mt < 2; mt++)
#pragma unroll
            for (int h2 = 0; h2 < 2; h2++) {
                int rr = wm * 32 + mt * 16 + q + h2 * 8;
                float tsum = sRed[rr] + sRed[64 + rr] + sRed[128 + rr] + sRed[192 + rr];
                l_run[mt][h2] = l_run[mt][h2] * corr[mt][h2] + tsum;
            }
        // rescale O
#pragma unroll
        for (int mt = 0; mt < 2; mt++)
#pragma unroll
            for (int nt = 0; nt < 6; nt++) {
                acc_o[mt][nt][0] *= corr[mt][0];
                acc_o[mt][nt][1] *= corr[mt][0];
                acc_o[mt][nt][2] *= corr[mt][1];
                acc_o[mt][nt][3] *= corr[mt][1];
            }
        // store P (tf32) to panel wn
#pragma unroll
        for (int mt = 0; mt < 2; mt++)
#pragma unroll
            for (int nt = 0; nt < 4; nt++) {
                int r0 = wm * 32 + mt * 16 + q;
                int c  = nt * 8 + 2 * lq;
                float2 p0 = {__uint_as_float(f2tf(acc_s[mt][nt][0])),
                             __uint_as_float(f2tf(acc_s[mt][nt][1]))};
                float2 p1 = {__uint_as_float(f2tf(acc_s[mt][nt][2])),
                             __uint_as_float(f2tf(acc_s[mt][nt][3]))};
                *reinterpret_cast<float2*>(sm + FS_P + wn * 2048 + r0 * 32 + (c ^ sw)) = p0;
                *reinterpret_cast<float2*>(sm + FS_P + wn * 2048 + (r0 + 8) * 32 + (c ^ sw)) = p1;
            }
        __syncthreads();

        // ---------- phase 2: O += P V ----------
        for (int pv = 0; pv < 4; pv++) {
            int g = t * 10 + 6 + pv;
            cp_wait<1>();
            __syncthreads();
            if (g + 2 < 80) issuePanel(g + 2);
            cp_commit();
            const uint32_t* Ap = reinterpret_cast<const uint32_t*>(sm + FS_P + pv * 2048);
            const uint32_t* Bp = reinterpret_cast<const uint32_t*>(sm + FS_KV + (g % 3) * 6144);
#pragma unroll
            for (int ks = 0; ks < 4; ks++) {
                const int c0 = (ks * 8 + lq) ^ sw;
                const int c1 = (ks * 8 + 4 + lq) ^ sw;
                uint32_t a[2][4];
#pragma unroll
                for (int mt = 0; mt < 2; mt++) {
                    int rb = (wm * 32 + mt * 16 + q) * 32;
                    a[mt][0] = Ap[rb + c0];
                    a[mt][1] = Ap[rb + 256 + c0];
                    a[mt][2] = Ap[rb + c1];
                    a[mt][3] = Ap[rb + 256 + c1];
                }
#pragma unroll
                for (int nt = 0; nt < 6; nt++) {
                    uint32_t b[2];
                    int nb = (wn * 48 + nt * 8 + q) * 32;
                    b[0] = Bp[nb + c0];
                    b[1] = Bp[nb + c1];
#pragma unroll
                    for (int mt = 0; mt < 2; mt++)
                        mma_tf32(acc_o[mt][nt], a[mt], b);
                }
            }
        }
    }

    // ---------- epilogue: O /= l, merged-head store ----------
    int b = z >> 2, h = z & 3;
    float inv[2][2];
#pragma unroll
    for (int mt = 0; mt < 2; mt++)
#pragma unroll
        for (int h2 = 0; h2 < 2; h2++) inv[mt][h2] = 1.f / l_run[mt][h2];
#pragma unroll
    for (int mt = 0; mt < 2; mt++)
#pragma unroll
        for (int nt = 0; nt < 6; nt++) {
            int rl = wm * 32 + mt * 16 + q;
            int col = wn * 48 + nt * 8 + 2 * lq;
            float2 v0 = {tfr(acc_o[mt][nt][0] * inv[mt][0]),
                         tfr(acc_o[mt][nt][1] * inv[mt][0])};
            float2 v1 = {tfr(acc_o[mt][nt][2] * inv[mt][1]),
                         tfr(acc_o[mt][nt][3] * inv[mt][1])};
            *reinterpret_cast<float2*>(
                g_om + ((size_t)(b * HW + m0 + rl)) * DIM + h * DHd + col) = v0;
            *reinterpret_cast<float2*>(
                g_om + ((size_t)(b * HW + m0 + rl + 8)) * DIM + h * DHd + col) = v1;
        }
}

// ---------------------------------------------------------------------------
// Producers / elementwise
// ---------------------------------------------------------------------------
__global__ void permute_t(const float* __restrict__ x,
                          const float* __restrict__ pos) {
    __shared__ float tile[32][33];
    int bz = blockIdx.z, hw0 = blockIdx.y * 32, cd0 = blockIdx.x * 32;
    int tx = threadIdx.x, ty = threadIdx.y;
#pragma unroll
    for (int k = 0; k < 4; k++) {
        int cd = cd0 + ty + 8 * k;
        tile[ty + 8 * k][tx] = x[((size_t)bz * 768 + cd) * 1024 + hw0 + tx];
    }
    __syncthreads();
#pragma unroll
    for (int k = 0; k < 4; k++) {
        int hw = hw0 + ty + 8 * k;
        int cd = cd0 + tx;
        g_t[((size_t)bz * 1024 + hw) * 768 + cd] =
            tfr(tile[tx][ty + 8 * k] + pos[(size_t)hw * 768 + cd]);
    }
}

__global__ void cvt_weights(const float* __restrict__ qkv_w,
                            const float* __restrict__ proj_w) {
    int i = blockIdx.x * 256 + threadIdx.x;
    if (i < 3 * DIM * DIM) g_wq[i] = tfr(qkv_w[i]);
    if (i < DIM * DIM)     g_wp[i] = tfr(proj_w[i]);
}

// l2norm over seq axis (R6 split version): partials -> inv -> scale
__global__ void l2_part() {
    int chunk = blockIdx.x, z = blockIdx.y, which = blockIdx.z;
    const float* p = (which ? g_k : g_q) + ((size_t)z * HW + chunk * 128) * DHd;
    int col = threadIdx.x;
    float ss = 0.f;
#pragma unroll 4
    for (int r = 0; r < 128; r++) {
        float v = p[(size_t)r * DHd + col];
        ss += v * v;
    }
    g_part[(((size_t)which * BH + z) * 8 + chunk) * DHd + col] = ss;
}

__global__ void l2_inv() {
    int which = blockIdx.x >> 5, z = blockIdx.x & 31;
    int col = threadIdx.x;
    float ss = 0.f;
#pragma unroll
    for (int c = 0; c < 8; c++)
        ss += g_part[(((size_t)which * BH + z) * 8 + c) * DHd + col];
    g_inv[((size_t)which * BH + z) * DHd + col] = 1.f / fmaxf(sqrtf(ss), 1e-12f);
}

__global__ void l2_scale() {
    int which = blockIdx.z, z = blockIdx.y;
    int i = blockIdx.x * 256 + threadIdx.x;
    int seq = i / 48, c4 = i % 48;
    float* p = (which ? g_k : g_q) + ((size_t)z * HW + seq) * DHd + c4 * 4;
    float4 v  = *reinterpret_cast<float4*>(p);
    float4 iv = *reinterpret_cast<const float4*>(g_inv + ((size_t)which * BH + z) * DHd + c4 * 4);
    v.x = tfr(v.x * iv.x); v.y = tfr(v.y * iv.y);
    v.z = tfr(v.z * iv.z); v.w = tfr(v.w * iv.w);
    *reinterpret_cast<float4*>(p) = v;
}

__global__ void ln_stats() {
    __shared__ float red[256];
    int row = blockIdx.x;
    int tid = threadIdx.x;
    const float* basep = g_proj + (size_t)row * DIM;

    float v[3];
    float s = 0.f;
#pragma unroll
    for (int j = 0; j < 3; j++) { v[j] = basep[tid + 256 * j]; s += v[j]; }
    red[tid] = s; __syncthreads();
    for (int st = 128; st > 0; st >>= 1) {
        if (tid < st) red[tid] += red[tid + st];
        __syncthreads();
    }
    float mu = red[0] * (1.f / DIM); __syncthreads();

    float s2 = 0.f;
#pragma unroll
    for (int j = 0; j < 3; j++) { float d = v[j] - mu; s2 += d * d; }
    red[tid] = s2; __syncthreads();
    for (int st = 128; st > 0; st >>= 1) {
        if (tid < st) red[tid] += red[tid + st];
        __syncthreads();
    }
    if (tid == 0) {
        g_mu[row] = mu;
        g_rs[row] = rsqrtf(red[0] * (1.f / DIM) + 1e-5f);
    }
}

__global__ void ln_apply(const float* __restrict__ x,
                         const float* __restrict__ gamma,
                         const float* __restrict__ beta) {
    __shared__ float tile[32][33];
    int bz = blockIdx.z, hw0 = blockIdx.y * 32, cd0 = blockIdx.x * 32;
    int tx = threadIdx.x, ty = threadIdx.y;
#pragma unroll
    for (int k = 0; k < 4; k++) {
        int hw = hw0 + ty + 8 * k;
        int row = bz * 1024 + hw;
        int cd = cd0 + tx;
        float v = g_proj[(size_t)row * 768 + cd];
        tile[ty + 8 * k][tx] = (v - g_mu[row]) * g_rs[row] * gamma[cd] + beta[cd];
    }
    __syncthreads();
#pragma unroll
    for (int k = 0; k < 4; k++) {
        int cd = cd0 + ty + 8 * k;
        int hw = hw0 + tx;
        size_t oi = ((size_t)bz * 768 + cd) * 1024 + hw;
        g_y[oi] = tile[tx][ty + 8 * k] + x[oi];
    }
}

__global__ __launch_bounds__(1024) void dwconv(const float* __restrict__ dw_w,
                                               const float* __restrict__ dw_b) {
    __shared__ float tile[3][34][34];
    __shared__ float wsh[27];
    int bcd = blockIdx.x;
    int d  = bcd & 7;
    int bc = bcd >> 3;
    int c  = bc % Cc;
    int tid = threadIdx.x;

    if (tid < 27) wsh[tid] = dw_w[c * 27 + tid];

    for (int idx = tid; idx < 3 * 34 * 34; idx += 1024) {
        int pl = idx / 1156;
        int r  = (idx - pl * 1156) / 34;
        int cc = idx - pl * 1156 - r * 34;
        int dd = d - 1 + pl, hh = r - 1, ww = cc - 1;
        float val = 0.f;
        if (dd >= 0 && dd < Dd && hh >= 0 && hh < Hh && ww >= 0 && ww < Ww)
            val = g_y[(bc * Dd + dd) * HW + hh * Ww + ww];
        tile[pl][r][cc] = val;
    }
    __syncthreads();

    int h = tid >> 5, w = tid & 31;
    float s = 0.f;
#pragma unroll
    for (int pl = 0; pl < 3; pl++)
#pragma unroll
        for (int i = 0; i < 3; i++)
#pragma unroll
            for (int j = 0; j < 3; j++)
                s += tile[pl][h + i][w + j] * wsh[pl * 9 + i * 3 + j];
    g_z[bcd * HW + tid] = s + dw_b[c];
}

__global__ __launch_bounds__(128) void pwconv(const float* __restrict__ pw_w,
                                              const float* __restrict__ pw_b,
                                              float* __restrict__ out) {
    __shared__ float wsh[Cc * Cc];
    int b = blockIdx.y;
    int pos = blockIdx.x * 128 + threadIdx.x;
    constexpr int SP = Dd * HW;

    for (int i = threadIdx.x; i < Cc * Cc; i += 128) wsh[i] = pw_w[i];
    __syncthreads();

    float acc[Cc];
#pragma unroll
    for (int co = 0; co < Cc; co++) acc[co] = 0.f;

    const float* zb = g_z + b * Cc * SP + pos;
    for (int ci = 0; ci < Cc; ci++) {
        float zv = zb[ci * SP];
#pragma unroll
        for (int co = 0; co < Cc; co++) acc[co] += zv * wsh[co * Cc + ci];
    }

    const float* yb = g_y + b * Cc * SP + pos;
    float* ob = out + b * Cc * SP + pos;
#pragma unroll
    for (int co = 0; co < Cc; co++)
        ob[co * SP] = yb[co * SP] + acc[co] + pw_b[co];
}

// ---------------------------------------------------------------------------
// Launch
// ---------------------------------------------------------------------------
extern "C" void kernel_launch(void* const* d_in, const int* in_sizes, int n_in,
                              void* d_out, int out_size) {
    const float* x      = (const float*)d_in[0];
    const float* pos    = (const float*)d_in[1];
    const float* qkv_w  = (const float*)d_in[2];
    const float* proj_w = (const float*)d_in[3];
    const float* proj_b = (const float*)d_in[4];
    const float* temp   = (const float*)d_in[5];
    const float* ln_g   = (const float*)d_in[6];
    const float* ln_b   = (const float*)d_in[7];
    const float* dw_w   = (const float*)d_in[8];
    const float* dw_b   = (const float*)d_in[9];
    const float* pw_w   = (const float*)d_in[10];
    const float* pw_b   = (const float*)d_in[11];
    float* out = (float*)d_out;

    constexpr int SMEM256 = 3 * (4096 + 8192) * 4;   // 144 KB
    constexpr int FSMEM   = FS_TOT * 4;              // 153 KB
    cudaFuncSetAttribute(tc_gemm<0>, cudaFuncAttributeMaxDynamicSharedMemorySize, SMEM256);
    cudaFuncSetAttribute(tc_gemm<3>, cudaFuncAttributeMaxDynamicSharedMemorySize, SMEM256);
    cudaFuncSetAttribute(flash_attn, cudaFuncAttributeMaxDynamicSharedMemorySize, FSMEM);

    permute_t<<<dim3(24, 32, 8), dim3(32, 8)>>>(x, pos);
    cvt_weights<<<(3 * DIM * DIM + 255) / 256, 256>>>(qkv_w, proj_w);
    tc_gemm<0><<<dim3(9, 64, 1), 512, SMEM256>>>(nullptr);
    l2_part<<<dim3(8, 32, 2), 192>>>();
    l2_inv<<<64, 192>>>();
    l2_scale<<<dim3(192, 32, 2), 256>>>();
    flash_attn<<<dim3(16, 32), 256, FSMEM>>>(temp);
    tc_gemm<3><<<dim3(3, 64, 1), 512, SMEM256>>>(proj_b);
    ln_stats<<<SEQROWS, 256>>>();
    ln_apply<<<dim3(24, 32, 8), dim3(32, 8)>>>(x, ln_g, ln_b);
    dwconv<<<Bn * Cc * Dd, 1024>>>(dw_w, dw_b);
    pwconv<<<dim3(64, Bn, 1), 128>>>(pw_w, pw_b, out);
}

// round 10
// speedup vs baseline: 1.6488x; 1.4320x over previous
#include <cuda_runtime.h>
#include <cuda_fp16.h>
#include <math.h>
#include <stdint.h>

// ---------------------------------------------------------------------------
// Problem constants
// ---------------------------------------------------------------------------
constexpr int Bn = 8, Cc = 96, Dd = 8, Hh = 32, Ww = 32;
constexpr int HW = Hh * Ww;          // 1024
constexpr int DIM = Cc * Dd;         // 768
constexpr int NH = 4;
constexpr int DHd = DIM / NH;        // 192
constexpr int SEQROWS = Bn * HW;     // 8192
constexpr int BH = Bn * NH;          // 32

// ---------------------------------------------------------------------------
// Scratch (device globals -- no allocations allowed). GEMM operands in fp16.
// ---------------------------------------------------------------------------
__device__ __align__(16) __half g_t[SEQROWS * DIM];
__device__ __align__(16) __half g_wq[3 * DIM * DIM];
__device__ __align__(16) __half g_wp[DIM * DIM];
__device__ __align__(16) __half g_q[BH * HW * DHd];
__device__ __align__(16) __half g_k[BH * HW * DHd];
__device__ __align__(16) __half g_vt[BH * DHd * HW];    // V^T: [z][dh][seq]
__device__ __align__(16) __half g_om[SEQROWS * DIM];
__device__ float g_proj[SEQROWS * DIM];
__device__ float g_y[Bn * Cc * Dd * HW];
__device__ float g_z[Bn * Cc * Dd * HW];
__device__ float g_part[2 * BH * 8 * DHd];
__device__ float g_inv[2 * BH * DHd];
__device__ float g_mu[SEQROWS];
__device__ float g_rs[SEQROWS];

// ---------------------------------------------------------------------------
// Helpers (baseline PTX only)
// ---------------------------------------------------------------------------
__device__ __forceinline__ void mma_f16(float* d, const uint32_t* a,
                                        const uint32_t* b) {
    asm volatile(
        "mma.sync.aligned.m16n8k16.row.col.f32.f16.f16.f32 "
        "{%0,%1,%2,%3}, {%4,%5,%6,%7}, {%8,%9}, {%0,%1,%2,%3};"
        : "+f"(d[0]), "+f"(d[1]), "+f"(d[2]), "+f"(d[3])
        : "r"(a[0]), "r"(a[1]), "r"(a[2]), "r"(a[3]), "r"(b[0]), "r"(b[1]));
}
__device__ __forceinline__ void cp_async16(uint32_t dst, const void* src) {
    asm volatile("cp.async.cg.shared.global [%0], [%1], 16;"
                 :: "r"(dst), "l"(src) : "memory");
}
__device__ __forceinline__ void cp_commit() {
    asm volatile("cp.async.commit_group;" ::: "memory");
}
template <int N>
__device__ __forceinline__ void cp_wait() {
    asm volatile("cp.async.wait_group %0;" :: "n"(N) : "memory");
}
__device__ __forceinline__ uint32_t pack_h2(float x, float y) {
    __half2 h = __floats2half2_rn(x, y);
    return *reinterpret_cast<uint32_t*>(&h);
}

// ---------------------------------------------------------------------------
// fp16 GEMM for QKV / PROJ:  C[M,N] = A[M,K] * B[N,K]^T, K=768 halves.
// Block tile 128 x 256 x 64(halves), 512 threads, warp tile 32x64,
// 3-stage cp.async. smem word = half2; k-step = 16 halves (m16n8k16).
// MODE 0: QKV   A=g_t  B=g_wq  -> scatter q/k/vt (fp16)
// MODE 3: PROJ  A=g_om B=g_wp  -> g_proj (fp32, +bias)
// ---------------------------------------------------------------------------
template <int MODE>
__global__ __launch_bounds__(512, 1) void tc_gemm(const float* __restrict__ bias) {
    constexpr int BK  = 64;                  // halves per stage
    constexpr int KK  = 768;
    constexpr int LD  = 768;                 // halves per row
    constexpr int T   = KK / BK;             // 12
    constexpr int AW  = 128 * 32;            // words (half2) per A stage
    constexpr int BWD = 256 * 32;            // words per B stage
    constexpr int STG = AW + BWD;            // 12288 words = 48 KB
    constexpr int WN  = 64;
    constexpr int NT  = 8;

    extern __shared__ uint32_t smw[];
    const uint32_t smBase = (uint32_t)__cvta_generic_to_shared(smw);

    const int tid  = threadIdx.x;
    const int lane = tid & 31;
    const int w    = tid >> 5;
    const int wm   = w & 3;
    const int wn   = w >> 2;
    const int q    = lane >> 2;
    const int lq   = lane & 3;
    const int m0   = blockIdx.y * 128;
    const int n0   = blockIdx.x * 256;

    const __half* gA = (MODE == 0) ? g_t  : g_om;
    const __half* gB = (MODE == 0) ? g_wq : g_wp;

    const __half* aRow = gA + (size_t)m0 * LD;
    const __half* bRow = gB + (size_t)n0 * LD;

    auto loadStage = [&](int it, int s) {
        const __half* aP = aRow + it * BK;
        const __half* bP = bRow + it * BK;
        uint32_t sA = smBase + (uint32_t)(s * STG) * 4u;
        uint32_t sB = sA + AW * 4u;
#pragma unroll
        for (int i = 0; i < 2; i++) {        // A: 1024 16B-chunks
            int idx = tid + 512 * i;
            int r = idx >> 3, c4 = idx & 7;
            uint32_t dst = sA + (uint32_t)(r * 32 + ((c4 * 4) ^ (4 * (r & 7)))) * 4u;
            cp_async16(dst, aP + (size_t)r * LD + c4 * 8);
        }
#pragma unroll
        for (int i = 0; i < 4; i++) {        // B: 2048 16B-chunks
            int idx = tid + 512 * i;
            int r = idx >> 3, c4 = idx & 7;
            uint32_t dst = sB + (uint32_t)(r * 32 + ((c4 * 4) ^ (4 * (r & 7)))) * 4u;
            cp_async16(dst, bP + (size_t)r * LD + c4 * 8);
        }
    };

    float acc[2][NT][4];
#pragma unroll
    for (int mt = 0; mt < 2; mt++)
#pragma unroll
        for (int nt = 0; nt < NT; nt++)
#pragma unroll
            for (int k = 0; k < 4; k++) acc[mt][nt][k] = 0.f;

#pragma unroll
    for (int s = 0; s < 3; s++) { loadStage(s, s); cp_commit(); }

    const int sw = 4 * q;

    for (int it = 0; it < T; ++it) {
        cp_wait<2>();
        __syncthreads();

        const int st = it % 3;
        const uint32_t* A_ = smw + st * STG;
        const uint32_t* B_ = A_ + AW;
#pragma unroll
        for (int ks = 0; ks < 4; ks++) {     // each ks = 16 halves of K
            const int c0 = (ks * 8 + lq) ^ sw;
            const int c1 = (ks * 8 + 4 + lq) ^ sw;
            uint32_t a[2][4];
#pragma unroll
            for (int mt = 0; mt < 2; mt++) {
                int rb = (wm * 32 + mt * 16 + q) * 32;
                a[mt][0] = A_[rb + c0];
                a[mt][1] = A_[rb + 256 + c0];
                a[mt][2] = A_[rb + c1];
                a[mt][3] = A_[rb + 256 + c1];
            }
            uint32_t b[NT][2];
#pragma unroll
            for (int nt = 0; nt < NT; nt++) {
                int nb = (wn * WN + nt * 8 + q) * 32;
                b[nt][0] = B_[nb + c0];
                b[nt][1] = B_[nb + c1];
            }
#pragma unroll
            for (int mt = 0; mt < 2; mt++)
#pragma unroll
                for (int nt = 0; nt < NT; nt++)
                    mma_f16(acc[mt][nt], a[mt], b[nt]);
        }
        __syncthreads();
        if (it + 3 < T) loadStage(it + 3, st);
        cp_commit();
    }

    // ---------------- epilogue (direct stores, R6 style) ----------------
    const int s0 = (MODE == 0) ? (n0 / 768) : 0;
#pragma unroll
    for (int mt = 0; mt < 2; mt++)
#pragma unroll
        for (int nt = 0; nt < NT; nt++) {
            int r = m0 + wm * 32 + mt * 16 + q;
            int c = n0 + wn * WN + nt * 8 + lq * 2;
            if constexpr (MODE == 3) {
                float2 bb = *reinterpret_cast<const float2*>(bias + c);
                float2 v0 = {acc[mt][nt][0] + bb.x, acc[mt][nt][1] + bb.y};
                float2 v1 = {acc[mt][nt][2] + bb.x, acc[mt][nt][3] + bb.y};
                *reinterpret_cast<float2*>(g_proj + (size_t)r * DIM + c) = v0;
                *reinterpret_cast<float2*>(g_proj + (size_t)(r + 8) * DIM + c) = v1;
            } else {
                int nl = c - s0 * 768;
                int h = nl / 192, dh = nl % 192;
                int b0i = r >> 10, seq0 = r & 1023;
                int b1i = (r + 8) >> 10, seq1 = (r + 8) & 1023;
                if (s0 == 2) {
                    int z0 = b0i * 4 + h, z1 = b1i * 4 + h;
                    g_vt[((size_t)z0 * 192 + dh) * 1024 + seq0]     = __float2half_rn(acc[mt][nt][0]);
                    g_vt[((size_t)z0 * 192 + dh + 1) * 1024 + seq0] = __float2half_rn(acc[mt][nt][1]);
                    g_vt[((size_t)z1 * 192 + dh) * 1024 + seq1]     = __float2half_rn(acc[mt][nt][2]);
                    g_vt[((size_t)z1 * 192 + dh + 1) * 1024 + seq1] = __float2half_rn(acc[mt][nt][3]);
                } else {
                    __half* dst = (s0 == 0) ? g_q : g_k;
                    uint32_t p0 = pack_h2(acc[mt][nt][0], acc[mt][nt][1]);
                    uint32_t p1 = pack_h2(acc[mt][nt][2], acc[mt][nt][3]);
                    *reinterpret_cast<uint32_t*>(
                        dst + ((size_t)(b0i * 4 + h) * 1024 + seq0) * 192 + dh) = p0;
                    *reinterpret_cast<uint32_t*>(
                        dst + ((size_t)(b1i * 4 + h) * 1024 + seq1) * 192 + dh) = p1;
                }
            }
        }
}

// ---------------------------------------------------------------------------
// Flash attention (fp16 operands): per CTA 64 q-rows x one (b,h). 256 threads,
// 8 warps (wm 2 x wn 4). Phase 1 warp tile 32x32; Phase 2 warp tile 32x48.
// Panels (word = half2, rows of 32 words = 64 halves):
//   Q:  3 panels [64][64h]   = 3*2048 w
//   KV: chain per tile: 3 K panels [128][64h] (4096 w) + 2 V panels [192][64h]
//       (6144 w); 3 rotating buffers of 6144 w
//   P:  2 panels [64][64h]   = 4096 w (written as half2 pairs)
// smem words: Q 6144 | KV 18432 | P 4096 | red 256 = 28928 (113 KB)
// ---------------------------------------------------------------------------
constexpr int FS_Q   = 0;
constexpr int FS_KV  = 6144;
constexpr int FS_P   = 24576;
constexpr int FS_RED = 28672;
constexpr int FS_TOT = 28928;

__global__ __launch_bounds__(256, 1) void flash_attn(const float* __restrict__ temp) {
    extern __shared__ uint32_t smw[];
    const uint32_t smBase = (uint32_t)__cvta_generic_to_shared(smw);

    const int tid  = threadIdx.x;
    const int lane = tid & 31;
    const int w    = tid >> 5;       // 0..7
    const int wm   = w & 1;
    const int wn   = w >> 1;         // 0..3
    const int q    = lane >> 2;
    const int lq   = lane & 3;
    const int z    = blockIdx.y;
    const int m0   = blockIdx.x * 64;

    const __half* Qz = g_q  + (size_t)z * HW * DHd;
    const __half* Kz = g_k  + (size_t)z * HW * DHd;
    const __half* Vz = g_vt + (size_t)z * DHd * HW;
    const float ts = temp[z & 3];

    // Q load: 3 panels [64][64 halves] = 1536 16B-chunks
#pragma unroll
    for (int i = 0; i < 6; i++) {
        int idx = tid + 256 * i;
        int c4 = idx & 7, r = (idx >> 3) & 63, p = idx >> 9;
        uint32_t dst = smBase + (uint32_t)(FS_Q + p * 2048 + r * 32 +
                                           ((c4 * 4) ^ (4 * (r & 7)))) * 4u;
        cp_async16(dst, Qz + (size_t)(m0 + r) * 192 + p * 64 + c4 * 8);
    }
    cp_commit();

    auto issuePanel = [&](int g) {
        int t = g / 5, i = g % 5, buf = g % 3;
        uint32_t base = smBase + (uint32_t)(FS_KV + buf * 6144) * 4u;
        if (i < 3) {               // K panel: 128 rows x 64 halves (1024 chunks)
#pragma unroll
            for (int j = 0; j < 4; j++) {
                int idx = tid + 256 * j;
                int c4 = idx & 7, r = idx >> 3;
                cp_async16(base + (uint32_t)(r * 32 + ((c4 * 4) ^ (4 * (r & 7)))) * 4u,
                           Kz + (size_t)(t * 128 + r) * 192 + i * 64 + c4 * 8);
            }
        } else {                   // V panel: 192 dh-rows x 64 seq halves (1536 chunks)
            int pv = i - 3;
#pragma unroll
            for (int j = 0; j < 6; j++) {
                int idx = tid + 256 * j;
                int c4 = idx & 7, r = idx >> 3;
                cp_async16(base + (uint32_t)(r * 32 + ((c4 * 4) ^ (4 * (r & 7)))) * 4u,
                           Vz + (size_t)r * 1024 + t * 128 + pv * 64 + c4 * 8);
            }
        }
    };
    issuePanel(0); cp_commit();
    issuePanel(1); cp_commit();

    constexpr float L2E = 1.4426950408889634f;
    float m_run[2][2] = {{-1e30f, -1e30f}, {-1e30f, -1e30f}};
    float l_run[2][2] = {{0.f, 0.f}, {0.f, 0.f}};
    float acc_o[2][6][4];
#pragma unroll
    for (int mt = 0; mt < 2; mt++)
#pragma unroll
        for (int nt = 0; nt < 6; nt++)
#pragma unroll
            for (int k = 0; k < 4; k++) acc_o[mt][nt][k] = 0.f;

    const int sw = 4 * q;
    float* sRed = reinterpret_cast<float*>(smw + FS_RED);

    for (int t = 0; t < 8; t++) {
        float acc_s[2][4][4];
#pragma unroll
        for (int mt = 0; mt < 2; mt++)
#pragma unroll
            for (int nt = 0; nt < 4; nt++)
#pragma unroll
                for (int k = 0; k < 4; k++) acc_s[mt][nt][k] = 0.f;

        // ---------- phase 1: S = Q K^T (3 dh-panels of 64 halves) ----------
        for (int p = 0; p < 3; p++) {
            int g = t * 5 + p;
            cp_wait<1>();
            __syncthreads();
            if (g + 2 < 40) issuePanel(g + 2);
            cp_commit();
            const uint32_t* Ap = smw + FS_Q + p * 2048;
            const uint32_t* Bp = smw + FS_KV + (g % 3) * 6144;
#pragma unroll
            for (int ks = 0; ks < 4; ks++) {
                const int c0 = (ks * 8 + lq) ^ sw;
                const int c1 = (ks * 8 + 4 + lq) ^ sw;
                uint32_t a[2][4];
#pragma unroll
                for (int mt = 0; mt < 2; mt++) {
                    int rb = (wm * 32 + mt * 16 + q) * 32;
                    a[mt][0] = Ap[rb + c0];
                    a[mt][1] = Ap[rb + 256 + c0];
                    a[mt][2] = Ap[rb + c1];
                    a[mt][3] = Ap[rb + 256 + c1];
                }
#pragma unroll
                for (int nt = 0; nt < 4; nt++) {
                    uint32_t b[2];
                    int nb = (wn * 32 + nt * 8 + q) * 32;
                    b[0] = Bp[nb + c0];
                    b[1] = Bp[nb + c1];
#pragma unroll
                    for (int mt = 0; mt < 2; mt++)
                        mma_f16(acc_s[mt][nt], a[mt], b);
                }
            }
        }

        // ---------- online softmax ----------
        float tmax[2][2], corr[2][2], rsum[2][2];
        {
            float rmax[2][2] = {{-1e30f, -1e30f}, {-1e30f, -1e30f}};
#pragma unroll
            for (int mt = 0; mt < 2; mt++)
#pragma unroll
                for (int nt = 0; nt < 4; nt++)
#pragma unroll
                    for (int j = 0; j < 4; j++) {
                        float v = acc_s[mt][nt][j] * ts;
                        acc_s[mt][nt][j] = v;
                        rmax[mt][j >> 1] = fmaxf(rmax[mt][j >> 1], v);
                    }
#pragma unroll
            for (int mt = 0; mt < 2; mt++)
#pragma unroll
                for (int h2 = 0; h2 < 2; h2++) {
                    float v = rmax[mt][h2];
                    v = fmaxf(v, __shfl_xor_sync(0xFFFFFFFF, v, 1));
                    v = fmaxf(v, __shfl_xor_sync(0xFFFFFFFF, v, 2));
                    rmax[mt][h2] = v;
                }
            if (lq == 0) {
#pragma unroll
                for (int mt = 0; mt < 2; mt++)
#pragma unroll
                    for (int h2 = 0; h2 < 2; h2++)
                        sRed[wn * 64 + wm * 32 + mt * 16 + q + h2 * 8] = rmax[mt][h2];
            }
            __syncthreads();
#pragma unroll
            for (int mt = 0; mt < 2; mt++)
#pragma unroll
                for (int h2 = 0; h2 < 2; h2++) {
                    int rr = wm * 32 + mt * 16 + q + h2 * 8;
                    tmax[mt][h2] = fmaxf(fmaxf(sRed[rr], sRed[64 + rr]),
                                         fmaxf(sRed[128 + rr], sRed[192 + rr]));
                }
        }
#pragma unroll
        for (int mt = 0; mt < 2; mt++)
#pragma unroll
            for (int h2 = 0; h2 < 2; h2++) {
                float nm = fmaxf(m_run[mt][h2], tmax[mt][h2]);
                corr[mt][h2] = exp2f((m_run[mt][h2] - nm) * L2E);
                m_run[mt][h2] = nm;
                rsum[mt][h2] = 0.f;
            }
#pragma unroll
        for (int mt = 0; mt < 2; mt++)
#pragma unroll
            for (int nt = 0; nt < 4; nt++)
#pragma unroll
                for (int j = 0; j < 4; j++) {
                    float pv = exp2f((acc_s[mt][nt][j] - m_run[mt][j >> 1]) * L2E);
                    acc_s[mt][nt][j] = pv;
                    rsum[mt][j >> 1] += pv;
                }
#pragma unroll
        for (int mt = 0; mt < 2; mt++)
#pragma unroll
            for (int h2 = 0; h2 < 2; h2++) {
                float v = rsum[mt][h2];
                v += __shfl_xor_sync(0xFFFFFFFF, v, 1);
                v += __shfl_xor_sync(0xFFFFFFFF, v, 2);
                rsum[mt][h2] = v;
            }
        __syncthreads();
        if (lq == 0) {
#pragma unroll
            for (int mt = 0; mt < 2; mt++)
#pragma unroll
                for (int h2 = 0; h2 < 2; h2++)
                    sRed[wn * 64 + wm * 32 + mt * 16 + q + h2 * 8] = rsum[mt][h2];
        }
        __syncthreads();
#pragma unroll
        for (int mt = 0; mt < 2; mt++)
#pragma unroll
            for (int h2 = 0; h2 < 2; h2++) {
                int rr = wm * 32 + mt * 16 + q + h2 * 8;
                float tsum = sRed[rr] + sRed[64 + rr] + sRed[128 + rr] + sRed[192 + rr];
                l_run[mt][h2] = l_run[mt][h2] * corr[mt][h2] + tsum;
            }
        // rescale O
#pragma unroll
        for (int mt = 0; mt < 2; mt++)
#pragma unroll
            for (int nt = 0; nt < 6; nt++) {
                acc_o[mt][nt][0] *= corr[mt][0];
                acc_o[mt][nt][1] *= corr[mt][0];
                acc_o[mt][nt][2] *= corr[mt][1];
                acc_o[mt][nt][3] *= corr[mt][1];
            }
        // store P (fp16 half2 pairs). col c = wn*32 + nt*8 + 2lq (even);
        // panel = c/64 = wn>>1; word in row = ((c%64)/2) ^ (4*(row&7))
#pragma unroll
        for (int mt = 0; mt < 2; mt++)
#pragma unroll
            for (int nt = 0; nt < 4; nt++) {
                int r0 = wm * 32 + mt * 16 + q;
                int wbase = (wn & 1) * 16 + nt * 4 + lq;
                uint32_t* pp = smw + FS_P + (wn >> 1) * 2048;
                pp[r0 * 32 + (wbase ^ sw)]       = pack_h2(acc_s[mt][nt][0], acc_s[mt][nt][1]);
                pp[(r0 + 8) * 32 + (wbase ^ sw)] = pack_h2(acc_s[mt][nt][2], acc_s[mt][nt][3]);
            }
        __syncthreads();

        // ---------- phase 2: O += P V (2 seq-panels of 64 halves) ----------
        for (int pv = 0; pv < 2; pv++) {
            int g = t * 5 + 3 + pv;
            cp_wait<1>();
            __syncthreads();
            if (g + 2 < 40) issuePanel(g + 2);
            cp_commit();
            const uint32_t* Ap = smw + FS_P + pv * 2048;
            const uint32_t* Bp = smw + FS_KV + (g % 3) * 6144;
#pragma unroll
            for (int ks = 0; ks < 4; ks++) {
                const int c0 = (ks * 8 + lq) ^ sw;
                const int c1 = (ks * 8 + 4 + lq) ^ sw;
                uint32_t a[2][4];
#pragma unroll
                for (int mt = 0; mt < 2; mt++) {
                    int rb = (wm * 32 + mt * 16 + q) * 32;
                    a[mt][0] = Ap[rb + c0];
                    a[mt][1] = Ap[rb + 256 + c0];
                    a[mt][2] = Ap[rb + c1];
                    a[mt][3] = Ap[rb + 256 + c1];
                }
#pragma unroll
                for (int nt = 0; nt < 6; nt++) {
                    uint32_t b[2];
                    int nb = (wn * 48 + nt * 8 + q) * 32;
                    b[0] = Bp[nb + c0];
                    b[1] = Bp[nb + c1];
#pragma unroll
                    for (int mt = 0; mt < 2; mt++)
                        mma_f16(acc_o[mt][nt], a[mt], b);
                }
            }
        }
    }

    // ---------- epilogue: O /= l, merged-head fp16 store ----------
    int b = z >> 2, h = z & 3;
    float inv[2][2];
#pragma unroll
    for (int mt = 0; mt < 2; mt++)
#pragma unroll
        for (int h2 = 0; h2 < 2; h2++) inv[mt][h2] = 1.f / l_run[mt][h2];
#pragma unroll
    for (int mt = 0; mt < 2; mt++)
#pragma unroll
        for (int nt = 0; nt < 6; nt++) {
            int rl = wm * 32 + mt * 16 + q;
            int col = wn * 48 + nt * 8 + 2 * lq;
            uint32_t p0 = pack_h2(acc_o[mt][nt][0] * inv[mt][0],
                                  acc_o[mt][nt][1] * inv[mt][0]);
            uint32_t p1 = pack_h2(acc_o[mt][nt][2] * inv[mt][1],
                                  acc_o[mt][nt][3] * inv[mt][1]);
            *reinterpret_cast<uint32_t*>(
                g_om + ((size_t)(b * HW + m0 + rl)) * DIM + h * DHd + col) = p0;
            *reinterpret_cast<uint32_t*>(
                g_om + ((size_t)(b * HW + m0 + rl + 8)) * DIM + h * DHd + col) = p1;
        }
}

// ---------------------------------------------------------------------------
// Producers / elementwise
// ---------------------------------------------------------------------------
__global__ void permute_t(const float* __restrict__ x,
                          const float* __restrict__ pos) {
    __shared__ float tile[32][33];
    int bz = blockIdx.z, hw0 = blockIdx.y * 32, cd0 = blockIdx.x * 32;
    int tx = threadIdx.x, ty = threadIdx.y;
#pragma unroll
    for (int k = 0; k < 4; k++) {
        int cd = cd0 + ty + 8 * k;
        tile[ty + 8 * k][tx] = x[((size_t)bz * 768 + cd) * 1024 + hw0 + tx];
    }
    __syncthreads();
#pragma unroll
    for (int k = 0; k < 4; k++) {
        int hw = hw0 + ty + 8 * k;
        int cd = cd0 + tx;
        g_t[((size_t)bz * 1024 + hw) * 768 + cd] =
            __float2half_rn(tile[tx][ty + 8 * k] + pos[(size_t)hw * 768 + cd]);
    }
}

__global__ void cvt_weights(const float* __restrict__ qkv_w,
                            const float* __restrict__ proj_w) {
    int i = blockIdx.x * 256 + threadIdx.x;
    if (i < 3 * DIM * DIM) g_wq[i] = __float2half_rn(qkv_w[i]);
    if (i < DIM * DIM)     g_wp[i] = __float2half_rn(proj_w[i]);
}

// l2norm over seq axis (split): partials -> inv -> scale
__global__ void l2_part() {
    int chunk = blockIdx.x, z = blockIdx.y, which = blockIdx.z;
    const __half* p = (which ? g_k : g_q) + ((size_t)z * HW + chunk * 128) * DHd;
    int col = threadIdx.x;
    float ss = 0.f;
#pragma unroll 4
    for (int r = 0; r < 128; r++) {
        float v = __half2float(p[(size_t)r * DHd + col]);
        ss += v * v;
    }
    g_part[(((size_t)which * BH + z) * 8 + chunk) * DHd + col] = ss;
}

__global__ void l2_inv() {
    int which = blockIdx.x >> 5, z = blockIdx.x & 31;
    int col = threadIdx.x;
    float ss = 0.f;
#pragma unroll
    for (int c = 0; c < 8; c++)
        ss += g_part[(((size_t)which * BH + z) * 8 + c) * DHd + col];
    g_inv[((size_t)which * BH + z) * DHd + col] = 1.f / fmaxf(sqrtf(ss), 1e-12f);
}

// scale q/k in half2 units: per (which,z): 1024*96 half2
__global__ void l2_scale() {
    int which = blockIdx.z, z = blockIdx.y;
    int i = blockIdx.x * 256 + threadIdx.x;           // < 98304
    int seq = i / 96, c2 = i % 96;
    __half2* p = reinterpret_cast<__half2*>((which ? g_k : g_q)) +
                 ((size_t)z * HW + seq) * 96 + c2;
    float2 v = __half22float2(*p);
    const float* ivp = g_inv + ((size_t)which * BH + z) * DHd + c2 * 2;
    *p = __floats2half2_rn(v.x * ivp[0], v.y * ivp[1]);
}

__global__ void ln_stats() {
    __shared__ float red[256];
    int row = blockIdx.x;
    int tid = threadIdx.x;
    const float* basep = g_proj + (size_t)row * DIM;

    float v[3];
    float s = 0.f;
#pragma unroll
    for (int j = 0; j < 3; j++) { v[j] = basep[tid + 256 * j]; s += v[j]; }
    red[tid] = s; __syncthreads();
    for (int st = 128; st > 0; st >>= 1) {
        if (tid < st) red[tid] += red[tid + st];
        __syncthreads();
    }
    float mu = red[0] * (1.f / DIM); __syncthreads();

    float s2 = 0.f;
#pragma unroll
    for (int j = 0; j < 3; j++) { float d = v[j] - mu; s2 += d * d; }
    red[tid] = s2; __syncthreads();
    for (int st = 128; st > 0; st >>= 1) {
        if (tid < st) red[tid] += red[tid + st];
        __syncthreads();
    }
    if (tid == 0) {
        g_mu[row] = mu;
        g_rs[row] = rsqrtf(red[0] * (1.f / DIM) + 1e-5f);
    }
}

__global__ void ln_apply(const float* __restrict__ x,
                         const float* __restrict__ gamma,
                         const float* __restrict__ beta) {
    __shared__ float tile[32][33];
    int bz = blockIdx.z, hw0 = blockIdx.y * 32, cd0 = blockIdx.x * 32;
    int tx = threadIdx.x, ty = threadIdx.y;
#pragma unroll
    for (int k = 0; k < 4; k++) {
        int hw = hw0 + ty + 8 * k;
        int row = bz * 1024 + hw;
        int cd = cd0 + tx;
        float v = g_proj[(size_t)row * 768 + cd];
        tile[ty + 8 * k][tx] = (v - g_mu[row]) * g_rs[row] * gamma[cd] + beta[cd];
    }
    __syncthreads();
#pragma unroll
    for (int k = 0; k < 4; k++) {
        int cd = cd0 + ty + 8 * k;
        int hw = hw0 + tx;
        size_t oi = ((size_t)bz * 768 + cd) * 1024 + hw;
        g_y[oi] = tile[tx][ty + 8 * k] + x[oi];
    }
}

__global__ __launch_bounds__(1024) void dwconv(const float* __restrict__ dw_w,
                                               const float* __restrict__ dw_b) {
    __shared__ float tile[3][34][34];
    __shared__ float wsh[27];
    int bcd = blockIdx.x;
    int d  = bcd & 7;
    int bc = bcd >> 3;
    int c  = bc % Cc;
    int tid = threadIdx.x;

    if (tid < 27) wsh[tid] = dw_w[c * 27 + tid];

    for (int idx = tid; idx < 3 * 34 * 34; idx += 1024) {
        int pl = idx / 1156;
        int r  = (idx - pl * 1156) / 34;
        int cc = idx - pl * 1156 - r * 34;
        int dd = d - 1 + pl, hh = r - 1, ww = cc - 1;
        float val = 0.f;
        if (dd >= 0 && dd < Dd && hh >= 0 && hh < Hh && ww >= 0 && ww < Ww)
            val = g_y[(bc * Dd + dd) * HW + hh * Ww + ww];
        tile[pl][r][cc] = val;
    }
    __syncthreads();

    int h = tid >> 5, w = tid & 31;
    float s = 0.f;
#pragma unroll
    for (int pl = 0; pl < 3; pl++)
#pragma unroll
        for (int i = 0; i < 3; i++)
#pragma unroll
            for (int j = 0; j < 3; j++)
                s += tile[pl][h + i][w + j] * wsh[pl * 9 + i * 3 + j];
    g_z[bcd * HW + tid] = s + dw_b[c];
}

__global__ __launch_bounds__(128) void pwconv(const float* __restrict__ pw_w,
                                              const float* __restrict__ pw_b,
                                              float* __restrict__ out) {
    __shared__ float wsh[Cc * Cc];
    int b = blockIdx.y;
    int pos = blockIdx.x * 128 + threadIdx.x;
    constexpr int SP = Dd * HW;

    for (int i = threadIdx.x; i < Cc * Cc; i += 128) wsh[i] = pw_w[i];
    __syncthreads();

    float acc[Cc];
#pragma unroll
    for (int co = 0; co < Cc; co++) acc[co] = 0.f;

    const float* zb = g_z + b * Cc * SP + pos;
    for (int ci = 0; ci < Cc; ci++) {
        float zv = zb[ci * SP];
#pragma unroll
        for (int co = 0; co < Cc; co++) acc[co] += zv * wsh[co * Cc + ci];
    }

    const float* yb = g_y + b * Cc * SP + pos;
    float* ob = out + b * Cc * SP + pos;
#pragma unroll
    for (int co = 0; co < Cc; co++)
        ob[co * SP] = yb[co * SP] + acc[co] + pw_b[co];
}

// ---------------------------------------------------------------------------
// Launch
// ---------------------------------------------------------------------------
extern "C" void kernel_launch(void* const* d_in, const int* in_sizes, int n_in,
                              void* d_out, int out_size) {
    const float* x      = (const float*)d_in[0];
    const float* pos    = (const float*)d_in[1];
    const float* qkv_w  = (const float*)d_in[2];
    const float* proj_w = (const float*)d_in[3];
    const float* proj_b = (const float*)d_in[4];
    const float* temp   = (const float*)d_in[5];
    const float* ln_g   = (const float*)d_in[6];
    const float* ln_b   = (const float*)d_in[7];
    const float* dw_w   = (const float*)d_in[8];
    const float* dw_b   = (const float*)d_in[9];
    const float* pw_w   = (const float*)d_in[10];
    const float* pw_b   = (const float*)d_in[11];
    float* out = (float*)d_out;

    constexpr int SMEM256 = 3 * 12288 * 4;           // 144 KB
    constexpr int FSMEM   = FS_TOT * 4;              // 113 KB
    cudaFuncSetAttribute(tc_gemm<0>, cudaFuncAttributeMaxDynamicSharedMemorySize, SMEM256);
    cudaFuncSetAttribute(tc_gemm<3>, cudaFuncAttributeMaxDynamicSharedMemorySize, SMEM256);
    cudaFuncSetAttribute(flash_attn, cudaFuncAttributeMaxDynamicSharedMemorySize, FSMEM);

    permute_t<<<dim3(24, 32, 8), dim3(32, 8)>>>(x, pos);
    cvt_weights<<<(3 * DIM * DIM + 255) / 256, 256>>>(qkv_w, proj_w);
    tc_gemm<0><<<dim3(9, 64, 1), 512, SMEM256>>>(nullptr);
    l2_part<<<dim3(8, 32, 2), 192>>>();
    l2_inv<<<64, 192>>>();
    l2_scale<<<dim3(384, 32, 2), 256>>>();
    flash_attn<<<dim3(16, 32), 256, FSMEM>>>(temp);
    tc_gemm<3><<<dim3(3, 64, 1), 512, SMEM256>>>(proj_b);
    ln_stats<<<SEQROWS, 256>>>();
    ln_apply<<<dim3(24, 32, 8), dim3(32, 8)>>>(x, ln_g, ln_b);
    dwconv<<<Bn * Cc * Dd, 1024>>>(dw_w, dw_b);
    pwconv<<<dim3(64, Bn, 1), 128>>>(pw_w, pw_b, out);
}

// round 11
// speedup vs baseline: 1.7237x; 1.0454x over previous
#include <cuda_runtime.h>
#include <cuda_fp16.h>
#include <math.h>
#include <stdint.h>

// ---------------------------------------------------------------------------
// Problem constants
// ---------------------------------------------------------------------------
constexpr int Bn = 8, Cc = 96, Dd = 8, Hh = 32, Ww = 32;
constexpr int HW = Hh * Ww;          // 1024
constexpr int DIM = Cc * Dd;         // 768
constexpr int NH = 4;
constexpr int DHd = DIM / NH;        // 192
constexpr int SEQROWS = Bn * HW;     // 8192
constexpr int BH = Bn * NH;          // 32

// ---------------------------------------------------------------------------
// Scratch (device globals -- no allocations allowed). GEMM operands in fp16.
// ---------------------------------------------------------------------------
__device__ __align__(16) __half g_t[SEQROWS * DIM];
__device__ __align__(16) __half g_wq[3 * DIM * DIM];
__device__ __align__(16) __half g_wp[DIM * DIM];
__device__ __align__(16) __half g_q[BH * HW * DHd];
__device__ __align__(16) __half g_k[BH * HW * DHd];
__device__ __align__(16) __half g_vt[BH * DHd * HW];    // V^T: [z][dh][seq]
__device__ __align__(16) __half g_om[SEQROWS * DIM];
__device__ float g_proj[SEQROWS * DIM];
__device__ float g_y[Bn * Cc * Dd * HW];
__device__ float g_z[Bn * Cc * Dd * HW];
__device__ float g_part[2 * BH * 8 * DHd];
__device__ float g_inv[2 * BH * DHd];
__device__ float g_psum[SEQROWS * 3];                   // LN partial sums
__device__ float g_psq[SEQROWS * 3];                    // LN partial sumsq
__device__ float g_mu[SEQROWS];
__device__ float g_rs[SEQROWS];

// ---------------------------------------------------------------------------
// Helpers (baseline PTX only)
// ---------------------------------------------------------------------------
__device__ __forceinline__ void mma_f16(float* d, const uint32_t* a,
                                        const uint32_t* b) {
    asm volatile(
        "mma.sync.aligned.m16n8k16.row.col.f32.f16.f16.f32 "
        "{%0,%1,%2,%3}, {%4,%5,%6,%7}, {%8,%9}, {%0,%1,%2,%3};"
        : "+f"(d[0]), "+f"(d[1]), "+f"(d[2]), "+f"(d[3])
        : "r"(a[0]), "r"(a[1]), "r"(a[2]), "r"(a[3]), "r"(b[0]), "r"(b[1]));
}
__device__ __forceinline__ void cp_async16(uint32_t dst, const void* src) {
    asm volatile("cp.async.cg.shared.global [%0], [%1], 16;"
                 :: "r"(dst), "l"(src) : "memory");
}
__device__ __forceinline__ void cp_commit() {
    asm volatile("cp.async.commit_group;" ::: "memory");
}
template <int N>
__device__ __forceinline__ void cp_wait() {
    asm volatile("cp.async.wait_group %0;" :: "n"(N) : "memory");
}
__device__ __forceinline__ uint32_t pack_h2(float x, float y) {
    __half2 h = __floats2half2_rn(x, y);
    return *reinterpret_cast<uint32_t*>(&h);
}

// ---------------------------------------------------------------------------
// fp16 GEMM for QKV / PROJ:  C[M,N] = A[M,K] * B[N,K]^T, K=768 halves.
// Block tile 128 x 256 x 64(halves), 512 threads, warp tile 32x64,
// 3-stage cp.async. MODE 3 additionally reduces per-row (sum, sumsq) LN
// partials into g_psum/g_psq (one slot per N-tile).
// ---------------------------------------------------------------------------
template <int MODE>
__global__ __launch_bounds__(512, 1) void tc_gemm(const float* __restrict__ bias) {
    constexpr int BK  = 64;                  // halves per stage
    constexpr int KK  = 768;
    constexpr int LD  = 768;
    constexpr int T   = KK / BK;             // 12
    constexpr int AW  = 128 * 32;            // words per A stage
    constexpr int BWD = 256 * 32;            // words per B stage
    constexpr int STG = AW + BWD;            // 12288 words
    constexpr int WN  = 64;
    constexpr int NT  = 8;

    extern __shared__ uint32_t smw[];
    const uint32_t smBase = (uint32_t)__cvta_generic_to_shared(smw);

    const int tid  = threadIdx.x;
    const int lane = tid & 31;
    const int w    = tid >> 5;
    const int wm   = w & 3;
    const int wn   = w >> 2;
    const int q    = lane >> 2;
    const int lq   = lane & 3;
    const int m0   = blockIdx.y * 128;
    const int n0   = blockIdx.x * 256;

    const __half* gA = (MODE == 0) ? g_t  : g_om;
    const __half* gB = (MODE == 0) ? g_wq : g_wp;

    const __half* aRow = gA + (size_t)m0 * LD;
    const __half* bRow = gB + (size_t)n0 * LD;

    auto loadStage = [&](int it, int s) {
        const __half* aP = aRow + it * BK;
        const __half* bP = bRow + it * BK;
        uint32_t sA = smBase + (uint32_t)(s * STG) * 4u;
        uint32_t sB = sA + AW * 4u;
#pragma unroll
        for (int i = 0; i < 2; i++) {
            int idx = tid + 512 * i;
            int r = idx >> 3, c4 = idx & 7;
            uint32_t dst = sA + (uint32_t)(r * 32 + ((c4 * 4) ^ (4 * (r & 7)))) * 4u;
            cp_async16(dst, aP + (size_t)r * LD + c4 * 8);
        }
#pragma unroll
        for (int i = 0; i < 4; i++) {
            int idx = tid + 512 * i;
            int r = idx >> 3, c4 = idx & 7;
            uint32_t dst = sB + (uint32_t)(r * 32 + ((c4 * 4) ^ (4 * (r & 7)))) * 4u;
            cp_async16(dst, bP + (size_t)r * LD + c4 * 8);
        }
    };

    float acc[2][NT][4];
#pragma unroll
    for (int mt = 0; mt < 2; mt++)
#pragma unroll
        for (int nt = 0; nt < NT; nt++)
#pragma unroll
            for (int k = 0; k < 4; k++) acc[mt][nt][k] = 0.f;

#pragma unroll
    for (int s = 0; s < 3; s++) { loadStage(s, s); cp_commit(); }

    const int sw = 4 * q;

    for (int it = 0; it < T; ++it) {
        cp_wait<2>();
        __syncthreads();

        const int st = it % 3;
        const uint32_t* A_ = smw + st * STG;
        const uint32_t* B_ = A_ + AW;
#pragma unroll
        for (int ks = 0; ks < 4; ks++) {
            const int c0 = (ks * 8 + lq) ^ sw;
            const int c1 = (ks * 8 + 4 + lq) ^ sw;
            uint32_t a[2][4];
#pragma unroll
            for (int mt = 0; mt < 2; mt++) {
                int rb = (wm * 32 + mt * 16 + q) * 32;
                a[mt][0] = A_[rb + c0];
                a[mt][1] = A_[rb + 256 + c0];
                a[mt][2] = A_[rb + c1];
                a[mt][3] = A_[rb + 256 + c1];
            }
            uint32_t b[NT][2];
#pragma unroll
            for (int nt = 0; nt < NT; nt++) {
                int nb = (wn * WN + nt * 8 + q) * 32;
                b[nt][0] = B_[nb + c0];
                b[nt][1] = B_[nb + c1];
            }
#pragma unroll
            for (int mt = 0; mt < 2; mt++)
#pragma unroll
                for (int nt = 0; nt < NT; nt++)
                    mma_f16(acc[mt][nt], a[mt], b[nt]);
        }
        __syncthreads();
        if (it + 3 < T) loadStage(it + 3, st);
        cp_commit();
    }

    // ---------------- epilogue ----------------
    if constexpr (MODE == 3) {
        float sums[2][2] = {{0.f, 0.f}, {0.f, 0.f}};
        float sqs [2][2] = {{0.f, 0.f}, {0.f, 0.f}};
#pragma unroll
        for (int mt = 0; mt < 2; mt++)
#pragma unroll
            for (int nt = 0; nt < NT; nt++) {
                int r = m0 + wm * 32 + mt * 16 + q;
                int c = n0 + wn * WN + nt * 8 + lq * 2;
                float2 bb = *reinterpret_cast<const float2*>(bias + c);
                float2 v0 = {acc[mt][nt][0] + bb.x, acc[mt][nt][1] + bb.y};
                float2 v1 = {acc[mt][nt][2] + bb.x, acc[mt][nt][3] + bb.y};
                *reinterpret_cast<float2*>(g_proj + (size_t)r * DIM + c) = v0;
                *reinterpret_cast<float2*>(g_proj + (size_t)(r + 8) * DIM + c) = v1;
                sums[mt][0] += v0.x + v0.y;
                sqs [mt][0] += v0.x * v0.x + v0.y * v0.y;
                sums[mt][1] += v1.x + v1.y;
                sqs [mt][1] += v1.x * v1.x + v1.y * v1.y;
            }
        // reduce over lq (lanes q*4+lq): xor 1, xor 2
#pragma unroll
        for (int mt = 0; mt < 2; mt++)
#pragma unroll
            for (int h = 0; h < 2; h++) {
                sums[mt][h] += __shfl_xor_sync(0xFFFFFFFF, sums[mt][h], 1);
                sums[mt][h] += __shfl_xor_sync(0xFFFFFFFF, sums[mt][h], 2);
                sqs[mt][h]  += __shfl_xor_sync(0xFFFFFFFF, sqs[mt][h], 1);
                sqs[mt][h]  += __shfl_xor_sync(0xFFFFFFFF, sqs[mt][h], 2);
            }
        float* sSum = reinterpret_cast<float*>(smw);          // [4][128]
        float* sSq  = sSum + 512;                             // [4][128]
        __syncthreads();
        if (lq == 0) {
#pragma unroll
            for (int mt = 0; mt < 2; mt++)
#pragma unroll
                for (int h = 0; h < 2; h++) {
                    int r = wm * 32 + mt * 16 + q + h * 8;
                    sSum[wn * 128 + r] = sums[mt][h];
                    sSq [wn * 128 + r] = sqs[mt][h];
                }
        }
        __syncthreads();
        if (tid < 128) {
            float s = sSum[tid] + sSum[128 + tid] + sSum[256 + tid] + sSum[384 + tid];
            float qq = sSq[tid] + sSq[128 + tid] + sSq[256 + tid] + sSq[384 + tid];
            g_psum[(size_t)(m0 + tid) * 3 + blockIdx.x] = s;
            g_psq [(size_t)(m0 + tid) * 3 + blockIdx.x] = qq;
        }
    } else {
        const int s0 = n0 / 768;
#pragma unroll
        for (int mt = 0; mt < 2; mt++)
#pragma unroll
            for (int nt = 0; nt < NT; nt++) {
                int r = m0 + wm * 32 + mt * 16 + q;
                int c = n0 + wn * WN + nt * 8 + lq * 2;
                int nl = c - s0 * 768;
                int h = nl / 192, dh = nl % 192;
                int b0i = r >> 10, seq0 = r & 1023;
                int b1i = (r + 8) >> 10, seq1 = (r + 8) & 1023;
                if (s0 == 2) {
                    int z0 = b0i * 4 + h, z1 = b1i * 4 + h;
                    g_vt[((size_t)z0 * 192 + dh) * 1024 + seq0]     = __float2half_rn(acc[mt][nt][0]);
                    g_vt[((size_t)z0 * 192 + dh + 1) * 1024 + seq0] = __float2half_rn(acc[mt][nt][1]);
                    g_vt[((size_t)z1 * 192 + dh) * 1024 + seq1]     = __float2half_rn(acc[mt][nt][2]);
                    g_vt[((size_t)z1 * 192 + dh + 1) * 1024 + seq1] = __float2half_rn(acc[mt][nt][3]);
                } else {
                    __half* dst = (s0 == 0) ? g_q : g_k;
                    uint32_t p0 = pack_h2(acc[mt][nt][0], acc[mt][nt][1]);
                    uint32_t p1 = pack_h2(acc[mt][nt][2], acc[mt][nt][3]);
                    *reinterpret_cast<uint32_t*>(
                        dst + ((size_t)(b0i * 4 + h) * 1024 + seq0) * 192 + dh) = p0;
                    *reinterpret_cast<uint32_t*>(
                        dst + ((size_t)(b1i * 4 + h) * 1024 + seq1) * 192 + dh) = p1;
                }
            }
    }
}

// combine LN partials -> mu, rstd
__global__ void ln_combine() {
    int row = blockIdx.x * 256 + threadIdx.x;
    if (row >= SEQROWS) return;
    float s  = g_psum[(size_t)row * 3] + g_psum[(size_t)row * 3 + 1] + g_psum[(size_t)row * 3 + 2];
    float qq = g_psq [(size_t)row * 3] + g_psq [(size_t)row * 3 + 1] + g_psq [(size_t)row * 3 + 2];
    float mu = s * (1.f / DIM);
    float var = fmaxf(qq * (1.f / DIM) - mu * mu, 0.f);
    g_mu[row] = mu;
    g_rs[row] = rsqrtf(var + 1e-5f);
}

// ---------------------------------------------------------------------------
// Flash attention (fp16, 2 CTAs/SM): per CTA 64 q-rows x one (b,h).
// 256 threads, 8 warps (wm 2 x wn 4). smem 113 KB -> two CTAs fit.
// ---------------------------------------------------------------------------
constexpr int FS_Q   = 0;
constexpr int FS_KV  = 6144;
constexpr int FS_P   = 24576;
constexpr int FS_RED = 28672;
constexpr int FS_TOT = 28928;

__global__ __launch_bounds__(256, 2) void flash_attn(const float* __restrict__ temp) {
    extern __shared__ uint32_t smw[];
    const uint32_t smBase = (uint32_t)__cvta_generic_to_shared(smw);

    const int tid  = threadIdx.x;
    const int lane = tid & 31;
    const int w    = tid >> 5;       // 0..7
    const int wm   = w & 1;
    const int wn   = w >> 1;         // 0..3
    const int q    = lane >> 2;
    const int lq   = lane & 3;
    const int z    = blockIdx.y;
    const int m0   = blockIdx.x * 64;

    const __half* Qz = g_q  + (size_t)z * HW * DHd;
    const __half* Kz = g_k  + (size_t)z * HW * DHd;
    const __half* Vz = g_vt + (size_t)z * DHd * HW;
    const float ts = temp[z & 3];

    // Q load: 3 panels [64][64 halves]
#pragma unroll
    for (int i = 0; i < 6; i++) {
        int idx = tid + 256 * i;
        int c4 = idx & 7, r = (idx >> 3) & 63, p = idx >> 9;
        uint32_t dst = smBase + (uint32_t)(FS_Q + p * 2048 + r * 32 +
                                           ((c4 * 4) ^ (4 * (r & 7)))) * 4u;
        cp_async16(dst, Qz + (size_t)(m0 + r) * 192 + p * 64 + c4 * 8);
    }
    cp_commit();

    auto issuePanel = [&](int g) {
        int t = g / 5, i = g % 5, buf = g % 3;
        uint32_t base = smBase + (uint32_t)(FS_KV + buf * 6144) * 4u;
        if (i < 3) {               // K panel: 128 rows x 64 halves
#pragma unroll
            for (int j = 0; j < 4; j++) {
                int idx = tid + 256 * j;
                int c4 = idx & 7, r = idx >> 3;
                cp_async16(base + (uint32_t)(r * 32 + ((c4 * 4) ^ (4 * (r & 7)))) * 4u,
                           Kz + (size_t)(t * 128 + r) * 192 + i * 64 + c4 * 8);
            }
        } else {                   // V panel: 192 dh-rows x 64 seq halves
            int pv = i - 3;
#pragma unroll
            for (int j = 0; j < 6; j++) {
                int idx = tid + 256 * j;
                int c4 = idx & 7, r = idx >> 3;
                cp_async16(base + (uint32_t)(r * 32 + ((c4 * 4) ^ (4 * (r & 7)))) * 4u,
                           Vz + (size_t)r * 1024 + t * 128 + pv * 64 + c4 * 8);
            }
        }
    };
    issuePanel(0); cp_commit();
    issuePanel(1); cp_commit();

    constexpr float L2E = 1.4426950408889634f;
    float m_run[2][2] = {{-1e30f, -1e30f}, {-1e30f, -1e30f}};
    float l_run[2][2] = {{0.f, 0.f}, {0.f, 0.f}};
    float acc_o[2][6][4];
#pragma unroll
    for (int mt = 0; mt < 2; mt++)
#pragma unroll
        for (int nt = 0; nt < 6; nt++)
#pragma unroll
            for (int k = 0; k < 4; k++) acc_o[mt][nt][k] = 0.f;

    const int sw = 4 * q;
    float* sRed = reinterpret_cast<float*>(smw + FS_RED);

    for (int t = 0; t < 8; t++) {
        float acc_s[2][4][4];
#pragma unroll
        for (int mt = 0; mt < 2; mt++)
#pragma unroll
            for (int nt = 0; nt < 4; nt++)
#pragma unroll
                for (int k = 0; k < 4; k++) acc_s[mt][nt][k] = 0.f;

        // ---------- phase 1: S = Q K^T ----------
        for (int p = 0; p < 3; p++) {
            int g = t * 5 + p;
            cp_wait<1>();
            __syncthreads();
            if (g + 2 < 40) issuePanel(g + 2);
            cp_commit();
            const uint32_t* Ap = smw + FS_Q + p * 2048;
            const uint32_t* Bp = smw + FS_KV + (g % 3) * 6144;
#pragma unroll
            for (int ks = 0; ks < 4; ks++) {
                const int c0 = (ks * 8 + lq) ^ sw;
                const int c1 = (ks * 8 + 4 + lq) ^ sw;
                uint32_t a[2][4];
#pragma unroll
                for (int mt = 0; mt < 2; mt++) {
                    int rb = (wm * 32 + mt * 16 + q) * 32;
                    a[mt][0] = Ap[rb + c0];
                    a[mt][1] = Ap[rb + 256 + c0];
                    a[mt][2] = Ap[rb + c1];
                    a[mt][3] = Ap[rb + 256 + c1];
                }
#pragma unroll
                for (int nt = 0; nt < 4; nt++) {
                    uint32_t b[2];
                    int nb = (wn * 32 + nt * 8 + q) * 32;
                    b[0] = Bp[nb + c0];
                    b[1] = Bp[nb + c1];
#pragma unroll
                    for (int mt = 0; mt < 2; mt++)
                        mma_f16(acc_s[mt][nt], a[mt], b);
                }
            }
        }

        // ---------- online softmax ----------
        float tmax[2][2], corr[2][2], rsum[2][2];
        {
            float rmax[2][2] = {{-1e30f, -1e30f}, {-1e30f, -1e30f}};
#pragma unroll
            for (int mt = 0; mt < 2; mt++)
#pragma unroll
                for (int nt = 0; nt < 4; nt++)
#pragma unroll
                    for (int j = 0; j < 4; j++) {
                        float v = acc_s[mt][nt][j] * ts;
                        acc_s[mt][nt][j] = v;
                        rmax[mt][j >> 1] = fmaxf(rmax[mt][j >> 1], v);
                    }
#pragma unroll
            for (int mt = 0; mt < 2; mt++)
#pragma unroll
                for (int h2 = 0; h2 < 2; h2++) {
                    float v = rmax[mt][h2];
                    v = fmaxf(v, __shfl_xor_sync(0xFFFFFFFF, v, 1));
                    v = fmaxf(v, __shfl_xor_sync(0xFFFFFFFF, v, 2));
                    rmax[mt][h2] = v;
                }
            if (lq == 0) {
#pragma unroll
                for (int mt = 0; mt < 2; mt++)
#pragma unroll
                    for (int h2 = 0; h2 < 2; h2++)
                        sRed[wn * 64 + wm * 32 + mt * 16 + q + h2 * 8] = rmax[mt][h2];
            }
            __syncthreads();
#pragma unroll
            for (int mt = 0; mt < 2; mt++)
#pragma unroll
                for (int h2 = 0; h2 < 2; h2++) {
                    int rr = wm * 32 + mt * 16 + q + h2 * 8;
                    tmax[mt][h2] = fmaxf(fmaxf(sRed[rr], sRed[64 + rr]),
                                         fmaxf(sRed[128 + rr], sRed[192 + rr]));
                }
        }
#pragma unroll
        for (int mt = 0; mt < 2; mt++)
#pragma unroll
            for (int h2 = 0; h2 < 2; h2++) {
                float nm = fmaxf(m_run[mt][h2], tmax[mt][h2]);
                corr[mt][h2] = exp2f((m_run[mt][h2] - nm) * L2E);
                m_run[mt][h2] = nm;
                rsum[mt][h2] = 0.f;
            }
#pragma unroll
        for (int mt = 0; mt < 2; mt++)
#pragma unroll
            for (int nt = 0; nt < 4; nt++)
#pragma unroll
                for (int j = 0; j < 4; j++) {
                    float pv = exp2f((acc_s[mt][nt][j] - m_run[mt][j >> 1]) * L2E);
                    acc_s[mt][nt][j] = pv;
                    rsum[mt][j >> 1] += pv;
                }
#pragma unroll
        for (int mt = 0; mt < 2; mt++)
#pragma unroll
            for (int h2 = 0; h2 < 2; h2++) {
                float v = rsum[mt][h2];
                v += __shfl_xor_sync(0xFFFFFFFF, v, 1);
                v += __shfl_xor_sync(0xFFFFFFFF, v, 2);
                rsum[mt][h2] = v;
            }
        __syncthreads();
        if (lq == 0) {
#pragma unroll
            for (int mt = 0; mt < 2; mt++)
#pragma unroll
                for (int h2 = 0; h2 < 2; h2++)
                    sRed[wn * 64 + wm * 32 + mt * 16 + q + h2 * 8] = rsum[mt][h2];
        }
        __syncthreads();
#pragma unroll
        for (int mt = 0; mt < 2; mt++)
#pragma unroll
            for (int h2 = 0; h2 < 2; h2++) {
                int rr = wm * 32 + mt * 16 + q + h2 * 8;
                float tsum = sRed[rr] + sRed[64 + rr] + sRed[128 + rr] + sRed[192 + rr];
                l_run[mt][h2] = l_run[mt][h2] * corr[mt][h2] + tsum;
            }
        // rescale O
#pragma unroll
        for (int mt = 0; mt < 2; mt++)
#pragma unroll
            for (int nt = 0; nt < 6; nt++) {
                acc_o[mt][nt][0] *= corr[mt][0];
                acc_o[mt][nt][1] *= corr[mt][0];
                acc_o[mt][nt][2] *= corr[mt][1];
                acc_o[mt][nt][3] *= corr[mt][1];
            }
        // store P (fp16 half2 pairs)
#pragma unroll
        for (int mt = 0; mt < 2; mt++)
#pragma unroll
            for (int nt = 0; nt < 4; nt++) {
                int r0 = wm * 32 + mt * 16 + q;
                int wbase = (wn & 1) * 16 + nt * 4 + lq;
                uint32_t* pp = smw + FS_P + (wn >> 1) * 2048;
                pp[r0 * 32 + (wbase ^ sw)]       = pack_h2(acc_s[mt][nt][0], acc_s[mt][nt][1]);
                pp[(r0 + 8) * 32 + (wbase ^ sw)] = pack_h2(acc_s[mt][nt][2], acc_s[mt][nt][3]);
            }
        __syncthreads();

        // ---------- phase 2: O += P V ----------
        for (int pv = 0; pv < 2; pv++) {
            int g = t * 5 + 3 + pv;
            cp_wait<1>();
            __syncthreads();
            if (g + 2 < 40) issuePanel(g + 2);
            cp_commit();
            const uint32_t* Ap = smw + FS_P + pv * 2048;
            const uint32_t* Bp = smw + FS_KV + (g % 3) * 6144;
#pragma unroll
            for (int ks = 0; ks < 4; ks++) {
                const int c0 = (ks * 8 + lq) ^ sw;
                const int c1 = (ks * 8 + 4 + lq) ^ sw;
                uint32_t a[2][4];
#pragma unroll
                for (int mt = 0; mt < 2; mt++) {
                    int rb = (wm * 32 + mt * 16 + q) * 32;
                    a[mt][0] = Ap[rb + c0];
                    a[mt][1] = Ap[rb + 256 + c0];
                    a[mt][2] = Ap[rb + c1];
                    a[mt][3] = Ap[rb + 256 + c1];
                }
#pragma unroll
                for (int nt = 0; nt < 6; nt++) {
                    uint32_t b[2];
                    int nb = (wn * 48 + nt * 8 + q) * 32;
                    b[0] = Bp[nb + c0];
                    b[1] = Bp[nb + c1];
#pragma unroll
                    for (int mt = 0; mt < 2; mt++)
                        mma_f16(acc_o[mt][nt], a[mt], b);
                }
            }
        }
    }

    // ---------- epilogue: O /= l, merged-head fp16 store ----------
    int b = z >> 2, h = z & 3;
    float inv[2][2];
#pragma unroll
    for (int mt = 0; mt < 2; mt++)
#pragma unroll
        for (int h2 = 0; h2 < 2; h2++) inv[mt][h2] = 1.f / l_run[mt][h2];
#pragma unroll
    for (int mt = 0; mt < 2; mt++)
#pragma unroll
        for (int nt = 0; nt < 6; nt++) {
            int rl = wm * 32 + mt * 16 + q;
            int col = wn * 48 + nt * 8 + 2 * lq;
            uint32_t p0 = pack_h2(acc_o[mt][nt][0] * inv[mt][0],
                                  acc_o[mt][nt][1] * inv[mt][0]);
            uint32_t p1 = pack_h2(acc_o[mt][nt][2] * inv[mt][1],
                                  acc_o[mt][nt][3] * inv[mt][1]);
            *reinterpret_cast<uint32_t*>(
                g_om + ((size_t)(b * HW + m0 + rl)) * DIM + h * DHd + col) = p0;
            *reinterpret_cast<uint32_t*>(
                g_om + ((size_t)(b * HW + m0 + rl + 8)) * DIM + h * DHd + col) = p1;
        }
}

// ---------------------------------------------------------------------------
// Producers / elementwise
// ---------------------------------------------------------------------------
__global__ void permute_t(const float* __restrict__ x,
                          const float* __restrict__ pos) {
    __shared__ float tile[32][33];
    int bz = blockIdx.z, hw0 = blockIdx.y * 32, cd0 = blockIdx.x * 32;
    int tx = threadIdx.x, ty = threadIdx.y;
#pragma unroll
    for (int k = 0; k < 4; k++) {
        int cd = cd0 + ty + 8 * k;
        tile[ty + 8 * k][tx] = x[((size_t)bz * 768 + cd) * 1024 + hw0 + tx];
    }
    __syncthreads();
#pragma unroll
    for (int k = 0; k < 4; k++) {
        int hw = hw0 + ty + 8 * k;
        int cd = cd0 + tx;
        g_t[((size_t)bz * 1024 + hw) * 768 + cd] =
            __float2half_rn(tile[tx][ty + 8 * k] + pos[(size_t)hw * 768 + cd]);
    }
}

__global__ void cvt_weights(const float* __restrict__ qkv_w,
                            const float* __restrict__ proj_w) {
    int i = blockIdx.x * 256 + threadIdx.x;
    if (i < 3 * DIM * DIM) g_wq[i] = __float2half_rn(qkv_w[i]);
    if (i < DIM * DIM)     g_wp[i] = __float2half_rn(proj_w[i]);
}

// l2norm over seq axis (split): partials -> inv -> scale
__global__ void l2_part() {
    int chunk = blockIdx.x, z = blockIdx.y, which = blockIdx.z;
    const __half* p = (which ? g_k : g_q) + ((size_t)z * HW + chunk * 128) * DHd;
    int col = threadIdx.x;
    float ss = 0.f;
#pragma unroll 4
    for (int r = 0; r < 128; r++) {
        float v = __half2float(p[(size_t)r * DHd + col]);
        ss += v * v;
    }
    g_part[(((size_t)which * BH + z) * 8 + chunk) * DHd + col] = ss;
}

__global__ void l2_inv() {
    int which = blockIdx.x >> 5, z = blockIdx.x & 31;
    int col = threadIdx.x;
    float ss = 0.f;
#pragma unroll
    for (int c = 0; c < 8; c++)
        ss += g_part[(((size_t)which * BH + z) * 8 + c) * DHd + col];
    g_inv[((size_t)which * BH + z) * DHd + col] = 1.f / fmaxf(sqrtf(ss), 1e-12f);
}

__global__ void l2_scale() {
    int which = blockIdx.z, z = blockIdx.y;
    int i = blockIdx.x * 256 + threadIdx.x;           // < 98304
    int seq = i / 96, c2 = i % 96;
    __half2* p = reinterpret_cast<__half2*>((which ? g_k : g_q)) +
                 ((size_t)z * HW + seq) * 96 + c2;
    float2 v = __half22float2(*p);
    const float* ivp = g_inv + ((size_t)which * BH + z) * DHd + c2 * 2;
    *p = __floats2half2_rn(v.x * ivp[0], v.y * ivp[1]);
}

__global__ void ln_apply(const float* __restrict__ x,
                         const float* __restrict__ gamma,
                         const float* __restrict__ beta) {
    __shared__ float tile[32][33];
    int bz = blockIdx.z, hw0 = blockIdx.y * 32, cd0 = blockIdx.x * 32;
    int tx = threadIdx.x, ty = threadIdx.y;
#pragma unroll
    for (int k = 0; k < 4; k++) {
        int hw = hw0 + ty + 8 * k;
        int row = bz * 1024 + hw;
        int cd = cd0 + tx;
        float v = g_proj[(size_t)row * 768 + cd];
        tile[ty + 8 * k][tx] = (v - g_mu[row]) * g_rs[row] * gamma[cd] + beta[cd];
    }
    __syncthreads();
#pragma unroll
    for (int k = 0; k < 4; k++) {
        int cd = cd0 + ty + 8 * k;
        int hw = hw0 + tx;
        size_t oi = ((size_t)bz * 768 + cd) * 1024 + hw;
        g_y[oi] = tile[tx][ty + 8 * k] + x[oi];
    }
}

__global__ __launch_bounds__(1024) void dwconv(const float* __restrict__ dw_w,
                                               const float* __restrict__ dw_b) {
    __shared__ float tile[3][34][34];
    __shared__ float wsh[27];
    int bcd = blockIdx.x;
    int d  = bcd & 7;
    int bc = bcd >> 3;
    int c  = bc % Cc;
    int tid = threadIdx.x;

    if (tid < 27) wsh[tid] = dw_w[c * 27 + tid];

    for (int idx = tid; idx < 3 * 34 * 34; idx += 1024) {
        int pl = idx / 1156;
        int r  = (idx - pl * 1156) / 34;
        int cc = idx - pl * 1156 - r * 34;
        int dd = d - 1 + pl, hh = r - 1, ww = cc - 1;
        float val = 0.f;
        if (dd >= 0 && dd < Dd && hh >= 0 && hh < Hh && ww >= 0 && ww < Ww)
            val = g_y[(bc * Dd + dd) * HW + hh * Ww + ww];
        tile[pl][r][cc] = val;
    }
    __syncthreads();

    int h = tid >> 5, w = tid & 31;
    float s = 0.f;
#pragma unroll
    for (int pl = 0; pl < 3; pl++)
#pragma unroll
        for (int i = 0; i < 3; i++)
#pragma unroll
            for (int j = 0; j < 3; j++)
                s += tile[pl][h + i][w + j] * wsh[pl * 9 + i * 3 + j];
    g_z[bcd * HW + tid] = s + dw_b[c];
}

__global__ __launch_bounds__(128) void pwconv(const float* __restrict__ pw_w,
                                              const float* __restrict__ pw_b,
                                              float* __restrict__ out) {
    __shared__ float wsh[Cc * Cc];
    int b = blockIdx.y;
    int pos = blockIdx.x * 128 + threadIdx.x;
    constexpr int SP = Dd * HW;

    for (int i = threadIdx.x; i < Cc * Cc; i += 128) wsh[i] = pw_w[i];
    __syncthreads();

    float acc[Cc];
#pragma unroll
    for (int co = 0; co < Cc; co++) acc[co] = 0.f;

    const float* zb = g_z + b * Cc * SP + pos;
    for (int ci = 0; ci < Cc; ci++) {
        float zv = zb[ci * SP];
#pragma unroll
        for (int co = 0; co < Cc; co++) acc[co] += zv * wsh[co * Cc + ci];
    }

    const float* yb = g_y + b * Cc * SP + pos;
    float* ob = out + b * Cc * SP + pos;
#pragma unroll
    for (int co = 0; co < Cc; co++)
        ob[co * SP] = yb[co * SP] + acc[co] + pw_b[co];
}

// ---------------------------------------------------------------------------
// Launch
// ---------------------------------------------------------------------------
extern "C" void kernel_launch(void* const* d_in, const int* in_sizes, int n_in,
                              void* d_out, int out_size) {
    const float* x      = (const float*)d_in[0];
    const float* pos    = (const float*)d_in[1];
    const float* qkv_w  = (const float*)d_in[2];
    const float* proj_w = (const float*)d_in[3];
    const float* proj_b = (const float*)d_in[4];
    const float* temp   = (const float*)d_in[5];
    const float* ln_g   = (const float*)d_in[6];
    const float* ln_b   = (const float*)d_in[7];
    const float* dw_w   = (const float*)d_in[8];
    const float* dw_b   = (const float*)d_in[9];
    const float* pw_w   = (const float*)d_in[10];
    const float* pw_b   = (const float*)d_in[11];
    float* out = (float*)d_out;

    constexpr int SMEM256 = 3 * 12288 * 4;           // 144 KB
    constexpr int FSMEM   = FS_TOT * 4;              // 113 KB
    cudaFuncSetAttribute(tc_gemm<0>, cudaFuncAttributeMaxDynamicSharedMemorySize, SMEM256);
    cudaFuncSetAttribute(tc_gemm<3>, cudaFuncAttributeMaxDynamicSharedMemorySize, SMEM256);
    cudaFuncSetAttribute(flash_attn, cudaFuncAttributeMaxDynamicSharedMemorySize, FSMEM);

    permute_t<<<dim3(24, 32, 8), dim3(32, 8)>>>(x, pos);
    cvt_weights<<<(3 * DIM * DIM + 255) / 256, 256>>>(qkv_w, proj_w);
    tc_gemm<0><<<dim3(9, 64, 1), 512, SMEM256>>>(nullptr);
    l2_part<<<dim3(8, 32, 2), 192>>>();
    l2_inv<<<64, 192>>>();
    l2_scale<<<dim3(384, 32, 2), 256>>>();
    flash_attn<<<dim3(16, 32), 256, FSMEM>>>(temp);
    tc_gemm<3><<<dim3(3, 64, 1), 512, SMEM256>>>(proj_b);
    ln_combine<<<SEQROWS / 256, 256>>>();
    ln_apply<<<dim3(24, 32, 8), dim3(32, 8)>>>(x, ln_g, ln_b);
    dwconv<<<Bn * Cc * Dd, 1024>>>(dw_w, dw_b);
    pwconv<<<dim3(64, Bn, 1), 128>>>(pw_w, pw_b, out);
}

// round 12
// speedup vs baseline: 1.8116x; 1.0510x over previous
#include <cuda_runtime.h>
#include <cuda_fp16.h>
#include <math.h>
#include <stdint.h>

// ---------------------------------------------------------------------------
// Problem constants
// ---------------------------------------------------------------------------
constexpr int Bn = 8, Cc = 96, Dd = 8, Hh = 32, Ww = 32;
constexpr int HW = Hh * Ww;          // 1024
constexpr int DIM = Cc * Dd;         // 768
constexpr int NH = 4;
constexpr int DHd = DIM / NH;        // 192
constexpr int SEQROWS = Bn * HW;     // 8192
constexpr int BH = Bn * NH;          // 32

// ---------------------------------------------------------------------------
// Scratch (device globals). GEMM operands in fp16.
// ---------------------------------------------------------------------------
__device__ __align__(16) __half g_t[SEQROWS * DIM];
__device__ __align__(16) __half g_wq[3 * DIM * DIM];
__device__ __align__(16) __half g_wp[DIM * DIM];
__device__ __align__(16) __half g_q[BH * HW * DHd];
__device__ __align__(16) __half g_k[BH * HW * DHd];
__device__ __align__(16) __half g_vt[BH * DHd * HW];    // V^T: [z][dh][seq]
__device__ __align__(16) __half g_om[SEQROWS * DIM];
__device__ float g_proj[SEQROWS * DIM];
__device__ float g_y[Bn * Cc * Dd * HW];
__device__ float g_z[Bn * Cc * Dd * HW];
__device__ float g_part[2 * BH * 8 * DHd];
__device__ float g_inv[BH * DHd];                       // combined ivq*ivk
__device__ float g_psum[SEQROWS * 3];
__device__ float g_psq[SEQROWS * 3];
__device__ float g_mu[SEQROWS];
__device__ float g_rs[SEQROWS];

// ---------------------------------------------------------------------------
// Helpers (baseline PTX only)
// ---------------------------------------------------------------------------
__device__ __forceinline__ void mma_f16(float* d, const uint32_t* a,
                                        const uint32_t* b) {
    asm volatile(
        "mma.sync.aligned.m16n8k16.row.col.f32.f16.f16.f32 "
        "{%0,%1,%2,%3}, {%4,%5,%6,%7}, {%8,%9}, {%0,%1,%2,%3};"
        : "+f"(d[0]), "+f"(d[1]), "+f"(d[2]), "+f"(d[3])
        : "r"(a[0]), "r"(a[1]), "r"(a[2]), "r"(a[3]), "r"(b[0]), "r"(b[1]));
}
__device__ __forceinline__ void ldsm4(uint32_t* d, uint32_t addr) {
    asm volatile("ldmatrix.sync.aligned.m8n8.x4.shared.b16 {%0,%1,%2,%3}, [%4];"
                 : "=r"(d[0]), "=r"(d[1]), "=r"(d[2]), "=r"(d[3]) : "r"(addr));
}
__device__ __forceinline__ void cp_async16(uint32_t dst, const void* src) {
    asm volatile("cp.async.cg.shared.global [%0], [%1], 16;"
                 :: "r"(dst), "l"(src) : "memory");
}
__device__ __forceinline__ void cp_commit() {
    asm volatile("cp.async.commit_group;" ::: "memory");
}
template <int N>
__device__ __forceinline__ void cp_wait() {
    asm volatile("cp.async.wait_group %0;" :: "n"(N) : "memory");
}
__device__ __forceinline__ uint32_t pack_h2(float x, float y) {
    __half2 h = __floats2half2_rn(x, y);
    return *reinterpret_cast<uint32_t*>(&h);
}

// ---------------------------------------------------------------------------
// fp16 GEMM (ldmatrix fragments): C[M,N] = A[M,K] * B[N,K]^T, K=768.
// Block 128x256x64h, 512 threads, warp tile 32x64, 3-stage cp.async.
// MODE 0: QKV -> scatter q/k/vt.  MODE 3: PROJ -> g_proj (+bias, LN partials)
// ---------------------------------------------------------------------------
template <int MODE>
__global__ __launch_bounds__(512, 1) void tc_gemm(const float* __restrict__ bias) {
    constexpr int BK  = 64;
    constexpr int KK  = 768;
    constexpr int LD  = 768;
    constexpr int T   = KK / BK;             // 12
    constexpr int AW  = 128 * 32;
    constexpr int BWD = 256 * 32;
    constexpr int STG = AW + BWD;            // 12288 words
    constexpr int WN  = 64;
    constexpr int NT  = 8;

    extern __shared__ uint32_t smw[];
    const uint32_t smBase = (uint32_t)__cvta_generic_to_shared(smw);

    const int tid  = threadIdx.x;
    const int lane = tid & 31;
    const int w    = tid >> 5;
    const int wm   = w & 3;
    const int wn   = w >> 2;
    const int q    = lane >> 2;
    const int lq   = lane & 3;
    const int m0   = blockIdx.y * 128;
    const int n0   = blockIdx.x * 256;

    const __half* gA = (MODE == 0) ? g_t  : g_om;
    const __half* gB = (MODE == 0) ? g_wq : g_wp;

    const __half* aRow = gA + (size_t)m0 * LD;
    const __half* bRow = gB + (size_t)n0 * LD;

    auto loadStage = [&](int it, int s) {
        const __half* aP = aRow + it * BK;
        const __half* bP = bRow + it * BK;
        uint32_t sA = smBase + (uint32_t)(s * STG) * 4u;
        uint32_t sB = sA + AW * 4u;
#pragma unroll
        for (int i = 0; i < 2; i++) {
            int idx = tid + 512 * i;
            int r = idx >> 3, c4 = idx & 7;
            uint32_t dst = sA + (uint32_t)(r * 32 + ((c4 * 4) ^ (4 * (r & 7)))) * 4u;
            cp_async16(dst, aP + (size_t)r * LD + c4 * 8);
        }
#pragma unroll
        for (int i = 0; i < 4; i++) {
            int idx = tid + 512 * i;
            int r = idx >> 3, c4 = idx & 7;
            uint32_t dst = sB + (uint32_t)(r * 32 + ((c4 * 4) ^ (4 * (r & 7)))) * 4u;
            cp_async16(dst, bP + (size_t)r * LD + c4 * 8);
        }
    };

    float acc[2][NT][4];
#pragma unroll
    for (int mt = 0; mt < 2; mt++)
#pragma unroll
        for (int nt = 0; nt < NT; nt++)
#pragma unroll
            for (int k = 0; k < 4; k++) acc[mt][nt][k] = 0.f;

#pragma unroll
    for (int s = 0; s < 3; s++) { loadStage(s, s); cp_commit(); }

    // ldmatrix per-lane constants
    const int lr8 = lane & 7;
    const int swr = 4 * lr8;
    const int aRowL = wm * 32 + lr8 + ((lane >> 3) & 1) * 8;   // + mt*16
    const int kqA   = lane >> 4;                               // 0/1
    const int bRowL = wn * WN + (lane >> 4) * 8 + lr8;         // + p*16
    const int kqB   = (lane >> 3) & 1;

    for (int it = 0; it < T; ++it) {
        cp_wait<2>();
        __syncthreads();

        const int st = it % 3;
        const uint32_t aAddr = smBase + (uint32_t)(st * STG) * 4u;
        const uint32_t bAddr = aAddr + AW * 4u;
#pragma unroll
        for (int ks = 0; ks < 4; ks++) {
            const int wA = ((ks * 2 + kqA) * 4) ^ swr;
            const int wB = ((ks * 2 + kqB) * 4) ^ swr;
            uint32_t a[2][4];
#pragma unroll
            for (int mt = 0; mt < 2; mt++)
                ldsm4(a[mt], aAddr + (uint32_t)((aRowL + mt * 16) * 32 + wA) * 4u);
            uint32_t b[NT][2];
#pragma unroll
            for (int p = 0; p < NT / 2; p++) {
                uint32_t tmp[4];
                ldsm4(tmp, bAddr + (uint32_t)((bRowL + p * 16) * 32 + wB) * 4u);
                b[2 * p][0] = tmp[0]; b[2 * p][1] = tmp[1];
                b[2 * p + 1][0] = tmp[2]; b[2 * p + 1][1] = tmp[3];
            }
#pragma unroll
            for (int mt = 0; mt < 2; mt++)
#pragma unroll
                for (int nt = 0; nt < NT; nt++)
                    mma_f16(acc[mt][nt], a[mt], b[nt]);
        }
        __syncthreads();
        if (it + 3 < T) loadStage(it + 3, st);
        cp_commit();
    }

    // ---------------- epilogue ----------------
    if constexpr (MODE == 3) {
        float sums[2][2] = {{0.f, 0.f}, {0.f, 0.f}};
        float sqs [2][2] = {{0.f, 0.f}, {0.f, 0.f}};
#pragma unroll
        for (int mt = 0; mt < 2; mt++)
#pragma unroll
            for (int nt = 0; nt < NT; nt++) {
                int r = m0 + wm * 32 + mt * 16 + q;
                int c = n0 + wn * WN + nt * 8 + lq * 2;
                float2 bb = *reinterpret_cast<const float2*>(bias + c);
                float2 v0 = {acc[mt][nt][0] + bb.x, acc[mt][nt][1] + bb.y};
                float2 v1 = {acc[mt][nt][2] + bb.x, acc[mt][nt][3] + bb.y};
                *reinterpret_cast<float2*>(g_proj + (size_t)r * DIM + c) = v0;
                *reinterpret_cast<float2*>(g_proj + (size_t)(r + 8) * DIM + c) = v1;
                sums[mt][0] += v0.x + v0.y;
                sqs [mt][0] += v0.x * v0.x + v0.y * v0.y;
                sums[mt][1] += v1.x + v1.y;
                sqs [mt][1] += v1.x * v1.x + v1.y * v1.y;
            }
#pragma unroll
        for (int mt = 0; mt < 2; mt++)
#pragma unroll
            for (int h = 0; h < 2; h++) {
                sums[mt][h] += __shfl_xor_sync(0xFFFFFFFF, sums[mt][h], 1);
                sums[mt][h] += __shfl_xor_sync(0xFFFFFFFF, sums[mt][h], 2);
                sqs[mt][h]  += __shfl_xor_sync(0xFFFFFFFF, sqs[mt][h], 1);
                sqs[mt][h]  += __shfl_xor_sync(0xFFFFFFFF, sqs[mt][h], 2);
            }
        float* sSum = reinterpret_cast<float*>(smw);          // [4][128]
        float* sSq  = sSum + 512;
        __syncthreads();
        if (lq == 0) {
#pragma unroll
            for (int mt = 0; mt < 2; mt++)
#pragma unroll
                for (int h = 0; h < 2; h++) {
                    int r = wm * 32 + mt * 16 + q + h * 8;
                    sSum[wn * 128 + r] = sums[mt][h];
                    sSq [wn * 128 + r] = sqs[mt][h];
                }
        }
        __syncthreads();
        if (tid < 128) {
            float s = sSum[tid] + sSum[128 + tid] + sSum[256 + tid] + sSum[384 + tid];
            float qq = sSq[tid] + sSq[128 + tid] + sSq[256 + tid] + sSq[384 + tid];
            g_psum[(size_t)(m0 + tid) * 3 + blockIdx.x] = s;
            g_psq [(size_t)(m0 + tid) * 3 + blockIdx.x] = qq;
        }
    } else {
        const int s0 = n0 / 768;
#pragma unroll
        for (int mt = 0; mt < 2; mt++)
#pragma unroll
            for (int nt = 0; nt < NT; nt++) {
                int r = m0 + wm * 32 + mt * 16 + q;
                int c = n0 + wn * WN + nt * 8 + lq * 2;
                int nl = c - s0 * 768;
                int h = nl / 192, dh = nl % 192;
                int b0i = r >> 10, seq0 = r & 1023;
                int b1i = (r + 8) >> 10, seq1 = (r + 8) & 1023;
                if (s0 == 2) {
                    int z0 = b0i * 4 + h, z1 = b1i * 4 + h;
                    g_vt[((size_t)z0 * 192 + dh) * 1024 + seq0]     = __float2half_rn(acc[mt][nt][0]);
                    g_vt[((size_t)z0 * 192 + dh + 1) * 1024 + seq0] = __float2half_rn(acc[mt][nt][1]);
                    g_vt[((size_t)z1 * 192 + dh) * 1024 + seq1]     = __float2half_rn(acc[mt][nt][2]);
                    g_vt[((size_t)z1 * 192 + dh + 1) * 1024 + seq1] = __float2half_rn(acc[mt][nt][3]);
                } else {
                    __half* dst = (s0 == 0) ? g_q : g_k;
                    uint32_t p0 = pack_h2(acc[mt][nt][0], acc[mt][nt][1]);
                    uint32_t p1 = pack_h2(acc[mt][nt][2], acc[mt][nt][3]);
                    *reinterpret_cast<uint32_t*>(
                        dst + ((size_t)(b0i * 4 + h) * 1024 + seq0) * 192 + dh) = p0;
                    *reinterpret_cast<uint32_t*>(
                        dst + ((size_t)(b1i * 4 + h) * 1024 + seq1) * 192 + dh) = p1;
                }
            }
    }
}

// combine LN partials -> mu, rstd
__global__ void ln_combine() {
    int row = blockIdx.x * 256 + threadIdx.x;
    if (row >= SEQROWS) return;
    float s  = g_psum[(size_t)row * 3] + g_psum[(size_t)row * 3 + 1] + g_psum[(size_t)row * 3 + 2];
    float qq = g_psq [(size_t)row * 3] + g_psq [(size_t)row * 3 + 1] + g_psq [(size_t)row * 3 + 2];
    float mu = s * (1.f / DIM);
    float var = fmaxf(qq * (1.f / DIM) - mu * mu, 0.f);
    g_mu[row] = mu;
    g_rs[row] = rsqrtf(var + 1e-5f);
}

// ---------------------------------------------------------------------------
// Flash attention (fp16, ldmatrix fragments, 2 CTAs/SM)
// ---------------------------------------------------------------------------
constexpr int FS_Q   = 0;
constexpr int FS_KV  = 6144;
constexpr int FS_P   = 24576;
constexpr int FS_RED = 28672;
constexpr int FS_TOT = 28928;

__global__ __launch_bounds__(256, 2) void flash_attn(const float* __restrict__ temp) {
    extern __shared__ uint32_t smw[];
    const uint32_t smBase = (uint32_t)__cvta_generic_to_shared(smw);

    const int tid  = threadIdx.x;
    const int lane = tid & 31;
    const int w    = tid >> 5;       // 0..7
    const int wm   = w & 1;
    const int wn   = w >> 1;         // 0..3
    const int q    = lane >> 2;
    const int lq   = lane & 3;
    const int z    = blockIdx.y;
    const int m0   = blockIdx.x * 64;

    const __half* Qz = g_q  + (size_t)z * HW * DHd;
    const __half* Kz = g_k  + (size_t)z * HW * DHd;
    const __half* Vz = g_vt + (size_t)z * DHd * HW;
    const float ts = temp[z & 3];

    // Q load: 3 panels [64][64 halves]
#pragma unroll
    for (int i = 0; i < 6; i++) {
        int idx = tid + 256 * i;
        int c4 = idx & 7, r = (idx >> 3) & 63, p = idx >> 9;
        uint32_t dst = smBase + (uint32_t)(FS_Q + p * 2048 + r * 32 +
                                           ((c4 * 4) ^ (4 * (r & 7)))) * 4u;
        cp_async16(dst, Qz + (size_t)(m0 + r) * 192 + p * 64 + c4 * 8);
    }
    cp_commit();

    auto issuePanel = [&](int g) {
        int t = g / 5, i = g % 5, buf = g % 3;
        uint32_t base = smBase + (uint32_t)(FS_KV + buf * 6144) * 4u;
        if (i < 3) {               // K panel: 128 rows x 64 halves
#pragma unroll
            for (int j = 0; j < 4; j++) {
                int idx = tid + 256 * j;
                int c4 = idx & 7, r = idx >> 3;
                cp_async16(base + (uint32_t)(r * 32 + ((c4 * 4) ^ (4 * (r & 7)))) * 4u,
                           Kz + (size_t)(t * 128 + r) * 192 + i * 64 + c4 * 8);
            }
        } else {                   // V panel: 192 dh-rows x 64 seq halves
            int pv = i - 3;
#pragma unroll
            for (int j = 0; j < 6; j++) {
                int idx = tid + 256 * j;
                int c4 = idx & 7, r = idx >> 3;
                cp_async16(base + (uint32_t)(r * 32 + ((c4 * 4) ^ (4 * (r & 7)))) * 4u,
                           Vz + (size_t)r * 1024 + t * 128 + pv * 64 + c4 * 8);
            }
        }
    };
    issuePanel(0); cp_commit();
    issuePanel(1); cp_commit();

    constexpr float L2E = 1.4426950408889634f;
    float m_run[2][2] = {{-1e30f, -1e30f}, {-1e30f, -1e30f}};
    float l_run[2][2] = {{0.f, 0.f}, {0.f, 0.f}};
    float acc_o[2][6][4];
#pragma unroll
    for (int mt = 0; mt < 2; mt++)
#pragma unroll
        for (int nt = 0; nt < 6; nt++)
#pragma unroll
            for (int k = 0; k < 4; k++) acc_o[mt][nt][k] = 0.f;

    const int sw = 4 * q;
    float* sRed = reinterpret_cast<float*>(smw + FS_RED);

    // ldmatrix per-lane constants
    const int lr8 = lane & 7;
    const int swr = 4 * lr8;
    const int aRowL = wm * 32 + lr8 + ((lane >> 3) & 1) * 8;   // + mt*16
    const int kqA   = lane >> 4;
    const int bRowL1 = wn * 32 + (lane >> 4) * 8 + lr8;        // phase1 + p*16
    const int bRowL2 = wn * 48 + (lane >> 4) * 8 + lr8;        // phase2 + p*16
    const int kqB   = (lane >> 3) & 1;

    for (int t = 0; t < 8; t++) {
        float acc_s[2][4][4];
#pragma unroll
        for (int mt = 0; mt < 2; mt++)
#pragma unroll
            for (int nt = 0; nt < 4; nt++)
#pragma unroll
                for (int k = 0; k < 4; k++) acc_s[mt][nt][k] = 0.f;

        // ---------- phase 1: S = Q K^T ----------
        for (int pp = 0; pp < 3; pp++) {
            int g = t * 5 + pp;
            cp_wait<1>();
            __syncthreads();
            if (g + 2 < 40) issuePanel(g + 2);
            cp_commit();
            const uint32_t aAddr = smBase + (uint32_t)(FS_Q + pp * 2048) * 4u;
            const uint32_t bAddr = smBase + (uint32_t)(FS_KV + (g % 3) * 6144) * 4u;
#pragma unroll
            for (int ks = 0; ks < 4; ks++) {
                const int wA = ((ks * 2 + kqA) * 4) ^ swr;
                const int wB = ((ks * 2 + kqB) * 4) ^ swr;
                uint32_t a[2][4];
#pragma unroll
                for (int mt = 0; mt < 2; mt++)
                    ldsm4(a[mt], aAddr + (uint32_t)((aRowL + mt * 16) * 32 + wA) * 4u);
                uint32_t b[4][2];
#pragma unroll
                for (int p = 0; p < 2; p++) {
                    uint32_t tmp[4];
                    ldsm4(tmp, bAddr + (uint32_t)((bRowL1 + p * 16) * 32 + wB) * 4u);
                    b[2 * p][0] = tmp[0]; b[2 * p][1] = tmp[1];
                    b[2 * p + 1][0] = tmp[2]; b[2 * p + 1][1] = tmp[3];
                }
#pragma unroll
                for (int mt = 0; mt < 2; mt++)
#pragma unroll
                    for (int nt = 0; nt < 4; nt++)
                        mma_f16(acc_s[mt][nt], a[mt], b[nt]);
            }
        }

        // ---------- online softmax ----------
        float tmax[2][2], corr[2][2], rsum[2][2];
        {
            float rmax[2][2] = {{-1e30f, -1e30f}, {-1e30f, -1e30f}};
#pragma unroll
            for (int mt = 0; mt < 2; mt++)
#pragma unroll
                for (int nt = 0; nt < 4; nt++)
#pragma unroll
                    for (int j = 0; j < 4; j++) {
                        float v = acc_s[mt][nt][j] * ts;
                        acc_s[mt][nt][j] = v;
                        rmax[mt][j >> 1] = fmaxf(rmax[mt][j >> 1], v);
                    }
#pragma unroll
            for (int mt = 0; mt < 2; mt++)
#pragma unroll
                for (int h2 = 0; h2 < 2; h2++) {
                    float v = rmax[mt][h2];
                    v = fmaxf(v, __shfl_xor_sync(0xFFFFFFFF, v, 1));
                    v = fmaxf(v, __shfl_xor_sync(0xFFFFFFFF, v, 2));
                    rmax[mt][h2] = v;
                }
            if (lq == 0) {
#pragma unroll
                for (int mt = 0; mt < 2; mt++)
#pragma unroll
                    for (int h2 = 0; h2 < 2; h2++)
                        sRed[wn * 64 + wm * 32 + mt * 16 + q + h2 * 8] = rmax[mt][h2];
            }
            __syncthreads();
#pragma unroll
            for (int mt = 0; mt < 2; mt++)
#pragma unroll
                for (int h2 = 0; h2 < 2; h2++) {
                    int rr = wm * 32 + mt * 16 + q + h2 * 8;
                    tmax[mt][h2] = fmaxf(fmaxf(sRed[rr], sRed[64 + rr]),
                                         fmaxf(sRed[128 + rr], sRed[192 + rr]));
                }
        }
#pragma unroll
        for (int mt = 0; mt < 2; mt++)
#pragma unroll
            for (int h2 = 0; h2 < 2; h2++) {
                float nm = fmaxf(m_run[mt][h2], tmax[mt][h2]);
                corr[mt][h2] = exp2f((m_run[mt][h2] - nm) * L2E);
                m_run[mt][h2] = nm;
                rsum[mt][h2] = 0.f;
            }
#pragma unroll
        for (int mt = 0; mt < 2; mt++)
#pragma unroll
            for (int nt = 0; nt < 4; nt++)
#pragma unroll
                for (int j = 0; j < 4; j++) {
                    float pv = exp2f((acc_s[mt][nt][j] - m_run[mt][j >> 1]) * L2E);
                    acc_s[mt][nt][j] = pv;
                    rsum[mt][j >> 1] += pv;
                }
#pragma unroll
        for (int mt = 0; mt < 2; mt++)
#pragma unroll
            for (int h2 = 0; h2 < 2; h2++) {
                float v = rsum[mt][h2];
                v += __shfl_xor_sync(0xFFFFFFFF, v, 1);
                v += __shfl_xor_sync(0xFFFFFFFF, v, 2);
                rsum[mt][h2] = v;
            }
        __syncthreads();
        if (lq == 0) {
#pragma unroll
            for (int mt = 0; mt < 2; mt++)
#pragma unroll
                for (int h2 = 0; h2 < 2; h2++)
                    sRed[wn * 64 + wm * 32 + mt * 16 + q + h2 * 8] = rsum[mt][h2];
        }
        __syncthreads();
#pragma unroll
        for (int mt = 0; mt < 2; mt++)
#pragma unroll
            for (int h2 = 0; h2 < 2; h2++) {
                int rr = wm * 32 + mt * 16 + q + h2 * 8;
                float tsum = sRed[rr] + sRed[64 + rr] + sRed[128 + rr] + sRed[192 + rr];
                l_run[mt][h2] = l_run[mt][h2] * corr[mt][h2] + tsum;
            }
#pragma unroll
        for (int mt = 0; mt < 2; mt++)
#pragma unroll
            for (int nt = 0; nt < 6; nt++) {
                acc_o[mt][nt][0] *= corr[mt][0];
                acc_o[mt][nt][1] *= corr[mt][0];
                acc_o[mt][nt][2] *= corr[mt][1];
                acc_o[mt][nt][3] *= corr[mt][1];
            }
        // store P (fp16 half2 pairs)
#pragma unroll
        for (int mt = 0; mt < 2; mt++)
#pragma unroll
            for (int nt = 0; nt < 4; nt++) {
                int r0 = wm * 32 + mt * 16 + q;
                int wbase = (wn & 1) * 16 + nt * 4 + lq;
                uint32_t* pp2 = smw + FS_P + (wn >> 1) * 2048;
                pp2[r0 * 32 + (wbase ^ sw)]       = pack_h2(acc_s[mt][nt][0], acc_s[mt][nt][1]);
                pp2[(r0 + 8) * 32 + (wbase ^ sw)] = pack_h2(acc_s[mt][nt][2], acc_s[mt][nt][3]);
            }
        __syncthreads();

        // ---------- phase 2: O += P V ----------
        for (int pv = 0; pv < 2; pv++) {
            int g = t * 5 + 3 + pv;
            cp_wait<1>();
            __syncthreads();
            if (g + 2 < 40) issuePanel(g + 2);
            cp_commit();
            const uint32_t aAddr = smBase + (uint32_t)(FS_P + pv * 2048) * 4u;
            const uint32_t bAddr = smBase + (uint32_t)(FS_KV + (g % 3) * 6144) * 4u;
#pragma unroll
            for (int ks = 0; ks < 4; ks++) {
                const int wA = ((ks * 2 + kqA) * 4) ^ swr;
                const int wB = ((ks * 2 + kqB) * 4) ^ swr;
                uint32_t a[2][4];
#pragma unroll
                for (int mt = 0; mt < 2; mt++)
                    ldsm4(a[mt], aAddr + (uint32_t)((aRowL + mt * 16) * 32 + wA) * 4u);
                uint32_t b[6][2];
#pragma unroll
                for (int p = 0; p < 3; p++) {
                    uint32_t tmp[4];
                    ldsm4(tmp, bAddr + (uint32_t)((bRowL2 + p * 16) * 32 + wB) * 4u);
                    b[2 * p][0] = tmp[0]; b[2 * p][1] = tmp[1];
                    b[2 * p + 1][0] = tmp[2]; b[2 * p + 1][1] = tmp[3];
                }
#pragma unroll
                for (int mt = 0; mt < 2; mt++)
#pragma unroll
                    for (int nt = 0; nt < 6; nt++)
                        mma_f16(acc_o[mt][nt], a[mt], b[nt]);
            }
        }
    }

    // ---------- epilogue: O /= l, merged-head fp16 store ----------
    int b = z >> 2, h = z & 3;
    float inv[2][2];
#pragma unroll
    for (int mt = 0; mt < 2; mt++)
#pragma unroll
        for (int h2 = 0; h2 < 2; h2++) inv[mt][h2] = 1.f / l_run[mt][h2];
#pragma unroll
    for (int mt = 0; mt < 2; mt++)
#pragma unroll
        for (int nt = 0; nt < 6; nt++) {
            int rl = wm * 32 + mt * 16 + q;
            int col = wn * 48 + nt * 8 + 2 * lq;
            uint32_t p0 = pack_h2(acc_o[mt][nt][0] * inv[mt][0],
                                  acc_o[mt][nt][1] * inv[mt][0]);
            uint32_t p1 = pack_h2(acc_o[mt][nt][2] * inv[mt][1],
                                  acc_o[mt][nt][3] * inv[mt][1]);
            *reinterpret_cast<uint32_t*>(
                g_om + ((size_t)(b * HW + m0 + rl)) * DIM + h * DHd + col) = p0;
            *reinterpret_cast<uint32_t*>(
                g_om + ((size_t)(b * HW + m0 + rl + 8)) * DIM + h * DHd + col) = p1;
        }
}

// ---------------------------------------------------------------------------
// Producers / elementwise
// ---------------------------------------------------------------------------
__global__ void permute_t(const float* __restrict__ x,
                          const float* __restrict__ pos) {
    __shared__ float tile[32][33];
    int bz = blockIdx.z, hw0 = blockIdx.y * 32, cd0 = blockIdx.x * 32;
    int tx = threadIdx.x, ty = threadIdx.y;
#pragma unroll
    for (int k = 0; k < 4; k++) {
        int cd = cd0 + ty + 8 * k;
        tile[ty + 8 * k][tx] = x[((size_t)bz * 768 + cd) * 1024 + hw0 + tx];
    }
    __syncthreads();
#pragma unroll
    for (int k = 0; k < 4; k++) {
        int hw = hw0 + ty + 8 * k;
        int cd = cd0 + tx;
        g_t[((size_t)bz * 1024 + hw) * 768 + cd] =
            __float2half_rn(tile[tx][ty + 8 * k] + pos[(size_t)hw * 768 + cd]);
    }
}

__global__ void cvt_wq(const float* __restrict__ qkv_w) {
    int i = blockIdx.x * 256 + threadIdx.x;
    if (i < 3 * DIM * DIM) g_wq[i] = __float2half_rn(qkv_w[i]);
}
__global__ void cvt_wp(const float* __restrict__ proj_w) {
    int i = blockIdx.x * 256 + threadIdx.x;
    if (i < DIM * DIM) g_wp[i] = __float2half_rn(proj_w[i]);
}

// l2norm over seq axis: partials -> combined inv (ivq*ivk) -> scale q only
__global__ void l2_part() {
    int chunk = blockIdx.x, z = blockIdx.y, which = blockIdx.z;
    const __half* p = (which ? g_k : g_q) + ((size_t)z * HW + chunk * 128) * DHd;
    int col = threadIdx.x;
    float ss = 0.f;
#pragma unroll 4
    for (int r = 0; r < 128; r++) {
        float v = __half2float(p[(size_t)r * DHd + col]);
        ss += v * v;
    }
    g_part[(((size_t)which * BH + z) * 8 + chunk) * DHd + col] = ss;
}

__global__ void l2_inv() {
    int z = blockIdx.x;
    int col = threadIdx.x;
    float sq = 0.f, sk = 0.f;
#pragma unroll
    for (int c = 0; c < 8; c++) {
        sq += g_part[((size_t)z * 8 + c) * DHd + col];
        sk += g_part[(((size_t)BH + z) * 8 + c) * DHd + col];
    }
    float ivq = 1.f / fmaxf(sqrtf(sq), 1e-12f);
    float ivk = 1.f / fmaxf(sqrtf(sk), 1e-12f);
    g_inv[(size_t)z * DHd + col] = ivq * ivk;
}

__global__ void l2_scale() {
    int z = blockIdx.y;
    int i = blockIdx.x * 256 + threadIdx.x;
    int seq = i / 96, c2 = i % 96;
    __half2* p = reinterpret_cast<__half2*>(g_q) + ((size_t)z * HW + seq) * 96 + c2;
    float2 v = __half22float2(*p);
    const float* ivp = g_inv + (size_t)z * DHd + c2 * 2;
    *p = __floats2half2_rn(v.x * ivp[0], v.y * ivp[1]);
}

__global__ void ln_apply(const float* __restrict__ x,
                         const float* __restrict__ gamma,
                         const float* __restrict__ beta) {
    __shared__ float tile[32][33];
    int bz = blockIdx.z, hw0 = blockIdx.y * 32, cd0 = blockIdx.x * 32;
    int tx = threadIdx.x, ty = threadIdx.y;
#pragma unroll
    for (int k = 0; k < 4; k++) {
        int hw = hw0 + ty + 8 * k;
        int row = bz * 1024 + hw;
        int cd = cd0 + tx;
        float v = g_proj[(size_t)row * 768 + cd];
        tile[ty + 8 * k][tx] = (v - g_mu[row]) * g_rs[row] * gamma[cd] + beta[cd];
    }
    __syncthreads();
#pragma unroll
    for (int k = 0; k < 4; k++) {
        int cd = cd0 + ty + 8 * k;
        int hw = hw0 + tx;
        size_t oi = ((size_t)bz * 768 + cd) * 1024 + hw;
        g_y[oi] = tile[tx][ty + 8 * k] + x[oi];
    }
}

__global__ __launch_bounds__(1024) void dwconv(const float* __restrict__ dw_w,
                                               const float* __restrict__ dw_b) {
    __shared__ float tile[3][34][34];
    __shared__ float wsh[27];
    int bcd = blockIdx.x;
    int d  = bcd & 7;
    int bc = bcd >> 3;
    int c  = bc % Cc;
    int tid = threadIdx.x;

    if (tid < 27) wsh[tid] = dw_w[c * 27 + tid];

    for (int idx = tid; idx < 3 * 34 * 34; idx += 1024) {
        int pl = idx / 1156;
        int r  = (idx - pl * 1156) / 34;
        int cc = idx - pl * 1156 - r * 34;
        int dd = d - 1 + pl, hh = r - 1, ww = cc - 1;
        float val = 0.f;
        if (dd >= 0 && dd < Dd && hh >= 0 && hh < Hh && ww >= 0 && ww < Ww)
            val = g_y[(bc * Dd + dd) * HW + hh * Ww + ww];
        tile[pl][r][cc] = val;
    }
    __syncthreads();

    int h = tid >> 5, w = tid & 31;
    float s = 0.f;
#pragma unroll
    for (int pl = 0; pl < 3; pl++)
#pragma unroll
        for (int i = 0; i < 3; i++)
#pragma unroll
            for (int j = 0; j < 3; j++)
                s += tile[pl][h + i][w + j] * wsh[pl * 9 + i * 3 + j];
    g_z[bcd * HW + tid] = s + dw_b[c];
}

__global__ __launch_bounds__(128) void pwconv(const float* __restrict__ pw_w,
                                              const float* __restrict__ pw_b,
                                              float* __restrict__ out) {
    __shared__ float wsh[Cc * Cc];
    int b = blockIdx.y;
    int pos = blockIdx.x * 128 + threadIdx.x;
    constexpr int SP = Dd * HW;

    for (int i = threadIdx.x; i < Cc * Cc; i += 128) wsh[i] = pw_w[i];
    __syncthreads();

    float acc[Cc];
#pragma unroll
    for (int co = 0; co < Cc; co++) acc[co] = 0.f;

    const float* zb = g_z + b * Cc * SP + pos;
    for (int ci = 0; ci < Cc; ci++) {
        float zv = zb[ci * SP];
#pragma unroll
        for (int co = 0; co < Cc; co++) acc[co] += zv * wsh[co * Cc + ci];
    }

    const float* yb = g_y + b * Cc * SP + pos;
    float* ob = out + b * Cc * SP + pos;
#pragma unroll
    for (int co = 0; co < Cc; co++)
        ob[co * SP] = yb[co * SP] + acc[co] + pw_b[co];
}

// ---------------------------------------------------------------------------
// Launch
// ---------------------------------------------------------------------------
extern "C" void kernel_launch(void* const* d_in, const int* in_sizes, int n_in,
                              void* d_out, int out_size) {
    const float* x      = (const float*)d_in[0];
    const float* pos    = (const float*)d_in[1];
    const float* qkv_w  = (const float*)d_in[2];
    const float* proj_w = (const float*)d_in[3];
    const float* proj_b = (const float*)d_in[4];
    const float* temp   = (const float*)d_in[5];
    const float* ln_g   = (const float*)d_in[6];
    const float* ln_b   = (const float*)d_in[7];
    const float* dw_w   = (const float*)d_in[8];
    const float* dw_b   = (const float*)d_in[9];
    const float* pw_w   = (const float*)d_in[10];
    const float* pw_b   = (const float*)d_in[11];
    float* out = (float*)d_out;

    constexpr int SMEM256 = 3 * 12288 * 4;           // 144 KB
    constexpr int FSMEM   = FS_TOT * 4;              // 113 KB
    cudaFuncSetAttribute(tc_gemm<0>, cudaFuncAttributeMaxDynamicSharedMemorySize, SMEM256);
    cudaFuncSetAttribute(tc_gemm<3>, cudaFuncAttributeMaxDynamicSharedMemorySize, SMEM256);
    cudaFuncSetAttribute(flash_attn, cudaFuncAttributeMaxDynamicSharedMemorySize, FSMEM);

    permute_t<<<dim3(24, 32, 8), dim3(32, 8)>>>(x, pos);
    cvt_wq<<<(3 * DIM * DIM + 255) / 256, 256>>>(qkv_w);
    cvt_wp<<<(DIM * DIM + 255) / 256, 256>>>(proj_w);
    tc_gemm<0><<<dim3(9, 64, 1), 512, SMEM256>>>(nullptr);
    l2_part<<<dim3(8, 32, 2), 192>>>();
    l2_inv<<<32, 192>>>();
    l2_scale<<<dim3(384, 32, 1), 256>>>();
    flash_attn<<<dim3(16, 32), 256, FSMEM>>>(temp);
    tc_gemm<3><<<dim3(3, 64, 1), 512, SMEM256>>>(proj_b);
    ln_combine<<<SEQROWS / 256, 256>>>();
    ln_apply<<<dim3(24, 32, 8), dim3(32, 8)>>>(x, ln_g, ln_b);
    dwconv<<<Bn * Cc * Dd, 1024>>>(dw_w, dw_b);
    pwconv<<<dim3(64, Bn, 1), 128>>>(pw_w, pw_b, out);
}

// round 13
// speedup vs baseline: 1.8269x; 1.0084x over previous
#include <cuda_runtime.h>
#include <cuda_fp16.h>
#include <math.h>
#include <stdint.h>

// ---------------------------------------------------------------------------
// Problem constants
// ---------------------------------------------------------------------------
constexpr int Bn = 8, Cc = 96, Dd = 8, Hh = 32, Ww = 32;
constexpr int HW = Hh * Ww;          // 1024
constexpr int DIM = Cc * Dd;         // 768
constexpr int NH = 4;
constexpr int DHd = DIM / NH;        // 192
constexpr int SEQROWS = Bn * HW;     // 8192
constexpr int BH = Bn * NH;          // 32

// ---------------------------------------------------------------------------
// Scratch (device globals). GEMM operands in fp16.
// ---------------------------------------------------------------------------
__device__ __align__(16) __half g_t[SEQROWS * DIM];
__device__ __align__(16) __half g_wq[3 * DIM * DIM];
__device__ __align__(16) __half g_wp[DIM * DIM];
__device__ __align__(16) __half g_q[BH * HW * DHd];
__device__ __align__(16) __half g_k[BH * HW * DHd];
__device__ __align__(16) __half g_vt[BH * DHd * HW];    // V^T: [z][dh][seq]
__device__ __align__(16) __half g_om[SEQROWS * DIM];
__device__ float g_proj[SEQROWS * DIM];
__device__ float g_y[Bn * Cc * Dd * HW];
__device__ float g_z[Bn * Cc * Dd * HW];
__device__ float g_part[2 * BH * 8 * DHd];
__device__ float g_inv[BH * DHd];                       // combined ivq*ivk
__device__ float g_psum[SEQROWS * 3];
__device__ float g_psq[SEQROWS * 3];
__device__ float g_mu[SEQROWS];
__device__ float g_rs[SEQROWS];

// ---------------------------------------------------------------------------
// Helpers (baseline PTX only)
// ---------------------------------------------------------------------------
__device__ __forceinline__ void mma_f16(float* d, const uint32_t* a,
                                        const uint32_t* b) {
    asm volatile(
        "mma.sync.aligned.m16n8k16.row.col.f32.f16.f16.f32 "
        "{%0,%1,%2,%3}, {%4,%5,%6,%7}, {%8,%9}, {%0,%1,%2,%3};"
        : "+f"(d[0]), "+f"(d[1]), "+f"(d[2]), "+f"(d[3])
        : "r"(a[0]), "r"(a[1]), "r"(a[2]), "r"(a[3]), "r"(b[0]), "r"(b[1]));
}
__device__ __forceinline__ void ldsm4(uint32_t* d, uint32_t addr) {
    asm volatile("ldmatrix.sync.aligned.m8n8.x4.shared.b16 {%0,%1,%2,%3}, [%4];"
                 : "=r"(d[0]), "=r"(d[1]), "=r"(d[2]), "=r"(d[3]) : "r"(addr));
}
__device__ __forceinline__ void cp_async16(uint32_t dst, const void* src) {
    asm volatile("cp.async.cg.shared.global [%0], [%1], 16;"
                 :: "r"(dst), "l"(src) : "memory");
}
__device__ __forceinline__ void cp_commit() {
    asm volatile("cp.async.commit_group;" ::: "memory");
}
template <int N>
__device__ __forceinline__ void cp_wait() {
    asm volatile("cp.async.wait_group %0;" :: "n"(N) : "memory");
}
__device__ __forceinline__ uint32_t pack_h2(float x, float y) {
    __half2 h = __floats2half2_rn(x, y);
    return *reinterpret_cast<uint32_t*>(&h);
}

// ---------------------------------------------------------------------------
// fp16 GEMM (ldmatrix fragments): C[M,N] = A[M,K] * B[N,K]^T, K=768.
// Block 128x256x64h, 512 threads, warp tile 32x64, 4-stage cp.async with a
// SINGLE barrier per iteration (loads for it+3 issue into slot (it+3)&3,
// disjoint from compute slot it&3; previous readers barrier-separated).
// MODE 0: QKV -> scatter q/k/vt.  MODE 3: PROJ -> g_proj (+bias, LN partials)
// ---------------------------------------------------------------------------
template <int MODE>
__global__ __launch_bounds__(512, 1) void tc_gemm(const float* __restrict__ bias) {
    constexpr int BK  = 64;
    constexpr int KK  = 768;
    constexpr int LD  = 768;
    constexpr int T   = KK / BK;             // 12
    constexpr int AW  = 128 * 32;
    constexpr int BWD = 256 * 32;
    constexpr int STG = AW + BWD;            // 12288 words (48 KB)
    constexpr int WN  = 64;
    constexpr int NT  = 8;

    extern __shared__ uint32_t smw[];
    const uint32_t smBase = (uint32_t)__cvta_generic_to_shared(smw);

    const int tid  = threadIdx.x;
    const int lane = tid & 31;
    const int w    = tid >> 5;
    const int wm   = w & 3;
    const int wn   = w >> 2;
    const int q    = lane >> 2;
    const int lq   = lane & 3;
    const int m0   = blockIdx.y * 128;
    const int n0   = blockIdx.x * 256;

    const __half* gA = (MODE == 0) ? g_t  : g_om;
    const __half* gB = (MODE == 0) ? g_wq : g_wp;

    const __half* aRow = gA + (size_t)m0 * LD;
    const __half* bRow = gB + (size_t)n0 * LD;

    auto loadStage = [&](int it, int s) {
        const __half* aP = aRow + it * BK;
        const __half* bP = bRow + it * BK;
        uint32_t sA = smBase + (uint32_t)(s * STG) * 4u;
        uint32_t sB = sA + AW * 4u;
#pragma unroll
        for (int i = 0; i < 2; i++) {
            int idx = tid + 512 * i;
            int r = idx >> 3, c4 = idx & 7;
            uint32_t dst = sA + (uint32_t)(r * 32 + ((c4 * 4) ^ (4 * (r & 7)))) * 4u;
            cp_async16(dst, aP + (size_t)r * LD + c4 * 8);
        }
#pragma unroll
        for (int i = 0; i < 4; i++) {
            int idx = tid + 512 * i;
            int r = idx >> 3, c4 = idx & 7;
            uint32_t dst = sB + (uint32_t)(r * 32 + ((c4 * 4) ^ (4 * (r & 7)))) * 4u;
            cp_async16(dst, bP + (size_t)r * LD + c4 * 8);
        }
    };

    float acc[2][NT][4];
#pragma unroll
    for (int mt = 0; mt < 2; mt++)
#pragma unroll
        for (int nt = 0; nt < NT; nt++)
#pragma unroll
            for (int k = 0; k < 4; k++) acc[mt][nt][k] = 0.f;

#pragma unroll
    for (int s = 0; s < 3; s++) { loadStage(s, s); cp_commit(); }

    // ldmatrix per-lane constants
    const int lr8 = lane & 7;
    const int swr = 4 * lr8;
    const int aRowL = wm * 32 + lr8 + ((lane >> 3) & 1) * 8;   // + mt*16
    const int kqA   = lane >> 4;                               // 0/1
    const int bRowL = wn * WN + (lane >> 4) * 8 + lr8;         // + p*16
    const int kqB   = (lane >> 3) & 1;

    for (int it = 0; it < T; ++it) {
        cp_wait<2>();
        __syncthreads();
        if (it + 3 < T) loadStage(it + 3, (it + 3) & 3);
        cp_commit();

        const uint32_t aAddr = smBase + (uint32_t)((it & 3) * STG) * 4u;
        const uint32_t bAddr = aAddr + AW * 4u;
#pragma unroll
        for (int ks = 0; ks < 4; ks++) {
            const int wA = ((ks * 2 + kqA) * 4) ^ swr;
            const int wB = ((ks * 2 + kqB) * 4) ^ swr;
            uint32_t a[2][4];
#pragma unroll
            for (int mt = 0; mt < 2; mt++)
                ldsm4(a[mt], aAddr + (uint32_t)((aRowL + mt * 16) * 32 + wA) * 4u);
            uint32_t b[NT][2];
#pragma unroll
            for (int p = 0; p < NT / 2; p++) {
                uint32_t tmp[4];
                ldsm4(tmp, bAddr + (uint32_t)((bRowL + p * 16) * 32 + wB) * 4u);
                b[2 * p][0] = tmp[0]; b[2 * p][1] = tmp[1];
                b[2 * p + 1][0] = tmp[2]; b[2 * p + 1][1] = tmp[3];
            }
#pragma unroll
            for (int mt = 0; mt < 2; mt++)
#pragma unroll
                for (int nt = 0; nt < NT; nt++)
                    mma_f16(acc[mt][nt], a[mt], b[nt]);
        }
    }

    // ---------------- epilogue ----------------
    if constexpr (MODE == 3) {
        float sums[2][2] = {{0.f, 0.f}, {0.f, 0.f}};
        float sqs [2][2] = {{0.f, 0.f}, {0.f, 0.f}};
#pragma unroll
        for (int mt = 0; mt < 2; mt++)
#pragma unroll
            for (int nt = 0; nt < NT; nt++) {
                int r = m0 + wm * 32 + mt * 16 + q;
                int c = n0 + wn * WN + nt * 8 + lq * 2;
                float2 bb = *reinterpret_cast<const float2*>(bias + c);
                float2 v0 = {acc[mt][nt][0] + bb.x, acc[mt][nt][1] + bb.y};
                float2 v1 = {acc[mt][nt][2] + bb.x, acc[mt][nt][3] + bb.y};
                *reinterpret_cast<float2*>(g_proj + (size_t)r * DIM + c) = v0;
                *reinterpret_cast<float2*>(g_proj + (size_t)(r + 8) * DIM + c) = v1;
                sums[mt][0] += v0.x + v0.y;
                sqs [mt][0] += v0.x * v0.x + v0.y * v0.y;
                sums[mt][1] += v1.x + v1.y;
                sqs [mt][1] += v1.x * v1.x + v1.y * v1.y;
            }
#pragma unroll
        for (int mt = 0; mt < 2; mt++)
#pragma unroll
            for (int h = 0; h < 2; h++) {
                sums[mt][h] += __shfl_xor_sync(0xFFFFFFFF, sums[mt][h], 1);
                sums[mt][h] += __shfl_xor_sync(0xFFFFFFFF, sums[mt][h], 2);
                sqs[mt][h]  += __shfl_xor_sync(0xFFFFFFFF, sqs[mt][h], 1);
                sqs[mt][h]  += __shfl_xor_sync(0xFFFFFFFF, sqs[mt][h], 2);
            }
        float* sSum = reinterpret_cast<float*>(smw);          // [4][128]
        float* sSq  = sSum + 512;
        __syncthreads();
        if (lq == 0) {
#pragma unroll
            for (int mt = 0; mt < 2; mt++)
#pragma unroll
                for (int h = 0; h < 2; h++) {
                    int r = wm * 32 + mt * 16 + q + h * 8;
                    sSum[wn * 128 + r] = sums[mt][h];
                    sSq [wn * 128 + r] = sqs[mt][h];
                }
        }
        __syncthreads();
        if (tid < 128) {
            float s = sSum[tid] + sSum[128 + tid] + sSum[256 + tid] + sSum[384 + tid];
            float qq = sSq[tid] + sSq[128 + tid] + sSq[256 + tid] + sSq[384 + tid];
            g_psum[(size_t)(m0 + tid) * 3 + blockIdx.x] = s;
            g_psq [(size_t)(m0 + tid) * 3 + blockIdx.x] = qq;
        }
    } else {
        const int s0 = n0 / 768;
#pragma unroll
        for (int mt = 0; mt < 2; mt++)
#pragma unroll
            for (int nt = 0; nt < NT; nt++) {
                int r = m0 + wm * 32 + mt * 16 + q;
                int c = n0 + wn * WN + nt * 8 + lq * 2;
                int nl = c - s0 * 768;
                int h = nl / 192, dh = nl % 192;
                int b0i = r >> 10, seq0 = r & 1023;
                int b1i = (r + 8) >> 10, seq1 = (r + 8) & 1023;
                if (s0 == 2) {
                    int z0 = b0i * 4 + h, z1 = b1i * 4 + h;
                    g_vt[((size_t)z0 * 192 + dh) * 1024 + seq0]     = __float2half_rn(acc[mt][nt][0]);
                    g_vt[((size_t)z0 * 192 + dh + 1) * 1024 + seq0] = __float2half_rn(acc[mt][nt][1]);
                    g_vt[((size_t)z1 * 192 + dh) * 1024 + seq1]     = __float2half_rn(acc[mt][nt][2]);
                    g_vt[((size_t)z1 * 192 + dh + 1) * 1024 + seq1] = __float2half_rn(acc[mt][nt][3]);
                } else {
                    __half* dst = (s0 == 0) ? g_q : g_k;
                    uint32_t p0 = pack_h2(acc[mt][nt][0], acc[mt][nt][1]);
                    uint32_t p1 = pack_h2(acc[mt][nt][2], acc[mt][nt][3]);
                    *reinterpret_cast<uint32_t*>(
                        dst + ((size_t)(b0i * 4 + h) * 1024 + seq0) * 192 + dh) = p0;
                    *reinterpret_cast<uint32_t*>(
                        dst + ((size_t)(b1i * 4 + h) * 1024 + seq1) * 192 + dh) = p1;
                }
            }
    }
}

// combine LN partials -> mu, rstd
__global__ void ln_combine() {
    int row = blockIdx.x * 256 + threadIdx.x;
    if (row >= SEQROWS) return;
    float s  = g_psum[(size_t)row * 3] + g_psum[(size_t)row * 3 + 1] + g_psum[(size_t)row * 3 + 2];
    float qq = g_psq [(size_t)row * 3] + g_psq [(size_t)row * 3 + 1] + g_psq [(size_t)row * 3 + 2];
    float mu = s * (1.f / DIM);
    float var = fmaxf(qq * (1.f / DIM) - mu * mu, 0.f);
    g_mu[row] = mu;
    g_rs[row] = rsqrtf(var + 1e-5f);
}

// ---------------------------------------------------------------------------
// Flash attention (fp16, ldmatrix fragments, 2 CTAs/SM)
// ---------------------------------------------------------------------------
constexpr int FS_Q   = 0;
constexpr int FS_KV  = 6144;
constexpr int FS_P   = 24576;
constexpr int FS_RED = 28672;
constexpr int FS_TOT = 28928;

__global__ __launch_bounds__(256, 2) void flash_attn(const float* __restrict__ temp) {
    extern __shared__ uint32_t smw[];
    const uint32_t smBase = (uint32_t)__cvta_generic_to_shared(smw);

    const int tid  = threadIdx.x;
    const int lane = tid & 31;
    const int w    = tid >> 5;       // 0..7
    const int wm   = w & 1;
    const int wn   = w >> 1;         // 0..3
    const int q    = lane >> 2;
    const int lq   = lane & 3;
    const int z    = blockIdx.y;
    const int m0   = blockIdx.x * 64;

    const __half* Qz = g_q  + (size_t)z * HW * DHd;
    const __half* Kz = g_k  + (size_t)z * HW * DHd;
    const __half* Vz = g_vt + (size_t)z * DHd * HW;
    const float ts = temp[z & 3];

    // Q load: 3 panels [64][64 halves]
#pragma unroll
    for (int i = 0; i < 6; i++) {
        int idx = tid + 256 * i;
        int c4 = idx & 7, r = (idx >> 3) & 63, p = idx >> 9;
        uint32_t dst = smBase + (uint32_t)(FS_Q + p * 2048 + r * 32 +
                                           ((c4 * 4) ^ (4 * (r & 7)))) * 4u;
        cp_async16(dst, Qz + (size_t)(m0 + r) * 192 + p * 64 + c4 * 8);
    }
    cp_commit();

    auto issuePanel = [&](int g) {
        int t = g / 5, i = g % 5, buf = g % 3;
        uint32_t base = smBase + (uint32_t)(FS_KV + buf * 6144) * 4u;
        if (i < 3) {               // K panel: 128 rows x 64 halves
#pragma unroll
            for (int j = 0; j < 4; j++) {
                int idx = tid + 256 * j;
                int c4 = idx & 7, r = idx >> 3;
                cp_async16(base + (uint32_t)(r * 32 + ((c4 * 4) ^ (4 * (r & 7)))) * 4u,
                           Kz + (size_t)(t * 128 + r) * 192 + i * 64 + c4 * 8);
            }
        } else {                   // V panel: 192 dh-rows x 64 seq halves
            int pv = i - 3;
#pragma unroll
            for (int j = 0; j < 6; j++) {
                int idx = tid + 256 * j;
                int c4 = idx & 7, r = idx >> 3;
                cp_async16(base + (uint32_t)(r * 32 + ((c4 * 4) ^ (4 * (r & 7)))) * 4u,
                           Vz + (size_t)r * 1024 + t * 128 + pv * 64 + c4 * 8);
            }
        }
    };
    issuePanel(0); cp_commit();
    issuePanel(1); cp_commit();

    constexpr float L2E = 1.4426950408889634f;
    float m_run[2][2] = {{-1e30f, -1e30f}, {-1e30f, -1e30f}};
    float l_run[2][2] = {{0.f, 0.f}, {0.f, 0.f}};
    float acc_o[2][6][4];
#pragma unroll
    for (int mt = 0; mt < 2; mt++)
#pragma unroll
        for (int nt = 0; nt < 6; nt++)
#pragma unroll
            for (int k = 0; k < 4; k++) acc_o[mt][nt][k] = 0.f;

    const int sw = 4 * q;
    float* sRed = reinterpret_cast<float*>(smw + FS_RED);

    // ldmatrix per-lane constants
    const int lr8 = lane & 7;
    const int swr = 4 * lr8;
    const int aRowL = wm * 32 + lr8 + ((lane >> 3) & 1) * 8;   // + mt*16
    const int kqA   = lane >> 4;
    const int bRowL1 = wn * 32 + (lane >> 4) * 8 + lr8;        // phase1 + p*16
    const int bRowL2 = wn * 48 + (lane >> 4) * 8 + lr8;        // phase2 + p*16
    const int kqB   = (lane >> 3) & 1;

    for (int t = 0; t < 8; t++) {
        float acc_s[2][4][4];
#pragma unroll
        for (int mt = 0; mt < 2; mt++)
#pragma unroll
            for (int nt = 0; nt < 4; nt++)
#pragma unroll
                for (int k = 0; k < 4; k++) acc_s[mt][nt][k] = 0.f;

        // ---------- phase 1: S = Q K^T ----------
        for (int pp = 0; pp < 3; pp++) {
            int g = t * 5 + pp;
            cp_wait<1>();
            __syncthreads();
            if (g + 2 < 40) issuePanel(g + 2);
            cp_commit();
            const uint32_t aAddr = smBase + (uint32_t)(FS_Q + pp * 2048) * 4u;
            const uint32_t bAddr = smBase + (uint32_t)(FS_KV + (g % 3) * 6144) * 4u;
#pragma unroll
            for (int ks = 0; ks < 4; ks++) {
                const int wA = ((ks * 2 + kqA) * 4) ^ swr;
                const int wB = ((ks * 2 + kqB) * 4) ^ swr;
                uint32_t a[2][4];
#pragma unroll
                for (int mt = 0; mt < 2; mt++)
                    ldsm4(a[mt], aAddr + (uint32_t)((aRowL + mt * 16) * 32 + wA) * 4u);
                uint32_t b[4][2];
#pragma unroll
                for (int p = 0; p < 2; p++) {
                    uint32_t tmp[4];
                    ldsm4(tmp, bAddr + (uint32_t)((bRowL1 + p * 16) * 32 + wB) * 4u);
                    b[2 * p][0] = tmp[0]; b[2 * p][1] = tmp[1];
                    b[2 * p + 1][0] = tmp[2]; b[2 * p + 1][1] = tmp[3];
                }
#pragma unroll
                for (int mt = 0; mt < 2; mt++)
#pragma unroll
                    for (int nt = 0; nt < 4; nt++)
                        mma_f16(acc_s[mt][nt], a[mt], b[nt]);
            }
        }

        // ---------- online softmax ----------
        float tmax[2][2], corr[2][2], rsum[2][2];
        {
            float rmax[2][2] = {{-1e30f, -1e30f}, {-1e30f, -1e30f}};
#pragma unroll
            for (int mt = 0; mt < 2; mt++)
#pragma unroll
                for (int nt = 0; nt < 4; nt++)
#pragma unroll
                    for (int j = 0; j < 4; j++) {
                        float v = acc_s[mt][nt][j] * ts;
                        acc_s[mt][nt][j] = v;
                        rmax[mt][j >> 1] = fmaxf(rmax[mt][j >> 1], v);
                    }
#pragma unroll
            for (int mt = 0; mt < 2; mt++)
#pragma unroll
                for (int h2 = 0; h2 < 2; h2++) {
                    float v = rmax[mt][h2];
                    v = fmaxf(v, __shfl_xor_sync(0xFFFFFFFF, v, 1));
                    v = fmaxf(v, __shfl_xor_sync(0xFFFFFFFF, v, 2));
                    rmax[mt][h2] = v;
                }
            if (lq == 0) {
#pragma unroll
                for (int mt = 0; mt < 2; mt++)
#pragma unroll
                    for (int h2 = 0; h2 < 2; h2++)
                        sRed[wn * 64 + wm * 32 + mt * 16 + q + h2 * 8] = rmax[mt][h2];
            }
            __syncthreads();
#pragma unroll
            for (int mt = 0; mt < 2; mt++)
#pragma unroll
                for (int h2 = 0; h2 < 2; h2++) {
                    int rr = wm * 32 + mt * 16 + q + h2 * 8;
                    tmax[mt][h2] = fmaxf(fmaxf(sRed[rr], sRed[64 + rr]),
                                         fmaxf(sRed[128 + rr], sRed[192 + rr]));
                }
        }
#pragma unroll
        for (int mt = 0; mt < 2; mt++)
#pragma unroll
            for (int h2 = 0; h2 < 2; h2++) {
                float nm = fmaxf(m_run[mt][h2], tmax[mt][h2]);
                corr[mt][h2] = exp2f((m_run[mt][h2] - nm) * L2E);
                m_run[mt][h2] = nm;
                rsum[mt][h2] = 0.f;
            }
#pragma unroll
        for (int mt = 0; mt < 2; mt++)
#pragma unroll
            for (int nt = 0; nt < 4; nt++)
#pragma unroll
                for (int j = 0; j < 4; j++) {
                    float pv = exp2f((acc_s[mt][nt][j] - m_run[mt][j >> 1]) * L2E);
                    acc_s[mt][nt][j] = pv;
                    rsum[mt][j >> 1] += pv;
                }
#pragma unroll
        for (int mt = 0; mt < 2; mt++)
#pragma unroll
            for (int h2 = 0; h2 < 2; h2++) {
                float v = rsum[mt][h2];
                v += __shfl_xor_sync(0xFFFFFFFF, v, 1);
                v += __shfl_xor_sync(0xFFFFFFFF, v, 2);
                rsum[mt][h2] = v;
            }
        __syncthreads();
        if (lq == 0) {
#pragma unroll
            for (int mt = 0; mt < 2; mt++)
#pragma unroll
                for (int h2 = 0; h2 < 2; h2++)
                    sRed[wn * 64 + wm * 32 + mt * 16 + q + h2 * 8] = rsum[mt][h2];
        }
        __syncthreads();
#pragma unroll
        for (int mt = 0; mt < 2; mt++)
#pragma unroll
            for (int h2 = 0; h2 < 2; h2++) {
                int rr = wm * 32 + mt * 16 + q + h2 * 8;
                float tsum = sRed[rr] + sRed[64 + rr] + sRed[128 + rr] + sRed[192 + rr];
                l_run[mt][h2] = l_run[mt][h2] * corr[mt][h2] + tsum;
            }
#pragma unroll
        for (int mt = 0; mt < 2; mt++)
#pragma unroll
            for (int nt = 0; nt < 6; nt++) {
                acc_o[mt][nt][0] *= corr[mt][0];
                acc_o[mt][nt][1] *= corr[mt][0];
                acc_o[mt][nt][2] *= corr[mt][1];
                acc_o[mt][nt][3] *= corr[mt][1];
            }
        // store P (fp16 half2 pairs)
#pragma unroll
        for (int mt = 0; mt < 2; mt++)
#pragma unroll
            for (int nt = 0; nt < 4; nt++) {
                int r0 = wm * 32 + mt * 16 + q;
                int wbase = (wn & 1) * 16 + nt * 4 + lq;
                uint32_t* pp2 = smw + FS_P + (wn >> 1) * 2048;
                pp2[r0 * 32 + (wbase ^ sw)]       = pack_h2(acc_s[mt][nt][0], acc_s[mt][nt][1]);
                pp2[(r0 + 8) * 32 + (wbase ^ sw)] = pack_h2(acc_s[mt][nt][2], acc_s[mt][nt][3]);
            }
        __syncthreads();

        // ---------- phase 2: O += P V ----------
        for (int pv = 0; pv < 2; pv++) {
            int g = t * 5 + 3 + pv;
            cp_wait<1>();
            __syncthreads();
            if (g + 2 < 40) issuePanel(g + 2);
            cp_commit();
            const uint32_t aAddr = smBase + (uint32_t)(FS_P + pv * 2048) * 4u;
            const uint32_t bAddr = smBase + (uint32_t)(FS_KV + (g % 3) * 6144) * 4u;
#pragma unroll
            for (int ks = 0; ks < 4; ks++) {
                const int wA = ((ks * 2 + kqA) * 4) ^ swr;
                const int wB = ((ks * 2 + kqB) * 4) ^ swr;
                uint32_t a[2][4];
#pragma unroll
                for (int mt = 0; mt < 2; mt++)
                    ldsm4(a[mt], aAddr + (uint32_t)((aRowL + mt * 16) * 32 + wA) * 4u);
                uint32_t b[6][2];
#pragma unroll
                for (int p = 0; p < 3; p++) {
                    uint32_t tmp[4];
                    ldsm4(tmp, bAddr + (uint32_t)((bRowL2 + p * 16) * 32 + wB) * 4u);
                    b[2 * p][0] = tmp[0]; b[2 * p][1] = tmp[1];
                    b[2 * p + 1][0] = tmp[2]; b[2 * p + 1][1] = tmp[3];
                }
#pragma unroll
                for (int mt = 0; mt < 2; mt++)
#pragma unroll
                    for (int nt = 0; nt < 6; nt++)
                        mma_f16(acc_o[mt][nt], a[mt], b[nt]);
            }
        }
    }

    // ---------- epilogue: O /= l, merged-head fp16 store ----------
    int b = z >> 2, h = z & 3;
    float inv[2][2];
#pragma unroll
    for (int mt = 0; mt < 2; mt++)
#pragma unroll
        for (int h2 = 0; h2 < 2; h2++) inv[mt][h2] = 1.f / l_run[mt][h2];
#pragma unroll
    for (int mt = 0; mt < 2; mt++)
#pragma unroll
        for (int nt = 0; nt < 6; nt++) {
            int rl = wm * 32 + mt * 16 + q;
            int col = wn * 48 + nt * 8 + 2 * lq;
            uint32_t p0 = pack_h2(acc_o[mt][nt][0] * inv[mt][0],
                                  acc_o[mt][nt][1] * inv[mt][0]);
            uint32_t p1 = pack_h2(acc_o[mt][nt][2] * inv[mt][1],
                                  acc_o[mt][nt][3] * inv[mt][1]);
            *reinterpret_cast<uint32_t*>(
                g_om + ((size_t)(b * HW + m0 + rl)) * DIM + h * DHd + col) = p0;
            *reinterpret_cast<uint32_t*>(
                g_om + ((size_t)(b * HW + m0 + rl + 8)) * DIM + h * DHd + col) = p1;
        }
}

// ---------------------------------------------------------------------------
// Producers / elementwise
// ---------------------------------------------------------------------------
__global__ void permute_t(const float* __restrict__ x,
                          const float* __restrict__ pos) {
    __shared__ float tile[32][33];
    int bz = blockIdx.z, hw0 = blockIdx.y * 32, cd0 = blockIdx.x * 32;
    int tx = threadIdx.x, ty = threadIdx.y;
#pragma unroll
    for (int k = 0; k < 4; k++) {
        int cd = cd0 + ty + 8 * k;
        tile[ty + 8 * k][tx] = x[((size_t)bz * 768 + cd) * 1024 + hw0 + tx];
    }
    __syncthreads();
#pragma unroll
    for (int k = 0; k < 4; k++) {
        int hw = hw0 + ty + 8 * k;
        int cd = cd0 + tx;
        g_t[((size_t)bz * 1024 + hw) * 768 + cd] =
            __float2half_rn(tile[tx][ty + 8 * k] + pos[(size_t)hw * 768 + cd]);
    }
}

__global__ void cvt_wq(const float* __restrict__ qkv_w) {
    int i = blockIdx.x * 256 + threadIdx.x;
    if (i < 3 * DIM * DIM) g_wq[i] = __float2half_rn(qkv_w[i]);
}
__global__ void cvt_wp(const float* __restrict__ proj_w) {
    int i = blockIdx.x * 256 + threadIdx.x;
    if (i < DIM * DIM) g_wp[i] = __float2half_rn(proj_w[i]);
}

// l2norm over seq axis: partials -> combined inv (ivq*ivk) -> scale q only
__global__ void l2_part() {
    int chunk = blockIdx.x, z = blockIdx.y, which = blockIdx.z;
    const __half* p = (which ? g_k : g_q) + ((size_t)z * HW + chunk * 128) * DHd;
    int col = threadIdx.x;
    float ss = 0.f;
#pragma unroll 4
    for (int r = 0; r < 128; r++) {
        float v = __half2float(p[(size_t)r * DHd + col]);
        ss += v * v;
    }
    g_part[(((size_t)which * BH + z) * 8 + chunk) * DHd + col] = ss;
}

__global__ void l2_inv() {
    int z = blockIdx.x;
    int col = threadIdx.x;
    float sq = 0.f, sk = 0.f;
#pragma unroll
    for (int c = 0; c < 8; c++) {
        sq += g_part[((size_t)z * 8 + c) * DHd + col];
        sk += g_part[(((size_t)BH + z) * 8 + c) * DHd + col];
    }
    float ivq = 1.f / fmaxf(sqrtf(sq), 1e-12f);
    float ivk = 1.f / fmaxf(sqrtf(sk), 1e-12f);
    g_inv[(size_t)z * DHd + col] = ivq * ivk;
}

__global__ void l2_scale() {
    int z = blockIdx.y;
    int i = blockIdx.x * 256 + threadIdx.x;
    int seq = i / 96, c2 = i % 96;
    __half2* p = reinterpret_cast<__half2*>(g_q) + ((size_t)z * HW + seq) * 96 + c2;
    float2 v = __half22float2(*p);
    const float* ivp = g_inv + (size_t)z * DHd + c2 * 2;
    *p = __floats2half2_rn(v.x * ivp[0], v.y * ivp[1]);
}

__global__ void ln_apply(const float* __restrict__ x,
                         const float* __restrict__ gamma,
                         const float* __restrict__ beta) {
    __shared__ float tile[32][33];
    int bz = blockIdx.z, hw0 = blockIdx.y * 32, cd0 = blockIdx.x * 32;
    int tx = threadIdx.x, ty = threadIdx.y;
#pragma unroll
    for (int k = 0; k < 4; k++) {
        int hw = hw0 + ty + 8 * k;
        int row = bz * 1024 + hw;
        int cd = cd0 + tx;
        float v = g_proj[(size_t)row * 768 + cd];
        tile[ty + 8 * k][tx] = (v - g_mu[row]) * g_rs[row] * gamma[cd] + beta[cd];
    }
    __syncthreads();
#pragma unroll
    for (int k = 0; k < 4; k++) {
        int cd = cd0 + ty + 8 * k;
        int hw = hw0 + tx;
        size_t oi = ((size_t)bz * 768 + cd) * 1024 + hw;
        g_y[oi] = tile[tx][ty + 8 * k] + x[oi];
    }
}

__global__ __launch_bounds__(1024) void dwconv(const float* __restrict__ dw_w,
                                               const float* __restrict__ dw_b) {
    __shared__ float tile[3][34][34];
    __shared__ float wsh[27];
    int bcd = blockIdx.x;
    int d  = bcd & 7;
    int bc = bcd >> 3;
    int c  = bc % Cc;
    int tid = threadIdx.x;

    if (tid < 27) wsh[tid] = dw_w[c * 27 + tid];

    for (int idx = tid; idx < 3 * 34 * 34; idx += 1024) {
        int pl = idx / 1156;
        int r  = (idx - pl * 1156) / 34;
        int cc = idx - pl * 1156 - r * 34;
        int dd = d - 1 + pl, hh = r - 1, ww = cc - 1;
        float val = 0.f;
        if (dd >= 0 && dd < Dd && hh >= 0 && hh < Hh && ww >= 0 && ww < Ww)
            val = g_y[(bc * Dd + dd) * HW + hh * Ww + ww];
        tile[pl][r][cc] = val;
    }
    __syncthreads();

    int h = tid >> 5, w = tid & 31;
    float s = 0.f;
#pragma unroll
    for (int pl = 0; pl < 3; pl++)
#pragma unroll
        for (int i = 0; i < 3; i++)
#pragma unroll
            for (int j = 0; j < 3; j++)
                s += tile[pl][h + i][w + j] * wsh[pl * 9 + i * 3 + j];
    g_z[bcd * HW + tid] = s + dw_b[c];
}

__global__ __launch_bounds__(128) void pwconv(const float* __restrict__ pw_w,
                                              const float* __restrict__ pw_b,
                                              float* __restrict__ out) {
    __shared__ float wsh[Cc * Cc];
    int b = blockIdx.y;
    int pos = blockIdx.x * 128 + threadIdx.x;
    constexpr int SP = Dd * HW;

    for (int i = threadIdx.x; i < Cc * Cc; i += 128) wsh[i] = pw_w[i];
    __syncthreads();

    float acc[Cc];
#pragma unroll
    for (int co = 0; co < Cc; co++) acc[co] = 0.f;

    const float* zb = g_z + b * Cc * SP + pos;
    for (int ci = 0; ci < Cc; ci++) {
        float zv = zb[ci * SP];
#pragma unroll
        for (int co = 0; co < Cc; co++) acc[co] += zv * wsh[co * Cc + ci];
    }

    const float* yb = g_y + b * Cc * SP + pos;
    float* ob = out + b * Cc * SP + pos;
#pragma unroll
    for (int co = 0; co < Cc; co++)
        ob[co * SP] = yb[co * SP] + acc[co] + pw_b[co];
}

// ---------------------------------------------------------------------------
// Launch
// ---------------------------------------------------------------------------
extern "C" void kernel_launch(void* const* d_in, const int* in_sizes, int n_in,
                              void* d_out, int out_size) {
    const float* x      = (const float*)d_in[0];
    const float* pos    = (const float*)d_in[1];
    const float* qkv_w  = (const float*)d_in[2];
    const float* proj_w = (const float*)d_in[3];
    const float* proj_b = (const float*)d_in[4];
    const float* temp   = (const float*)d_in[5];
    const float* ln_g   = (const float*)d_in[6];
    const float* ln_b   = (const float*)d_in[7];
    const float* dw_w   = (const float*)d_in[8];
    const float* dw_b   = (const float*)d_in[9];
    const float* pw_w   = (const float*)d_in[10];
    const float* pw_b   = (const float*)d_in[11];
    float* out = (float*)d_out;

    constexpr int SMEM256 = 4 * 12288 * 4;           // 192 KB (4 stages)
    constexpr int FSMEM   = FS_TOT * 4;              // 113 KB
    cudaFuncSetAttribute(tc_gemm<0>, cudaFuncAttributeMaxDynamicSharedMemorySize, SMEM256);
    cudaFuncSetAttribute(tc_gemm<3>, cudaFuncAttributeMaxDynamicSharedMemorySize, SMEM256);
    cudaFuncSetAttribute(flash_attn, cudaFuncAttributeMaxDynamicSharedMemorySize, FSMEM);

    permute_t<<<dim3(24, 32, 8), dim3(32, 8)>>>(x, pos);
    cvt_wq<<<(3 * DIM * DIM + 255) / 256, 256>>>(qkv_w);
    cvt_wp<<<(DIM * DIM + 255) / 256, 256>>>(proj_w);
    tc_gemm<0><<<dim3(9, 64, 1), 512, SMEM256>>>(nullptr);
    l2_part<<<dim3(8, 32, 2), 192>>>();
    l2_inv<<<32, 192>>>();
    l2_scale<<<dim3(384, 32, 1), 256>>>();
    flash_attn<<<dim3(16, 32), 256, FSMEM>>>(temp);
    tc_gemm<3><<<dim3(3, 64, 1), 512, SMEM256>>>(proj_b);
    ln_combine<<<SEQROWS / 256, 256>>>();
    ln_apply<<<dim3(24, 32, 8), dim3(32, 8)>>>(x, ln_g, ln_b);
    dwconv<<<Bn * Cc * Dd, 1024>>>(dw_w, dw_b);
    pwconv<<<dim3(64, Bn, 1), 128>>>(pw_w, pw_b, out);
}

// round 14
// speedup vs baseline: 1.8876x; 1.0332x over previous
#include <cuda_runtime.h>
#include <cuda_fp16.h>
#include <math.h>
#include <stdint.h>

// ---------------------------------------------------------------------------
// Problem constants
// ---------------------------------------------------------------------------
constexpr int Bn = 8, Cc = 96, Dd = 8, Hh = 32, Ww = 32;
constexpr int HW = Hh * Ww;          // 1024
constexpr int DIM = Cc * Dd;         // 768
constexpr int NH = 4;
constexpr int DHd = DIM / NH;        // 192
constexpr int SEQROWS = Bn * HW;     // 8192
constexpr int BH = Bn * NH;          // 32

// ---------------------------------------------------------------------------
// Scratch (device globals). GEMM operands in fp16.
// ---------------------------------------------------------------------------
__device__ __align__(16) __half g_t[SEQROWS * DIM];
__device__ __align__(16) __half g_wq[3 * DIM * DIM];
__device__ __align__(16) __half g_wp[DIM * DIM];
__device__ __align__(16) __half g_q[BH * HW * DHd];
__device__ __align__(16) __half g_k[BH * HW * DHd];
__device__ __align__(16) __half g_vt[BH * DHd * HW];    // V^T: [z][dh][seq]
__device__ __align__(16) __half g_om[SEQROWS * DIM];
__device__ float g_proj[SEQROWS * DIM];
__device__ float g_y[Bn * Cc * Dd * HW];
__device__ float g_z[Bn * Cc * Dd * HW];
__device__ float g_part[2 * BH * 8 * DHd];
__device__ float g_inv[BH * DHd];                       // combined ivq*ivk
__device__ float g_psum[SEQROWS * 6];
__device__ float g_psq[SEQROWS * 6];
__device__ float g_mu[SEQROWS];
__device__ float g_rs[SEQROWS];

// ---------------------------------------------------------------------------
// Helpers (baseline PTX only)
// ---------------------------------------------------------------------------
__device__ __forceinline__ void mma_f16(float* d, const uint32_t* a,
                                        const uint32_t* b) {
    asm volatile(
        "mma.sync.aligned.m16n8k16.row.col.f32.f16.f16.f32 "
        "{%0,%1,%2,%3}, {%4,%5,%6,%7}, {%8,%9}, {%0,%1,%2,%3};"
        : "+f"(d[0]), "+f"(d[1]), "+f"(d[2]), "+f"(d[3])
        : "r"(a[0]), "r"(a[1]), "r"(a[2]), "r"(a[3]), "r"(b[0]), "r"(b[1]));
}
__device__ __forceinline__ void ldsm4(uint32_t* d, uint32_t addr) {
    asm volatile("ldmatrix.sync.aligned.m8n8.x4.shared.b16 {%0,%1,%2,%3}, [%4];"
                 : "=r"(d[0]), "=r"(d[1]), "=r"(d[2]), "=r"(d[3]) : "r"(addr));
}
__device__ __forceinline__ void cp_async16(uint32_t dst, const void* src) {
    asm volatile("cp.async.cg.shared.global [%0], [%1], 16;"
                 :: "r"(dst), "l"(src) : "memory");
}
__device__ __forceinline__ void cp_commit() {
    asm volatile("cp.async.commit_group;" ::: "memory");
}
template <int N>
__device__ __forceinline__ void cp_wait() {
    asm volatile("cp.async.wait_group %0;" :: "n"(N) : "memory");
}
__device__ __forceinline__ uint32_t pack_h2(float x, float y) {
    __half2 h = __floats2half2_rn(x, y);
    return *reinterpret_cast<uint32_t*>(&h);
}

// ---------------------------------------------------------------------------
// fp16 GEMM (ldmatrix fragments): C[M,N] = A[M,K] * B[N,K]^T, K=768.
// Block 128x128x64h, 256 threads (8 warps, 4x2), warp tile 32x64,
// 3-stage cp.async (96 KB) -> 2 CTAs/SM; one barrier per iteration.
// MODE 0: QKV -> scatter q/k/vt.  MODE 3: PROJ -> g_proj (+bias, LN partials)
// ---------------------------------------------------------------------------
template <int MODE>
__global__ __launch_bounds__(256, 2) void tc_gemm(const float* __restrict__ bias) {
    constexpr int BK  = 64;
    constexpr int KK  = 768;
    constexpr int LD  = 768;
    constexpr int T   = KK / BK;             // 12
    constexpr int AW  = 128 * 32;            // 4096 words
    constexpr int BWD = 128 * 32;            // 4096 words
    constexpr int STG = AW + BWD;            // 8192 words (32 KB)
    constexpr int WN  = 64;
    constexpr int NT  = 8;

    extern __shared__ uint32_t smw[];
    const uint32_t smBase = (uint32_t)__cvta_generic_to_shared(smw);

    const int tid  = threadIdx.x;
    const int lane = tid & 31;
    const int w    = tid >> 5;               // 0..7
    const int wm   = w & 3;                  // 0..3
    const int wn   = w >> 2;                 // 0..1
    const int q    = lane >> 2;
    const int lq   = lane & 3;
    const int m0   = blockIdx.y * 128;
    const int n0   = blockIdx.x * 128;

    const __half* gA = (MODE == 0) ? g_t  : g_om;
    const __half* gB = (MODE == 0) ? g_wq : g_wp;

    const __half* aRow = gA + (size_t)m0 * LD;
    const __half* bRow = gB + (size_t)n0 * LD;

    auto loadStage = [&](int it, int s) {
        const __half* aP = aRow + it * BK;
        const __half* bP = bRow + it * BK;
        uint32_t sA = smBase + (uint32_t)(s * STG) * 4u;
        uint32_t sB = sA + AW * 4u;
#pragma unroll
        for (int i = 0; i < 4; i++) {        // A: 1024 16B-chunks
            int idx = tid + 256 * i;
            int r = idx >> 3, c4 = idx & 7;
            uint32_t dst = sA + (uint32_t)(r * 32 + ((c4 * 4) ^ (4 * (r & 7)))) * 4u;
            cp_async16(dst, aP + (size_t)r * LD + c4 * 8);
        }
#pragma unroll
        for (int i = 0; i < 4; i++) {        // B: 1024 16B-chunks
            int idx = tid + 256 * i;
            int r = idx >> 3, c4 = idx & 7;
            uint32_t dst = sB + (uint32_t)(r * 32 + ((c4 * 4) ^ (4 * (r & 7)))) * 4u;
            cp_async16(dst, bP + (size_t)r * LD + c4 * 8);
        }
    };

    float acc[2][NT][4];
#pragma unroll
    for (int mt = 0; mt < 2; mt++)
#pragma unroll
        for (int nt = 0; nt < NT; nt++)
#pragma unroll
            for (int k = 0; k < 4; k++) acc[mt][nt][k] = 0.f;

    loadStage(0, 0); cp_commit();
    loadStage(1, 1); cp_commit();

    // ldmatrix per-lane constants
    const int lr8 = lane & 7;
    const int swr = 4 * lr8;
    const int aRowL = wm * 32 + lr8 + ((lane >> 3) & 1) * 8;   // + mt*16
    const int kqA   = lane >> 4;                               // 0/1
    const int bRowL = wn * WN + (lane >> 4) * 8 + lr8;         // + p*16
    const int kqB   = (lane >> 3) & 1;

    for (int it = 0; it < T; ++it) {
        cp_wait<1>();
        __syncthreads();
        if (it + 2 < T) loadStage(it + 2, (it + 2) % 3);
        cp_commit();

        const uint32_t aAddr = smBase + (uint32_t)((it % 3) * STG) * 4u;
        const uint32_t bAddr = aAddr + AW * 4u;
#pragma unroll
        for (int ks = 0; ks < 4; ks++) {
            const int wA = ((ks * 2 + kqA) * 4) ^ swr;
            const int wB = ((ks * 2 + kqB) * 4) ^ swr;
            uint32_t a[2][4];
#pragma unroll
            for (int mt = 0; mt < 2; mt++)
                ldsm4(a[mt], aAddr + (uint32_t)((aRowL + mt * 16) * 32 + wA) * 4u);
            uint32_t b[NT][2];
#pragma unroll
            for (int p = 0; p < NT / 2; p++) {
                uint32_t tmp[4];
                ldsm4(tmp, bAddr + (uint32_t)((bRowL + p * 16) * 32 + wB) * 4u);
                b[2 * p][0] = tmp[0]; b[2 * p][1] = tmp[1];
                b[2 * p + 1][0] = tmp[2]; b[2 * p + 1][1] = tmp[3];
            }
#pragma unroll
            for (int mt = 0; mt < 2; mt++)
#pragma unroll
                for (int nt = 0; nt < NT; nt++)
                    mma_f16(acc[mt][nt], a[mt], b[nt]);
        }
    }

    // ---------------- epilogue ----------------
    if constexpr (MODE == 3) {
        float sums[2][2] = {{0.f, 0.f}, {0.f, 0.f}};
        float sqs [2][2] = {{0.f, 0.f}, {0.f, 0.f}};
#pragma unroll
        for (int mt = 0; mt < 2; mt++)
#pragma unroll
            for (int nt = 0; nt < NT; nt++) {
                int r = m0 + wm * 32 + mt * 16 + q;
                int c = n0 + wn * WN + nt * 8 + lq * 2;
                float2 bb = *reinterpret_cast<const float2*>(bias + c);
                float2 v0 = {acc[mt][nt][0] + bb.x, acc[mt][nt][1] + bb.y};
                float2 v1 = {acc[mt][nt][2] + bb.x, acc[mt][nt][3] + bb.y};
                *reinterpret_cast<float2*>(g_proj + (size_t)r * DIM + c) = v0;
                *reinterpret_cast<float2*>(g_proj + (size_t)(r + 8) * DIM + c) = v1;
                sums[mt][0] += v0.x + v0.y;
                sqs [mt][0] += v0.x * v0.x + v0.y * v0.y;
                sums[mt][1] += v1.x + v1.y;
                sqs [mt][1] += v1.x * v1.x + v1.y * v1.y;
            }
#pragma unroll
        for (int mt = 0; mt < 2; mt++)
#pragma unroll
            for (int h = 0; h < 2; h++) {
                sums[mt][h] += __shfl_xor_sync(0xFFFFFFFF, sums[mt][h], 1);
                sums[mt][h] += __shfl_xor_sync(0xFFFFFFFF, sums[mt][h], 2);
                sqs[mt][h]  += __shfl_xor_sync(0xFFFFFFFF, sqs[mt][h], 1);
                sqs[mt][h]  += __shfl_xor_sync(0xFFFFFFFF, sqs[mt][h], 2);
            }
        float* sSum = reinterpret_cast<float*>(smw);          // [2][128]
        float* sSq  = sSum + 256;
        __syncthreads();
        if (lq == 0) {
#pragma unroll
            for (int mt = 0; mt < 2; mt++)
#pragma unroll
                for (int h = 0; h < 2; h++) {
                    int r = wm * 32 + mt * 16 + q + h * 8;
                    sSum[wn * 128 + r] = sums[mt][h];
                    sSq [wn * 128 + r] = sqs[mt][h];
                }
        }
        __syncthreads();
        if (tid < 128) {
            float s = sSum[tid] + sSum[128 + tid];
            float qq = sSq[tid] + sSq[128 + tid];
            g_psum[(size_t)(m0 + tid) * 6 + blockIdx.x] = s;
            g_psq [(size_t)(m0 + tid) * 6 + blockIdx.x] = qq;
        }
    } else {
        const int s0 = n0 / 768;
#pragma unroll
        for (int mt = 0; mt < 2; mt++)
#pragma unroll
            for (int nt = 0; nt < NT; nt++) {
                int r = m0 + wm * 32 + mt * 16 + q;
                int c = n0 + wn * WN + nt * 8 + lq * 2;
                int nl = c - s0 * 768;
                int h = nl / 192, dh = nl % 192;
                int b0i = r >> 10, seq0 = r & 1023;
                int b1i = (r + 8) >> 10, seq1 = (r + 8) & 1023;
                if (s0 == 2) {
                    int z0 = b0i * 4 + h, z1 = b1i * 4 + h;
                    g_vt[((size_t)z0 * 192 + dh) * 1024 + seq0]     = __float2half_rn(acc[mt][nt][0]);
                    g_vt[((size_t)z0 * 192 + dh + 1) * 1024 + seq0] = __float2half_rn(acc[mt][nt][1]);
                    g_vt[((size_t)z1 * 192 + dh) * 1024 + seq1]     = __float2half_rn(acc[mt][nt][2]);
                    g_vt[((size_t)z1 * 192 + dh + 1) * 1024 + seq1] = __float2half_rn(acc[mt][nt][3]);
                } else {
                    __half* dst = (s0 == 0) ? g_q : g_k;
                    uint32_t p0 = pack_h2(acc[mt][nt][0], acc[mt][nt][1]);
                    uint32_t p1 = pack_h2(acc[mt][nt][2], acc[mt][nt][3]);
                    *reinterpret_cast<uint32_t*>(
                        dst + ((size_t)(b0i * 4 + h) * 1024 + seq0) * 192 + dh) = p0;
                    *reinterpret_cast<uint32_t*>(
                        dst + ((size_t)(b1i * 4 + h) * 1024 + seq1) * 192 + dh) = p1;
                }
            }
    }
}

// combine LN partials -> mu, rstd
__global__ void ln_combine() {
    int row = blockIdx.x * 256 + threadIdx.x;
    if (row >= SEQROWS) return;
    float s = 0.f, qq = 0.f;
#pragma unroll
    for (int i = 0; i < 6; i++) {
        s  += g_psum[(size_t)row * 6 + i];
        qq += g_psq [(size_t)row * 6 + i];
    }
    float mu = s * (1.f / DIM);
    float var = fmaxf(qq * (1.f / DIM) - mu * mu, 0.f);
    g_mu[row] = mu;
    g_rs[row] = rsqrtf(var + 1e-5f);
}

// ---------------------------------------------------------------------------
// Flash attention (fp16, ldmatrix fragments, 2 CTAs/SM)
// ---------------------------------------------------------------------------
constexpr int FS_Q   = 0;
constexpr int FS_KV  = 6144;
constexpr int FS_P   = 24576;
constexpr int FS_RED = 28672;
constexpr int FS_TOT = 28928;

__global__ __launch_bounds__(256, 2) void flash_attn(const float* __restrict__ temp) {
    extern __shared__ uint32_t smw[];
    const uint32_t smBase = (uint32_t)__cvta_generic_to_shared(smw);

    const int tid  = threadIdx.x;
    const int lane = tid & 31;
    const int w    = tid >> 5;       // 0..7
    const int wm   = w & 1;
    const int wn   = w >> 1;         // 0..3
    const int q    = lane >> 2;
    const int lq   = lane & 3;
    const int z    = blockIdx.y;
    const int m0   = blockIdx.x * 64;

    const __half* Qz = g_q  + (size_t)z * HW * DHd;
    const __half* Kz = g_k  + (size_t)z * HW * DHd;
    const __half* Vz = g_vt + (size_t)z * DHd * HW;
    const float ts = temp[z & 3];

    // Q load: 3 panels [64][64 halves]
#pragma unroll
    for (int i = 0; i < 6; i++) {
        int idx = tid + 256 * i;
        int c4 = idx & 7, r = (idx >> 3) & 63, p = idx >> 9;
        uint32_t dst = smBase + (uint32_t)(FS_Q + p * 2048 + r * 32 +
                                           ((c4 * 4) ^ (4 * (r & 7)))) * 4u;
        cp_async16(dst, Qz + (size_t)(m0 + r) * 192 + p * 64 + c4 * 8);
    }
    cp_commit();

    auto issuePanel = [&](int g) {
        int t = g / 5, i = g % 5, buf = g % 3;
        uint32_t base = smBase + (uint32_t)(FS_KV + buf * 6144) * 4u;
        if (i < 3) {               // K panel: 128 rows x 64 halves
#pragma unroll
            for (int j = 0; j < 4; j++) {
                int idx = tid + 256 * j;
                int c4 = idx & 7, r = idx >> 3;
                cp_async16(base + (uint32_t)(r * 32 + ((c4 * 4) ^ (4 * (r & 7)))) * 4u,
                           Kz + (size_t)(t * 128 + r) * 192 + i * 64 + c4 * 8);
            }
        } else {                   // V panel: 192 dh-rows x 64 seq halves
            int pv = i - 3;
#pragma unroll
            for (int j = 0; j < 6; j++) {
                int idx = tid + 256 * j;
                int c4 = idx & 7, r = idx >> 3;
                cp_async16(base + (uint32_t)(r * 32 + ((c4 * 4) ^ (4 * (r & 7)))) * 4u,
                           Vz + (size_t)r * 1024 + t * 128 + pv * 64 + c4 * 8);
            }
        }
    };
    issuePanel(0); cp_commit();
    issuePanel(1); cp_commit();

    constexpr float L2E = 1.4426950408889634f;
    float m_run[2][2] = {{-1e30f, -1e30f}, {-1e30f, -1e30f}};
    float l_run[2][2] = {{0.f, 0.f}, {0.f, 0.f}};
    float acc_o[2][6][4];
#pragma unroll
    for (int mt = 0; mt < 2; mt++)
#pragma unroll
        for (int nt = 0; nt < 6; nt++)
#pragma unroll
            for (int k = 0; k < 4; k++) acc_o[mt][nt][k] = 0.f;

    const int sw = 4 * q;
    float* sRed = reinterpret_cast<float*>(smw + FS_RED);

    // ldmatrix per-lane constants
    const int lr8 = lane & 7;
    const int swr = 4 * lr8;
    const int aRowL = wm * 32 + lr8 + ((lane >> 3) & 1) * 8;   // + mt*16
    const int kqA   = lane >> 4;
    const int bRowL1 = wn * 32 + (lane >> 4) * 8 + lr8;        // phase1 + p*16
    const int bRowL2 = wn * 48 + (lane >> 4) * 8 + lr8;        // phase2 + p*16
    const int kqB   = (lane >> 3) & 1;

    for (int t = 0; t < 8; t++) {
        float acc_s[2][4][4];
#pragma unroll
        for (int mt = 0; mt < 2; mt++)
#pragma unroll
            for (int nt = 0; nt < 4; nt++)
#pragma unroll
                for (int k = 0; k < 4; k++) acc_s[mt][nt][k] = 0.f;

        // ---------- phase 1: S = Q K^T ----------
        for (int pp = 0; pp < 3; pp++) {
            int g = t * 5 + pp;
            cp_wait<1>();
            __syncthreads();
            if (g + 2 < 40) issuePanel(g + 2);
            cp_commit();
            const uint32_t aAddr = smBase + (uint32_t)(FS_Q + pp * 2048) * 4u;
            const uint32_t bAddr = smBase + (uint32_t)(FS_KV + (g % 3) * 6144) * 4u;
#pragma unroll
            for (int ks = 0; ks < 4; ks++) {
                const int wA = ((ks * 2 + kqA) * 4) ^ swr;
                const int wB = ((ks * 2 + kqB) * 4) ^ swr;
                uint32_t a[2][4];
#pragma unroll
                for (int mt = 0; mt < 2; mt++)
                    ldsm4(a[mt], aAddr + (uint32_t)((aRowL + mt * 16) * 32 + wA) * 4u);
                uint32_t b[4][2];
#pragma unroll
                for (int p = 0; p < 2; p++) {
                    uint32_t tmp[4];
                    ldsm4(tmp, bAddr + (uint32_t)((bRowL1 + p * 16) * 32 + wB) * 4u);
                    b[2 * p][0] = tmp[0]; b[2 * p][1] = tmp[1];
                    b[2 * p + 1][0] = tmp[2]; b[2 * p + 1][1] = tmp[3];
                }
#pragma unroll
                for (int mt = 0; mt < 2; mt++)
#pragma unroll
                    for (int nt = 0; nt < 4; nt++)
                        mma_f16(acc_s[mt][nt], a[mt], b[nt]);
            }
        }

        // ---------- online softmax ----------
        float tmax[2][2], corr[2][2], rsum[2][2];
        {
            float rmax[2][2] = {{-1e30f, -1e30f}, {-1e30f, -1e30f}};
#pragma unroll
            for (int mt = 0; mt < 2; mt++)
#pragma unroll
                for (int nt = 0; nt < 4; nt++)
#pragma unroll
                    for (int j = 0; j < 4; j++) {
                        float v = acc_s[mt][nt][j] * ts;
                        acc_s[mt][nt][j] = v;
                        rmax[mt][j >> 1] = fmaxf(rmax[mt][j >> 1], v);
                    }
#pragma unroll
            for (int mt = 0; mt < 2; mt++)
#pragma unroll
                for (int h2 = 0; h2 < 2; h2++) {
                    float v = rmax[mt][h2];
                    v = fmaxf(v, __shfl_xor_sync(0xFFFFFFFF, v, 1));
                    v = fmaxf(v, __shfl_xor_sync(0xFFFFFFFF, v, 2));
                    rmax[mt][h2] = v;
                }
            if (lq == 0) {
#pragma unroll
                for (int mt = 0; mt < 2; mt++)
#pragma unroll
                    for (int h2 = 0; h2 < 2; h2++)
                        sRed[wn * 64 + wm * 32 + mt * 16 + q + h2 * 8] = rmax[mt][h2];
            }
            __syncthreads();
#pragma unroll
            for (int mt = 0; mt < 2; mt++)
#pragma unroll
                for (int h2 = 0; h2 < 2; h2++) {
                    int rr = wm * 32 + mt * 16 + q + h2 * 8;
                    tmax[mt][h2] = fmaxf(fmaxf(sRed[rr], sRed[64 + rr]),
                                         fmaxf(sRed[128 + rr], sRed[192 + rr]));
                }
        }
#pragma unroll
        for (int mt = 0; mt < 2; mt++)
#pragma unroll
            for (int h2 = 0; h2 < 2; h2++) {
                float nm = fmaxf(m_run[mt][h2], tmax[mt][h2]);
                corr[mt][h2] = exp2f((m_run[mt][h2] - nm) * L2E);
                m_run[mt][h2] = nm;
                rsum[mt][h2] = 0.f;
            }
#pragma unroll
        for (int mt = 0; mt < 2; mt++)
#pragma unroll
            for (int nt = 0; nt < 4; nt++)
#pragma unroll
                for (int j = 0; j < 4; j++) {
                    float pv = exp2f((acc_s[mt][nt][j] - m_run[mt][j >> 1]) * L2E);
                    acc_s[mt][nt][j] = pv;
                    rsum[mt][j >> 1] += pv;
                }
#pragma unroll
        for (int mt = 0; mt < 2; mt++)
#pragma unroll
            for (int h2 = 0; h2 < 2; h2++) {
                float v = rsum[mt][h2];
                v += __shfl_xor_sync(0xFFFFFFFF, v, 1);
                v += __shfl_xor_sync(0xFFFFFFFF, v, 2);
                rsum[mt][h2] = v;
            }
        __syncthreads();
        if (lq == 0) {
#pragma unroll
            for (int mt = 0; mt < 2; mt++)
#pragma unroll
                for (int h2 = 0; h2 < 2; h2++)
                    sRed[wn * 64 + wm * 32 + mt * 16 + q + h2 * 8] = rsum[mt][h2];
        }
        __syncthreads();
#pragma unroll
        for (int mt = 0; mt < 2; mt++)
#pragma unroll
            for (int h2 = 0; h2 < 2; h2++) {
                int rr = wm * 32 + mt * 16 + q + h2 * 8;
                float tsum = sRed[rr] + sRed[64 + rr] + sRed[128 + rr] + sRed[192 + rr];
                l_run[mt][h2] = l_run[mt][h2] * corr[mt][h2] + tsum;
            }
#pragma unroll
        for (int mt = 0; mt < 2; mt++)
#pragma unroll
            for (int nt = 0; nt < 6; nt++) {
                acc_o[mt][nt][0] *= corr[mt][0];
                acc_o[mt][nt][1] *= corr[mt][0];
                acc_o[mt][nt][2] *= corr[mt][1];
                acc_o[mt][nt][3] *= corr[mt][1];
            }
        // store P (fp16 half2 pairs)
#pragma unroll
        for (int mt = 0; mt < 2; mt++)
#pragma unroll
            for (int nt = 0; nt < 4; nt++) {
                int r0 = wm * 32 + mt * 16 + q;
                int wbase = (wn & 1) * 16 + nt * 4 + lq;
                uint32_t* pp2 = smw + FS_P + (wn >> 1) * 2048;
                pp2[r0 * 32 + (wbase ^ sw)]       = pack_h2(acc_s[mt][nt][0], acc_s[mt][nt][1]);
                pp2[(r0 + 8) * 32 + (wbase ^ sw)] = pack_h2(acc_s[mt][nt][2], acc_s[mt][nt][3]);
            }
        __syncthreads();

        // ---------- phase 2: O += P V ----------
        for (int pv = 0; pv < 2; pv++) {
            int g = t * 5 + 3 + pv;
            cp_wait<1>();
            __syncthreads();
            if (g + 2 < 40) issuePanel(g + 2);
            cp_commit();
            const uint32_t aAddr = smBase + (uint32_t)(FS_P + pv * 2048) * 4u;
            const uint32_t bAddr = smBase + (uint32_t)(FS_KV + (g % 3) * 6144) * 4u;
#pragma unroll
            for (int ks = 0; ks < 4; ks++) {
                const int wA = ((ks * 2 + kqA) * 4) ^ swr;
                const int wB = ((ks * 2 + kqB) * 4) ^ swr;
                uint32_t a[2][4];
#pragma unroll
                for (int mt = 0; mt < 2; mt++)
                    ldsm4(a[mt], aAddr + (uint32_t)((aRowL + mt * 16) * 32 + wA) * 4u);
                uint32_t b[6][2];
#pragma unroll
                for (int p = 0; p < 3; p++) {
                    uint32_t tmp[4];
                    ldsm4(tmp, bAddr + (uint32_t)((bRowL2 + p * 16) * 32 + wB) * 4u);
                    b[2 * p][0] = tmp[0]; b[2 * p][1] = tmp[1];
                    b[2 * p + 1][0] = tmp[2]; b[2 * p + 1][1] = tmp[3];
                }
#pragma unroll
                for (int mt = 0; mt < 2; mt++)
#pragma unroll
                    for (int nt = 0; nt < 6; nt++)
                        mma_f16(acc_o[mt][nt], a[mt], b[nt]);
            }
        }
    }

    // ---------- epilogue: O /= l, merged-head fp16 store ----------
    int b = z >> 2, h = z & 3;
    float inv[2][2];
#pragma unroll
    for (int mt = 0; mt < 2; mt++)
#pragma unroll
        for (int h2 = 0; h2 < 2; h2++) inv[mt][h2] = 1.f / l_run[mt][h2];
#pragma unroll
    for (int mt = 0; mt < 2; mt++)
#pragma unroll
        for (int nt = 0; nt < 6; nt++) {
            int rl = wm * 32 + mt * 16 + q;
            int col = wn * 48 + nt * 8 + 2 * lq;
            uint32_t p0 = pack_h2(acc_o[mt][nt][0] * inv[mt][0],
                                  acc_o[mt][nt][1] * inv[mt][0]);
            uint32_t p1 = pack_h2(acc_o[mt][nt][2] * inv[mt][1],
                                  acc_o[mt][nt][3] * inv[mt][1]);
            *reinterpret_cast<uint32_t*>(
                g_om + ((size_t)(b * HW + m0 + rl)) * DIM + h * DHd + col) = p0;
            *reinterpret_cast<uint32_t*>(
                g_om + ((size_t)(b * HW + m0 + rl + 8)) * DIM + h * DHd + col) = p1;
        }
}

// ---------------------------------------------------------------------------
// Producers / elementwise
// ---------------------------------------------------------------------------
__global__ void permute_t(const float* __restrict__ x,
                          const float* __restrict__ pos) {
    __shared__ float tile[32][33];
    int bz = blockIdx.z, hw0 = blockIdx.y * 32, cd0 = blockIdx.x * 32;
    int tx = threadIdx.x, ty = threadIdx.y;
#pragma unroll
    for (int k = 0; k < 4; k++) {
        int cd = cd0 + ty + 8 * k;
        tile[ty + 8 * k][tx] = x[((size_t)bz * 768 + cd) * 1024 + hw0 + tx];
    }
    __syncthreads();
#pragma unroll
    for (int k = 0; k < 4; k++) {
        int hw = hw0 + ty + 8 * k;
        int cd = cd0 + tx;
        g_t[((size_t)bz * 1024 + hw) * 768 + cd] =
            __float2half_rn(tile[tx][ty + 8 * k] + pos[(size_t)hw * 768 + cd]);
    }
}

__global__ void cvt_weights(const float* __restrict__ qkv_w,
                            const float* __restrict__ proj_w) {
    int i = blockIdx.x * 256 + threadIdx.x;
    if (i < 3 * DIM * DIM) g_wq[i] = __float2half_rn(qkv_w[i]);
    if (i < DIM * DIM)     g_wp[i] = __float2half_rn(proj_w[i]);
}

// l2norm over seq axis: partials -> combined inv (ivq*ivk) -> scale q only
__global__ void l2_part() {
    int chunk = blockIdx.x, z = blockIdx.y, which = blockIdx.z;
    const __half* p = (which ? g_k : g_q) + ((size_t)z * HW + chunk * 128) * DHd;
    int col = threadIdx.x;
    float ss = 0.f;
#pragma unroll 4
    for (int r = 0; r < 128; r++) {
        float v = __half2float(p[(size_t)r * DHd + col]);
        ss += v * v;
    }
    g_part[(((size_t)which * BH + z) * 8 + chunk) * DHd + col] = ss;
}

__global__ void l2_inv() {
    int z = blockIdx.x;
    int col = threadIdx.x;
    float sq = 0.f, sk = 0.f;
#pragma unroll
    for (int c = 0; c < 8; c++) {
        sq += g_part[((size_t)z * 8 + c) * DHd + col];
        sk += g_part[(((size_t)BH + z) * 8 + c) * DHd + col];
    }
    float ivq = 1.f / fmaxf(sqrtf(sq), 1e-12f);
    float ivk = 1.f / fmaxf(sqrtf(sk), 1e-12f);
    g_inv[(size_t)z * DHd + col] = ivq * ivk;
}

__global__ void l2_scale() {
    int z = blockIdx.y;
    int i = blockIdx.x * 256 + threadIdx.x;
    int seq = i / 96, c2 = i % 96;
    __half2* p = reinterpret_cast<__half2*>(g_q) + ((size_t)z * HW + seq) * 96 + c2;
    float2 v = __half22float2(*p);
    const float* ivp = g_inv + (size_t)z * DHd + c2 * 2;
    *p = __floats2half2_rn(v.x * ivp[0], v.y * ivp[1]);
}

__global__ void ln_apply(const float* __restrict__ x,
                         const float* __restrict__ gamma,
                         const float* __restrict__ beta) {
    __shared__ float tile[32][33];
    int bz = blockIdx.z, hw0 = blockIdx.y * 32, cd0 = blockIdx.x * 32;
    int tx = threadIdx.x, ty = threadIdx.y;
#pragma unroll
    for (int k = 0; k < 4; k++) {
        int hw = hw0 + ty + 8 * k;
        int row = bz * 1024 + hw;
        int cd = cd0 + tx;
        float v = g_proj[(size_t)row * 768 + cd];
        tile[ty + 8 * k][tx] = (v - g_mu[row]) * g_rs[row] * gamma[cd] + beta[cd];
    }
    __syncthreads();
#pragma unroll
    for (int k = 0; k < 4; k++) {
        int cd = cd0 + ty + 8 * k;
        int hw = hw0 + tx;
        size_t oi = ((size_t)bz * 768 + cd) * 1024 + hw;
        g_y[oi] = tile[tx][ty + 8 * k] + x[oi];
    }
}

__global__ __launch_bounds__(1024) void dwconv(const float* __restrict__ dw_w,
                                               const float* __restrict__ dw_b) {
    __shared__ float tile[3][34][34];
    __shared__ float wsh[27];
    int bcd = blockIdx.x;
    int d  = bcd & 7;
    int bc = bcd >> 3;
    int c  = bc % Cc;
    int tid = threadIdx.x;

    if (tid < 27) wsh[tid] = dw_w[c * 27 + tid];

    for (int idx = tid; idx < 3 * 34 * 34; idx += 1024) {
        int pl = idx / 1156;
        int r  = (idx - pl * 1156) / 34;
        int cc = idx - pl * 1156 - r * 34;
        int dd = d - 1 + pl, hh = r - 1, ww = cc - 1;
        float val = 0.f;
        if (dd >= 0 && dd < Dd && hh >= 0 && hh < Hh && ww >= 0 && ww < Ww)
            val = g_y[(bc * Dd + dd) * HW + hh * Ww + ww];
        tile[pl][r][cc] = val;
    }
    __syncthreads();

    int h = tid >> 5, w = tid & 31;
    float s = 0.f;
#pragma unroll
    for (int pl = 0; pl < 3; pl++)
#pragma unroll
        for (int i = 0; i < 3; i++)
#pragma unroll
            for (int j = 0; j < 3; j++)
                s += tile[pl][h + i][w + j] * wsh[pl * 9 + i * 3 + j];
    g_z[bcd * HW + tid] = s + dw_b[c];
}

__global__ __launch_bounds__(128) void pwconv(const float* __restrict__ pw_w,
                                              const float* __restrict__ pw_b,
                                              float* __restrict__ out) {
    __shared__ float wsh[Cc * Cc];
    int b = blockIdx.y;
    int pos = blockIdx.x * 128 + threadIdx.x;
    constexpr int SP = Dd * HW;

    for (int i = threadIdx.x; i < Cc * Cc; i += 128) wsh[i] = pw_w[i];
    __syncthreads();

    float acc[Cc];
#pragma unroll
    for (int co = 0; co < Cc; co++) acc[co] = 0.f;

    const float* zb = g_z + b * Cc * SP + pos;
    for (int ci = 0; ci < Cc; ci++) {
        float zv = zb[ci * SP];
#pragma unroll
        for (int co = 0; co < Cc; co++) acc[co] += zv * wsh[co * Cc + ci];
    }

    const float* yb = g_y + b * Cc * SP + pos;
    float* ob = out + b * Cc * SP + pos;
#pragma unroll
    for (int co = 0; co < Cc; co++)
        ob[co * SP] = yb[co * SP] + acc[co] + pw_b[co];
}

// ---------------------------------------------------------------------------
// Launch
// ---------------------------------------------------------------------------
extern "C" void kernel_launch(void* const* d_in, const int* in_sizes, int n_in,
                              void* d_out, int out_size) {
    const float* x      = (const float*)d_in[0];
    const float* pos    = (const float*)d_in[1];
    const float* qkv_w  = (const float*)d_in[2];
    const float* proj_w = (const float*)d_in[3];
    const float* proj_b = (const float*)d_in[4];
    const float* temp   = (const float*)d_in[5];
    const float* ln_g   = (const float*)d_in[6];
    const float* ln_b   = (const float*)d_in[7];
    const float* dw_w   = (const float*)d_in[8];
    const float* dw_b   = (const float*)d_in[9];
    const float* pw_w   = (const float*)d_in[10];
    const float* pw_b   = (const float*)d_in[11];
    float* out = (float*)d_out;

    constexpr int SMEMG = 3 * 8192 * 4;              // 96 KB (2 CTAs/SM)
    constexpr int FSMEM = FS_TOT * 4;                // 113 KB
    cudaFuncSetAttribute(tc_gemm<0>, cudaFuncAttributeMaxDynamicSharedMemorySize, SMEMG);
    cudaFuncSetAttribute(tc_gemm<3>, cudaFuncAttributeMaxDynamicSharedMemorySize, SMEMG);
    cudaFuncSetAttribute(flash_attn, cudaFuncAttributeMaxDynamicSharedMemorySize, FSMEM);

    permute_t<<<dim3(24, 32, 8), dim3(32, 8)>>>(x, pos);
    cvt_weights<<<(3 * DIM * DIM + 255) / 256, 256>>>(qkv_w, proj_w);
    tc_gemm<0><<<dim3(18, 64, 1), 256, SMEMG>>>(nullptr);
    l2_part<<<dim3(8, 32, 2), 192>>>();
    l2_inv<<<32, 192>>>();
    l2_scale<<<dim3(384, 32, 1), 256>>>();
    flash_attn<<<dim3(16, 32), 256, FSMEM>>>(temp);
    tc_gemm<3><<<dim3(6, 64, 1), 256, SMEMG>>>(proj_b);
    ln_combine<<<SEQROWS / 256, 256>>>();
    ln_apply<<<dim3(24, 32, 8), dim3(32, 8)>>>(x, ln_g, ln_b);
    dwconv<<<Bn * Cc * Dd, 1024>>>(dw_w, dw_b);
    pwconv<<<dim3(64, Bn, 1), 128>>>(pw_w, pw_b, out);
}

// round 16
// speedup vs baseline: 1.9292x; 1.0220x over previous
#include <cuda_runtime.h>
#include <cuda_fp16.h>
#include <math.h>
#include <stdint.h>

// ---------------------------------------------------------------------------
// Problem constants
// ---------------------------------------------------------------------------
constexpr int Bn = 8, Cc = 96, Dd = 8, Hh = 32, Ww = 32;
constexpr int HW = Hh * Ww;          // 1024
constexpr int DIM = Cc * Dd;         // 768
constexpr int NH = 4;
constexpr int DHd = DIM / NH;        // 192
constexpr int SEQROWS = Bn * HW;     // 8192
constexpr int BH = Bn * NH;          // 32

// ---------------------------------------------------------------------------
// Scratch (device globals). GEMM operands in fp16.
// ---------------------------------------------------------------------------
__device__ __align__(16) __half g_t[SEQROWS * DIM];
__device__ __align__(16) __half g_wq[3 * DIM * DIM];
__device__ __align__(16) __half g_wp[DIM * DIM];
__device__ __align__(16) __half g_q[BH * HW * DHd];
__device__ __align__(16) __half g_k[BH * HW * DHd];
__device__ __align__(16) __half g_vt[BH * DHd * HW];    // V^T: [z][dh][seq]
__device__ __align__(16) __half g_om[SEQROWS * DIM];
__device__ float g_proj[SEQROWS * DIM];
__device__ float g_y[Bn * Cc * Dd * HW];
__device__ float g_z[Bn * Cc * Dd * HW];
__device__ float g_part[2 * BH * 8 * DHd];
__device__ float g_inv[BH * DHd];                       // combined ivq*ivk
__device__ float g_psum[SEQROWS * 6];
__device__ float g_psq[SEQROWS * 6];
__device__ float g_mu[SEQROWS];
__device__ float g_rs[SEQROWS];

// ---------------------------------------------------------------------------
// Helpers (baseline PTX only)
// ---------------------------------------------------------------------------
__device__ __forceinline__ void mma_f16(float* d, const uint32_t* a,
                                        const uint32_t* b) {
    asm volatile(
        "mma.sync.aligned.m16n8k16.row.col.f32.f16.f16.f32 "
        "{%0,%1,%2,%3}, {%4,%5,%6,%7}, {%8,%9}, {%0,%1,%2,%3};"
        : "+f"(d[0]), "+f"(d[1]), "+f"(d[2]), "+f"(d[3])
        : "r"(a[0]), "r"(a[1]), "r"(a[2]), "r"(a[3]), "r"(b[0]), "r"(b[1]));
}
__device__ __forceinline__ void ldsm4(uint32_t* d, uint32_t addr) {
    asm volatile("ldmatrix.sync.aligned.m8n8.x4.shared.b16 {%0,%1,%2,%3}, [%4];"
                 : "=r"(d[0]), "=r"(d[1]), "=r"(d[2]), "=r"(d[3]) : "r"(addr));
}
__device__ __forceinline__ void cp_async16(uint32_t dst, const void* src) {
    asm volatile("cp.async.cg.shared.global [%0], [%1], 16;"
                 :: "r"(dst), "l"(src) : "memory");
}
__device__ __forceinline__ void cp_commit() {
    asm volatile("cp.async.commit_group;" ::: "memory");
}
template <int N>
__device__ __forceinline__ void cp_wait() {
    asm volatile("cp.async.wait_group %0;" :: "n"(N) : "memory");
}
__device__ __forceinline__ uint32_t pack_h2(float x, float y) {
    __half2 h = __floats2half2_rn(x, y);
    return *reinterpret_cast<uint32_t*>(&h);
}

// ---------------------------------------------------------------------------
// fp16 GEMM (ldmatrix fragments): C[M,N] = A[M,K] * B[N,K]^T, K=768.
// Block 128x128x64h, 256 threads (8 warps, 4x2), warp tile 32x64,
// 3-stage cp.async (96 KB) -> 2 CTAs/SM; one barrier per iteration.
// MODE 0: QKV -> scatter q/k/vt; q/k CTAs ALSO reduce per-column sum of
//         squares over their 128 seq rows into g_part (l2_part fused;
//         indices are for the 128-wide N tile -- R15 NaN lesson).
// MODE 3: PROJ -> g_proj (+bias, LN partials)
// ---------------------------------------------------------------------------
template <int MODE>
__global__ __launch_bounds__(256, 2) void tc_gemm(const float* __restrict__ bias) {
    constexpr int BK  = 64;
    constexpr int KK  = 768;
    constexpr int LD  = 768;
    constexpr int T   = KK / BK;             // 12
    constexpr int AW  = 128 * 32;            // 4096 words
    constexpr int BWD = 128 * 32;            // 4096 words
    constexpr int STG = AW + BWD;            // 8192 words (32 KB)
    constexpr int WN  = 64;
    constexpr int NT  = 8;

    extern __shared__ uint32_t smw[];
    const uint32_t smBase = (uint32_t)__cvta_generic_to_shared(smw);

    const int tid  = threadIdx.x;
    const int lane = tid & 31;
    const int w    = tid >> 5;               // 0..7
    const int wm   = w & 3;                  // 0..3
    const int wn   = w >> 2;                 // 0..1
    const int q    = lane >> 2;
    const int lq   = lane & 3;
    const int m0   = blockIdx.y * 128;
    const int n0   = blockIdx.x * 128;

    const __half* gA = (MODE == 0) ? g_t  : g_om;
    const __half* gB = (MODE == 0) ? g_wq : g_wp;

    const __half* aRow = gA + (size_t)m0 * LD;
    const __half* bRow = gB + (size_t)n0 * LD;

    auto loadStage = [&](int it, int s) {
        const __half* aP = aRow + it * BK;
        const __half* bP = bRow + it * BK;
        uint32_t sA = smBase + (uint32_t)(s * STG) * 4u;
        uint32_t sB = sA + AW * 4u;
#pragma unroll
        for (int i = 0; i < 4; i++) {
            int idx = tid + 256 * i;
            int r = idx >> 3, c4 = idx & 7;
            uint32_t dst = sA + (uint32_t)(r * 32 + ((c4 * 4) ^ (4 * (r & 7)))) * 4u;
            cp_async16(dst, aP + (size_t)r * LD + c4 * 8);
        }
#pragma unroll
        for (int i = 0; i < 4; i++) {
            int idx = tid + 256 * i;
            int r = idx >> 3, c4 = idx & 7;
            uint32_t dst = sB + (uint32_t)(r * 32 + ((c4 * 4) ^ (4 * (r & 7)))) * 4u;
            cp_async16(dst, bP + (size_t)r * LD + c4 * 8);
        }
    };

    float acc[2][NT][4];
#pragma unroll
    for (int mt = 0; mt < 2; mt++)
#pragma unroll
        for (int nt = 0; nt < NT; nt++)
#pragma unroll
            for (int k = 0; k < 4; k++) acc[mt][nt][k] = 0.f;

    loadStage(0, 0); cp_commit();
    loadStage(1, 1); cp_commit();

    // ldmatrix per-lane constants
    const int lr8 = lane & 7;
    const int swr = 4 * lr8;
    const int aRowL = wm * 32 + lr8 + ((lane >> 3) & 1) * 8;   // + mt*16
    const int kqA   = lane >> 4;                               // 0/1
    const int bRowL = wn * WN + (lane >> 4) * 8 + lr8;         // + p*16
    const int kqB   = (lane >> 3) & 1;

    for (int it = 0; it < T; ++it) {
        cp_wait<1>();
        __syncthreads();
        if (it + 2 < T) loadStage(it + 2, (it + 2) % 3);
        cp_commit();

        const uint32_t aAddr = smBase + (uint32_t)((it % 3) * STG) * 4u;
        const uint32_t bAddr = aAddr + AW * 4u;
#pragma unroll
        for (int ks = 0; ks < 4; ks++) {
            const int wA = ((ks * 2 + kqA) * 4) ^ swr;
            const int wB = ((ks * 2 + kqB) * 4) ^ swr;
            uint32_t a[2][4];
#pragma unroll
            for (int mt = 0; mt < 2; mt++)
                ldsm4(a[mt], aAddr + (uint32_t)((aRowL + mt * 16) * 32 + wA) * 4u);
            uint32_t b[NT][2];
#pragma unroll
            for (int p = 0; p < NT / 2; p++) {
                uint32_t tmp[4];
                ldsm4(tmp, bAddr + (uint32_t)((bRowL + p * 16) * 32 + wB) * 4u);
                b[2 * p][0] = tmp[0]; b[2 * p][1] = tmp[1];
                b[2 * p + 1][0] = tmp[2]; b[2 * p + 1][1] = tmp[3];
            }
#pragma unroll
            for (int mt = 0; mt < 2; mt++)
#pragma unroll
                for (int nt = 0; nt < NT; nt++)
                    mma_f16(acc[mt][nt], a[mt], b[nt]);
        }
    }

    // ---------------- epilogue ----------------
    if constexpr (MODE == 3) {
        float sums[2][2] = {{0.f, 0.f}, {0.f, 0.f}};
        float sqs [2][2] = {{0.f, 0.f}, {0.f, 0.f}};
#pragma unroll
        for (int mt = 0; mt < 2; mt++)
#pragma unroll
            for (int nt = 0; nt < NT; nt++) {
                int r = m0 + wm * 32 + mt * 16 + q;
                int c = n0 + wn * WN + nt * 8 + lq * 2;
                float2 bb = *reinterpret_cast<const float2*>(bias + c);
                float2 v0 = {acc[mt][nt][0] + bb.x, acc[mt][nt][1] + bb.y};
                float2 v1 = {acc[mt][nt][2] + bb.x, acc[mt][nt][3] + bb.y};
                *reinterpret_cast<float2*>(g_proj + (size_t)r * DIM + c) = v0;
                *reinterpret_cast<float2*>(g_proj + (size_t)(r + 8) * DIM + c) = v1;
                sums[mt][0] += v0.x + v0.y;
                sqs [mt][0] += v0.x * v0.x + v0.y * v0.y;
                sums[mt][1] += v1.x + v1.y;
                sqs [mt][1] += v1.x * v1.x + v1.y * v1.y;
            }
#pragma unroll
        for (int mt = 0; mt < 2; mt++)
#pragma unroll
            for (int h = 0; h < 2; h++) {
                sums[mt][h] += __shfl_xor_sync(0xFFFFFFFF, sums[mt][h], 1);
                sums[mt][h] += __shfl_xor_sync(0xFFFFFFFF, sums[mt][h], 2);
                sqs[mt][h]  += __shfl_xor_sync(0xFFFFFFFF, sqs[mt][h], 1);
                sqs[mt][h]  += __shfl_xor_sync(0xFFFFFFFF, sqs[mt][h], 2);
            }
        float* sSum = reinterpret_cast<float*>(smw);          // [2][128]
        float* sSq  = sSum + 256;
        __syncthreads();
        if (lq == 0) {
#pragma unroll
            for (int mt = 0; mt < 2; mt++)
#pragma unroll
                for (int h = 0; h < 2; h++) {
                    int r = wm * 32 + mt * 16 + q + h * 8;
                    sSum[wn * 128 + r] = sums[mt][h];
                    sSq [wn * 128 + r] = sqs[mt][h];
                }
        }
        __syncthreads();
        if (tid < 128) {
            float s = sSum[tid] + sSum[128 + tid];
            float qq = sSq[tid] + sSq[128 + tid];
            g_psum[(size_t)(m0 + tid) * 6 + blockIdx.x] = s;
            g_psq [(size_t)(m0 + tid) * 6 + blockIdx.x] = qq;
        }
    } else {
        const int s0 = n0 / 768;
        float ss[NT][2];
#pragma unroll
        for (int nt = 0; nt < NT; nt++) { ss[nt][0] = 0.f; ss[nt][1] = 0.f; }
#pragma unroll
        for (int mt = 0; mt < 2; mt++)
#pragma unroll
            for (int nt = 0; nt < NT; nt++) {
                int r = m0 + wm * 32 + mt * 16 + q;
                int c = n0 + wn * WN + nt * 8 + lq * 2;
                int nl = c - s0 * 768;
                int h = nl / 192, dh = nl % 192;
                int b0i = r >> 10, seq0 = r & 1023;
                int b1i = (r + 8) >> 10, seq1 = (r + 8) & 1023;
                if (s0 == 2) {
                    int z0 = b0i * 4 + h, z1 = b1i * 4 + h;
                    g_vt[((size_t)z0 * 192 + dh) * 1024 + seq0]     = __float2half_rn(acc[mt][nt][0]);
                    g_vt[((size_t)z0 * 192 + dh + 1) * 1024 + seq0] = __float2half_rn(acc[mt][nt][1]);
                    g_vt[((size_t)z1 * 192 + dh) * 1024 + seq1]     = __float2half_rn(acc[mt][nt][2]);
                    g_vt[((size_t)z1 * 192 + dh + 1) * 1024 + seq1] = __float2half_rn(acc[mt][nt][3]);
                } else {
                    __half* dst = (s0 == 0) ? g_q : g_k;
                    uint32_t p0 = pack_h2(acc[mt][nt][0], acc[mt][nt][1]);
                    uint32_t p1 = pack_h2(acc[mt][nt][2], acc[mt][nt][3]);
                    *reinterpret_cast<uint32_t*>(
                        dst + ((size_t)(b0i * 4 + h) * 1024 + seq0) * 192 + dh) = p0;
                    *reinterpret_cast<uint32_t*>(
                        dst + ((size_t)(b1i * 4 + h) * 1024 + seq1) * 192 + dh) = p1;
                    ss[nt][0] += acc[mt][nt][0] * acc[mt][nt][0]
                               + acc[mt][nt][2] * acc[mt][nt][2];
                    ss[nt][1] += acc[mt][nt][1] * acc[mt][nt][1]
                               + acc[mt][nt][3] * acc[mt][nt][3];
                }
            }
        if (s0 < 2) {
            // reduce over q (lane bits 2..4) -> per-(wn,nt,lq) column sums
#pragma unroll
            for (int nt = 0; nt < NT; nt++)
#pragma unroll
                for (int j = 0; j < 2; j++) {
                    ss[nt][j] += __shfl_xor_sync(0xFFFFFFFF, ss[nt][j], 4);
                    ss[nt][j] += __shfl_xor_sync(0xFFFFFFFF, ss[nt][j], 8);
                    ss[nt][j] += __shfl_xor_sync(0xFFFFFFFF, ss[nt][j], 16);
                }
            float* sSq = reinterpret_cast<float*>(smw);      // [4][128]
            __syncthreads();
            if (q == 0) {
#pragma unroll
                for (int nt = 0; nt < NT; nt++) {
                    int cl = wn * WN + nt * 8 + lq * 2;      // 0..127
                    sSq[wm * 128 + cl]     = ss[nt][0];
                    sSq[wm * 128 + cl + 1] = ss[nt][1];
                }
            }
            __syncthreads();
            if (tid < 128) {
                float tot = sSq[tid] + sSq[128 + tid] + sSq[256 + tid] + sSq[384 + tid];
                int nl = n0 + tid - s0 * 768;
                int h = nl / 192, dh = nl % 192;
                int z = (m0 >> 10) * 4 + h;
                int chunk = (m0 & 1023) >> 7;
                g_part[(((size_t)s0 * BH + z) * 8 + chunk) * DHd + dh] = tot;
            }
        }
    }
}

// combine LN partials -> mu, rstd
__global__ void ln_combine() {
    int row = blockIdx.x * 256 + threadIdx.x;
    if (row >= SEQROWS) return;
    float s = 0.f, qq = 0.f;
#pragma unroll
    for (int i = 0; i < 6; i++) {
        s  += g_psum[(size_t)row * 6 + i];
        qq += g_psq [(size_t)row * 6 + i];
    }
    float mu = s * (1.f / DIM);
    float var = fmaxf(qq * (1.f / DIM) - mu * mu, 0.f);
    g_mu[row] = mu;
    g_rs[row] = rsqrtf(var + 1e-5f);
}

// ---------------------------------------------------------------------------
// Flash attention (fp16, ldmatrix fragments, 2 CTAs/SM)
// ---------------------------------------------------------------------------
constexpr int FS_Q   = 0;
constexpr int FS_KV  = 6144;
constexpr int FS_P   = 24576;
constexpr int FS_RED = 28672;
constexpr int FS_TOT = 28928;

__global__ __launch_bounds__(256, 2) void flash_attn(const float* __restrict__ temp) {
    extern __shared__ uint32_t smw[];
    const uint32_t smBase = (uint32_t)__cvta_generic_to_shared(smw);

    const int tid  = threadIdx.x;
    const int lane = tid & 31;
    const int w    = tid >> 5;       // 0..7
    const int wm   = w & 1;
    const int wn   = w >> 1;         // 0..3
    const int q    = lane >> 2;
    const int lq   = lane & 3;
    const int z    = blockIdx.y;
    const int m0   = blockIdx.x * 64;

    const __half* Qz = g_q  + (size_t)z * HW * DHd;
    const __half* Kz = g_k  + (size_t)z * HW * DHd;
    const __half* Vz = g_vt + (size_t)z * DHd * HW;
    const float ts = temp[z & 3];

    // Q load: 3 panels [64][64 halves]
#pragma unroll
    for (int i = 0; i < 6; i++) {
        int idx = tid + 256 * i;
        int c4 = idx & 7, r = (idx >> 3) & 63, p = idx >> 9;
        uint32_t dst = smBase + (uint32_t)(FS_Q + p * 2048 + r * 32 +
                                           ((c4 * 4) ^ (4 * (r & 7)))) * 4u;
        cp_async16(dst, Qz + (size_t)(m0 + r) * 192 + p * 64 + c4 * 8);
    }
    cp_commit();

    auto issuePanel = [&](int g) {
        int t = g / 5, i = g % 5, buf = g % 3;
        uint32_t base = smBase + (uint32_t)(FS_KV + buf * 6144) * 4u;
        if (i < 3) {               // K panel: 128 rows x 64 halves
#pragma unroll
            for (int j = 0; j < 4; j++) {
                int idx = tid + 256 * j;
                int c4 = idx & 7, r = idx >> 3;
                cp_async16(base + (uint32_t)(r * 32 + ((c4 * 4) ^ (4 * (r & 7)))) * 4u,
                           Kz + (size_t)(t * 128 + r) * 192 + i * 64 + c4 * 8);
            }
        } else {                   // V panel: 192 dh-rows x 64 seq halves
            int pv = i - 3;
#pragma unroll
            for (int j = 0; j < 6; j++) {
                int idx = tid + 256 * j;
                int c4 = idx & 7, r = idx >> 3;
                cp_async16(base + (uint32_t)(r * 32 + ((c4 * 4) ^ (4 * (r & 7)))) * 4u,
                           Vz + (size_t)r * 1024 + t * 128 + pv * 64 + c4 * 8);
            }
        }
    };
    issuePanel(0); cp_commit();
    issuePanel(1); cp_commit();

    constexpr float L2E = 1.4426950408889634f;
    float m_run[2][2] = {{-1e30f, -1e30f}, {-1e30f, -1e30f}};
    float l_run[2][2] = {{0.f, 0.f}, {0.f, 0.f}};
    float acc_o[2][6][4];
#pragma unroll
    for (int mt = 0; mt < 2; mt++)
#pragma unroll
        for (int nt = 0; nt < 6; nt++)
#pragma unroll
            for (int k = 0; k < 4; k++) acc_o[mt][nt][k] = 0.f;

    const int sw = 4 * q;
    float* sRed = reinterpret_cast<float*>(smw + FS_RED);

    // ldmatrix per-lane constants
    const int lr8 = lane & 7;
    const int swr = 4 * lr8;
    const int aRowL = wm * 32 + lr8 + ((lane >> 3) & 1) * 8;   // + mt*16
    const int kqA   = lane >> 4;
    const int bRowL1 = wn * 32 + (lane >> 4) * 8 + lr8;        // phase1 + p*16
    const int bRowL2 = wn * 48 + (lane >> 4) * 8 + lr8;        // phase2 + p*16
    const int kqB   = (lane >> 3) & 1;

    for (int t = 0; t < 8; t++) {
        float acc_s[2][4][4];
#pragma unroll
        for (int mt = 0; mt < 2; mt++)
#pragma unroll
            for (int nt = 0; nt < 4; nt++)
#pragma unroll
                for (int k = 0; k < 4; k++) acc_s[mt][nt][k] = 0.f;

        // ---------- phase 1: S = Q K^T ----------
        for (int pp = 0; pp < 3; pp++) {
            int g = t * 5 + pp;
            cp_wait<1>();
            __syncthreads();
            if (g + 2 < 40) issuePanel(g + 2);
            cp_commit();
            const uint32_t aAddr = smBase + (uint32_t)(FS_Q + pp * 2048) * 4u;
            const uint32_t bAddr = smBase + (uint32_t)(FS_KV + (g % 3) * 6144) * 4u;
#pragma unroll
            for (int ks = 0; ks < 4; ks++) {
                const int wA = ((ks * 2 + kqA) * 4) ^ swr;
                const int wB = ((ks * 2 + kqB) * 4) ^ swr;
                uint32_t a[2][4];
#pragma unroll
                for (int mt = 0; mt < 2; mt++)
                    ldsm4(a[mt], aAddr + (uint32_t)((aRowL + mt * 16) * 32 + wA) * 4u);
                uint32_t b[4][2];
#pragma unroll
                for (int p = 0; p < 2; p++) {
                    uint32_t tmp[4];
                    ldsm4(tmp, bAddr + (uint32_t)((bRowL1 + p * 16) * 32 + wB) * 4u);
                    b[2 * p][0] = tmp[0]; b[2 * p][1] = tmp[1];
                    b[2 * p + 1][0] = tmp[2]; b[2 * p + 1][1] = tmp[3];
                }
#pragma unroll
                for (int mt = 0; mt < 2; mt++)
#pragma unroll
                    for (int nt = 0; nt < 4; nt++)
                        mma_f16(acc_s[mt][nt], a[mt], b[nt]);
            }
        }

        // ---------- online softmax ----------
        float tmax[2][2], corr[2][2], rsum[2][2];
        {
            float rmax[2][2] = {{-1e30f, -1e30f}, {-1e30f, -1e30f}};
#pragma unroll
            for (int mt = 0; mt < 2; mt++)
#pragma unroll
                for (int nt = 0; nt < 4; nt++)
#pragma unroll
                    for (int j = 0; j < 4; j++) {
                        float v = acc_s[mt][nt][j] * ts;
                        acc_s[mt][nt][j] = v;
                        rmax[mt][j >> 1] = fmaxf(rmax[mt][j >> 1], v);
                    }
#pragma unroll
            for (int mt = 0; mt < 2; mt++)
#pragma unroll
                for (int h2 = 0; h2 < 2; h2++) {
                    float v = rmax[mt][h2];
                    v = fmaxf(v, __shfl_xor_sync(0xFFFFFFFF, v, 1));
                    v = fmaxf(v, __shfl_xor_sync(0xFFFFFFFF, v, 2));
                    rmax[mt][h2] = v;
                }
            if (lq == 0) {
#pragma unroll
                for (int mt = 0; mt < 2; mt++)
#pragma unroll
                    for (int h2 = 0; h2 < 2; h2++)
                        sRed[wn * 64 + wm * 32 + mt * 16 + q + h2 * 8] = rmax[mt][h2];
            }
            __syncthreads();
#pragma unroll
            for (int mt = 0; mt < 2; mt++)
#pragma unroll
                for (int h2 = 0; h2 < 2; h2++) {
                    int rr = wm * 32 + mt * 16 + q + h2 * 8;
                    tmax[mt][h2] = fmaxf(fmaxf(sRed[rr], sRed[64 + rr]),
                                         fmaxf(sRed[128 + rr], sRed[192 + rr]));
                }
        }
#pragma unroll
        for (int mt = 0; mt < 2; mt++)
#pragma unroll
            for (int h2 = 0; h2 < 2; h2++) {
                float nm = fmaxf(m_run[mt][h2], tmax[mt][h2]);
                corr[mt][h2] = exp2f((m_run[mt][h2] - nm) * L2E);
                m_run[mt][h2] = nm;
                rsum[mt][h2] = 0.f;
            }
#pragma unroll
        for (int mt = 0; mt < 2; mt++)
#pragma unroll
            for (int nt = 0; nt < 4; nt++)
#pragma unroll
                for (int j = 0; j < 4; j++) {
                    float pv = exp2f((acc_s[mt][nt][j] - m_run[mt][j >> 1]) * L2E);
                    acc_s[mt][nt][j] = pv;
                    rsum[mt][j >> 1] += pv;
                }
#pragma unroll
        for (int mt = 0; mt < 2; mt++)
#pragma unroll
            for (int h2 = 0; h2 < 2; h2++) {
                float v = rsum[mt][h2];
                v += __shfl_xor_sync(0xFFFFFFFF, v, 1);
                v += __shfl_xor_sync(0xFFFFFFFF, v, 2);
                rsum[mt][h2] = v;
            }
        __syncthreads();
        if (lq == 0) {
#pragma unroll
            for (int mt = 0; mt < 2; mt++)
#pragma unroll
                for (int h2 = 0; h2 < 2; h2++)
                    sRed[wn * 64 + wm * 32 + mt * 16 + q + h2 * 8] = rsum[mt][h2];
        }
        __syncthreads();
#pragma unroll
        for (int mt = 0; mt < 2; mt++)
#pragma unroll
            for (int h2 = 0; h2 < 2; h2++) {
                int rr = wm * 32 + mt * 16 + q + h2 * 8;
                float tsum = sRed[rr] + sRed[64 + rr] + sRed[128 + rr] + sRed[192 + rr];
                l_run[mt][h2] = l_run[mt][h2] * corr[mt][h2] + tsum;
            }
#pragma unroll
        for (int mt = 0; mt < 2; mt++)
#pragma unroll
            for (int nt = 0; nt < 6; nt++) {
                acc_o[mt][nt][0] *= corr[mt][0];
                acc_o[mt][nt][1] *= corr[mt][0];
                acc_o[mt][nt][2] *= corr[mt][1];
                acc_o[mt][nt][3] *= corr[mt][1];
            }
        // store P (fp16 half2 pairs)
#pragma unroll
        for (int mt = 0; mt < 2; mt++)
#pragma unroll
            for (int nt = 0; nt < 4; nt++) {
                int r0 = wm * 32 + mt * 16 + q;
                int wbase = (wn & 1) * 16 + nt * 4 + lq;
                uint32_t* pp2 = smw + FS_P + (wn >> 1) * 2048;
                pp2[r0 * 32 + (wbase ^ sw)]       = pack_h2(acc_s[mt][nt][0], acc_s[mt][nt][1]);
                pp2[(r0 + 8) * 32 + (wbase ^ sw)] = pack_h2(acc_s[mt][nt][2], acc_s[mt][nt][3]);
            }
        __syncthreads();

        // ---------- phase 2: O += P V ----------
        for (int pv = 0; pv < 2; pv++) {
            int g = t * 5 + 3 + pv;
            cp_wait<1>();
            __syncthreads();
            if (g + 2 < 40) issuePanel(g + 2);
            cp_commit();
            const uint32_t aAddr = smBase + (uint32_t)(FS_P + pv * 2048) * 4u;
            const uint32_t bAddr = smBase + (uint32_t)(FS_KV + (g % 3) * 6144) * 4u;
#pragma unroll
            for (int ks = 0; ks < 4; ks++) {
                const int wA = ((ks * 2 + kqA) * 4) ^ swr;
                const int wB = ((ks * 2 + kqB) * 4) ^ swr;
                uint32_t a[2][4];
#pragma unroll
                for (int mt = 0; mt < 2; mt++)
                    ldsm4(a[mt], aAddr + (uint32_t)((aRowL + mt * 16) * 32 + wA) * 4u);
                uint32_t b[6][2];
#pragma unroll
                for (int p = 0; p < 3; p++) {
                    uint32_t tmp[4];
                    ldsm4(tmp, bAddr + (uint32_t)((bRowL2 + p * 16) * 32 + wB) * 4u);
                    b[2 * p][0] = tmp[0]; b[2 * p][1] = tmp[1];
                    b[2 * p + 1][0] = tmp[2]; b[2 * p + 1][1] = tmp[3];
                }
#pragma unroll
                for (int mt = 0; mt < 2; mt++)
#pragma unroll
                    for (int nt = 0; nt < 6; nt++)
                        mma_f16(acc_o[mt][nt], a[mt], b[nt]);
            }
        }
    }

    // ---------- epilogue: O /= l, merged-head fp16 store ----------
    int b = z >> 2, h = z & 3;
    float inv[2][2];
#pragma unroll
    for (int mt = 0; mt < 2; mt++)
#pragma unroll
        for (int h2 = 0; h2 < 2; h2++) inv[mt][h2] = 1.f / l_run[mt][h2];
#pragma unroll
    for (int mt = 0; mt < 2; mt++)
#pragma unroll
        for (int nt = 0; nt < 6; nt++) {
            int rl = wm * 32 + mt * 16 + q;
            int col = wn * 48 + nt * 8 + 2 * lq;
            uint32_t p0 = pack_h2(acc_o[mt][nt][0] * inv[mt][0],
                                  acc_o[mt][nt][1] * inv[mt][0]);
            uint32_t p1 = pack_h2(acc_o[mt][nt][2] * inv[mt][1],
                                  acc_o[mt][nt][3] * inv[mt][1]);
            *reinterpret_cast<uint32_t*>(
                g_om + ((size_t)(b * HW + m0 + rl)) * DIM + h * DHd + col) = p0;
            *reinterpret_cast<uint32_t*>(
                g_om + ((size_t)(b * HW + m0 + rl + 8)) * DIM + h * DHd + col) = p1;
        }
}

// ---------------------------------------------------------------------------
// Producers / elementwise
// ---------------------------------------------------------------------------
__global__ void permute_t(const float* __restrict__ x,
                          const float* __restrict__ pos) {
    __shared__ float tile[32][33];
    int bz = blockIdx.z, hw0 = blockIdx.y * 32, cd0 = blockIdx.x * 32;
    int tx = threadIdx.x, ty = threadIdx.y;
#pragma unroll
    for (int k = 0; k < 4; k++) {
        int cd = cd0 + ty + 8 * k;
        tile[ty + 8 * k][tx] = x[((size_t)bz * 768 + cd) * 1024 + hw0 + tx];
    }
    __syncthreads();
#pragma unroll
    for (int k = 0; k < 4; k++) {
        int hw = hw0 + ty + 8 * k;
        int cd = cd0 + tx;
        g_t[((size_t)bz * 1024 + hw) * 768 + cd] =
            __float2half_rn(tile[tx][ty + 8 * k] + pos[(size_t)hw * 768 + cd]);
    }
}

__global__ void cvt_weights(const float* __restrict__ qkv_w,
                            const float* __restrict__ proj_w) {
    int i = blockIdx.x * 256 + threadIdx.x;
    if (i < 3 * DIM * DIM) g_wq[i] = __float2half_rn(qkv_w[i]);
    if (i < DIM * DIM)     g_wp[i] = __float2half_rn(proj_w[i]);
}

__global__ void l2_inv() {
    int z = blockIdx.x;
    int col = threadIdx.x;
    float sq = 0.f, sk = 0.f;
#pragma unroll
    for (int c = 0; c < 8; c++) {
        sq += g_part[((size_t)z * 8 + c) * DHd + col];
        sk += g_part[(((size_t)BH + z) * 8 + c) * DHd + col];
    }
    float ivq = 1.f / fmaxf(sqrtf(sq), 1e-12f);
    float ivk = 1.f / fmaxf(sqrtf(sk), 1e-12f);
    g_inv[(size_t)z * DHd + col] = ivq * ivk;
}

__global__ void l2_scale() {
    int z = blockIdx.y;
    int i = blockIdx.x * 256 + threadIdx.x;
    int seq = i / 96, c2 = i % 96;
    __half2* p = reinterpret_cast<__half2*>(g_q) + ((size_t)z * HW + seq) * 96 + c2;
    float2 v = __half22float2(*p);
    const float* ivp = g_inv + (size_t)z * DHd + c2 * 2;
    *p = __floats2half2_rn(v.x * ivp[0], v.y * ivp[1]);
}

__global__ void ln_apply(const float* __restrict__ x,
                         const float* __restrict__ gamma,
                         const float* __restrict__ beta) {
    __shared__ float tile[32][33];
    int bz = blockIdx.z, hw0 = blockIdx.y * 32, cd0 = blockIdx.x * 32;
    int tx = threadIdx.x, ty = threadIdx.y;
#pragma unroll
    for (int k = 0; k < 4; k++) {
        int hw = hw0 + ty + 8 * k;
        int row = bz * 1024 + hw;
        int cd = cd0 + tx;
        float v = g_proj[(size_t)row * 768 + cd];
        tile[ty + 8 * k][tx] = (v - g_mu[row]) * g_rs[row] * gamma[cd] + beta[cd];
    }
    __syncthreads();
#pragma unroll
    for (int k = 0; k < 4; k++) {
        int cd = cd0 + ty + 8 * k;
        int hw = hw0 + tx;
        size_t oi = ((size_t)bz * 768 + cd) * 1024 + hw;
        g_y[oi] = tile[tx][ty + 8 * k] + x[oi];
    }
}

__global__ __launch_bounds__(1024) void dwconv(const float* __restrict__ dw_w,
                                               const float* __restrict__ dw_b) {
    __shared__ float tile[3][34][34];
    __shared__ float wsh[27];
    int bcd = blockIdx.x;
    int d  = bcd & 7;
    int bc = bcd >> 3;
    int c  = bc % Cc;
    int tid = threadIdx.x;

    if (tid < 27) wsh[tid] = dw_w[c * 27 + tid];

    for (int idx = tid; idx < 3 * 34 * 34; idx += 1024) {
        int pl = idx / 1156;
        int r  = (idx - pl * 1156) / 34;
        int cc = idx - pl * 1156 - r * 34;
        int dd = d - 1 + pl, hh = r - 1, ww = cc - 1;
        float val = 0.f;
        if (dd >= 0 && dd < Dd && hh >= 0 && hh < Hh && ww >= 0 && ww < Ww)
            val = g_y[(bc * Dd + dd) * HW + hh * Ww + ww];
        tile[pl][r][cc] = val;
    }
    __syncthreads();

    int h = tid >> 5, w = tid & 31;
    float s = 0.f;
#pragma unroll
    for (int pl = 0; pl < 3; pl++)
#pragma unroll
        for (int i = 0; i < 3; i++)
#pragma unroll
            for (int j = 0; j < 3; j++)
                s += tile[pl][h + i][w + j] * wsh[pl * 9 + i * 3 + j];
    g_z[bcd * HW + tid] = s + dw_b[c];
}

__global__ __launch_bounds__(128) void pwconv(const float* __restrict__ pw_w,
                                              const float* __restrict__ pw_b,
                                              float* __restrict__ out) {
    __shared__ float wsh[Cc * Cc];
    int b = blockIdx.y;
    int pos = blockIdx.x * 128 + threadIdx.x;
    constexpr int SP = Dd * HW;

    for (int i = threadIdx.x; i < Cc * Cc; i += 128) wsh[i] = pw_w[i];
    __syncthreads();

    float acc[Cc];
#pragma unroll
    for (int co = 0; co < Cc; co++) acc[co] = 0.f;

    const float* zb = g_z + b * Cc * SP + pos;
    for (int ci = 0; ci < Cc; ci++) {
        float zv = zb[ci * SP];
#pragma unroll
        for (int co = 0; co < Cc; co++) acc[co] += zv * wsh[co * Cc + ci];
    }

    const float* yb = g_y + b * Cc * SP + pos;
    float* ob = out + b * Cc * SP + pos;
#pragma unroll
    for (int co = 0; co < Cc; co++)
        ob[co * SP] = yb[co * SP] + acc[co] + pw_b[co];
}

// ---------------------------------------------------------------------------
// Launch
// ---------------------------------------------------------------------------
extern "C" void kernel_launch(void* const* d_in, const int* in_sizes, int n_in,
                              void* d_out, int out_size) {
    const float* x      = (const float*)d_in[0];
    const float* pos    = (const float*)d_in[1];
    const float* qkv_w  = (const float*)d_in[2];
    const float* proj_w = (const float*)d_in[3];
    const float* proj_b = (const float*)d_in[4];
    const float* temp   = (const float*)d_in[5];
    const float* ln_g   = (const float*)d_in[6];
    const float* ln_b   = (const float*)d_in[7];
    const float* dw_w   = (const float*)d_in[8];
    const float* dw_b   = (const float*)d_in[9];
    const float* pw_w   = (const float*)d_in[10];
    const float* pw_b   = (const float*)d_in[11];
    float* out = (float*)d_out;

    constexpr int SMEMG = 3 * 8192 * 4;              // 96 KB (2 CTAs/SM)
    constexpr int FSMEM = FS_TOT * 4;                // 113 KB
    cudaFuncSetAttribute(tc_gemm<0>, cudaFuncAttributeMaxDynamicSharedMemorySize, SMEMG);
    cudaFuncSetAttribute(tc_gemm<3>, cudaFuncAttributeMaxDynamicSharedMemorySize, SMEMG);
    cudaFuncSetAttribute(flash_attn, cudaFuncAttributeMaxDynamicSharedMemorySize, FSMEM);

    permute_t<<<dim3(24, 32, 8), dim3(32, 8)>>>(x, pos);
    cvt_weights<<<(3 * DIM * DIM + 255) / 256, 256>>>(qkv_w, proj_w);
    tc_gemm<0><<<dim3(18, 64, 1), 256, SMEMG>>>(nullptr);
    l2_inv<<<32, 192>>>();
    l2_scale<<<dim3(384, 32, 1), 256>>>();
    flash_attn<<<dim3(16, 32), 256, FSMEM>>>(temp);
    tc_gemm<3><<<dim3(6, 64, 1), 256, SMEMG>>>(proj_b);
    ln_combine<<<SEQROWS / 256, 256>>>();
    ln_apply<<<dim3(24, 32, 8), dim3(32, 8)>>>(x, ln_g, ln_b);
    dwconv<<<Bn * Cc * Dd, 1024>>>(dw_w, dw_b);
    pwconv<<<dim3(64, Bn, 1), 128>>>(pw_w, pw_b, out);
}

// round 17
// speedup vs baseline: 1.9579x; 1.0149x over previous
#include <cuda_runtime.h>
#include <cuda_fp16.h>
#include <math.h>
#include <stdint.h>

// ---------------------------------------------------------------------------
// Problem constants
// ---------------------------------------------------------------------------
constexpr int Bn = 8, Cc = 96, Dd = 8, Hh = 32, Ww = 32;
constexpr int HW = Hh * Ww;          // 1024
constexpr int DIM = Cc * Dd;         // 768
constexpr int NH = 4;
constexpr int DHd = DIM / NH;        // 192
constexpr int SEQROWS = Bn * HW;     // 8192
constexpr int BH = Bn * NH;          // 32

// ---------------------------------------------------------------------------
// Scratch (device globals). GEMM operands in fp16.
// ---------------------------------------------------------------------------
__device__ __align__(16) __half g_t[SEQROWS * DIM];
__device__ __align__(16) __half g_wq[3 * DIM * DIM];
__device__ __align__(16) __half g_wp[DIM * DIM];
__device__ __align__(16) __half g_q[BH * HW * DHd];
__device__ __align__(16) __half g_k[BH * HW * DHd];
__device__ __align__(16) __half g_vt[BH * DHd * HW];    // V^T: [z][dh][seq]
__device__ __align__(16) __half g_om[SEQROWS * DIM];
__device__ float g_proj[SEQROWS * DIM];
__device__ float g_y[Bn * Cc * Dd * HW];
__device__ float g_z[Bn * Cc * Dd * HW];
__device__ float g_part[2 * BH * 8 * DHd];
__device__ float g_inv[BH * DHd];                       // combined ivq*ivk
__device__ float g_psum[SEQROWS * 6];
__device__ float g_psq[SEQROWS * 6];

// ---------------------------------------------------------------------------
// Helpers (baseline PTX only)
// ---------------------------------------------------------------------------
__device__ __forceinline__ void mma_f16(float* d, const uint32_t* a,
                                        const uint32_t* b) {
    asm volatile(
        "mma.sync.aligned.m16n8k16.row.col.f32.f16.f16.f32 "
        "{%0,%1,%2,%3}, {%4,%5,%6,%7}, {%8,%9}, {%0,%1,%2,%3};"
        : "+f"(d[0]), "+f"(d[1]), "+f"(d[2]), "+f"(d[3])
        : "r"(a[0]), "r"(a[1]), "r"(a[2]), "r"(a[3]), "r"(b[0]), "r"(b[1]));
}
__device__ __forceinline__ void ldsm4(uint32_t* d, uint32_t addr) {
    asm volatile("ldmatrix.sync.aligned.m8n8.x4.shared.b16 {%0,%1,%2,%3}, [%4];"
                 : "=r"(d[0]), "=r"(d[1]), "=r"(d[2]), "=r"(d[3]) : "r"(addr));
}
__device__ __forceinline__ void cp_async16(uint32_t dst, const void* src) {
    asm volatile("cp.async.cg.shared.global [%0], [%1], 16;"
                 :: "r"(dst), "l"(src) : "memory");
}
__device__ __forceinline__ void cp_commit() {
    asm volatile("cp.async.commit_group;" ::: "memory");
}
template <int N>
__device__ __forceinline__ void cp_wait() {
    asm volatile("cp.async.wait_group %0;" :: "n"(N) : "memory");
}
__device__ __forceinline__ uint32_t pack_h2(float x, float y) {
    __half2 h = __floats2half2_rn(x, y);
    return *reinterpret_cast<uint32_t*>(&h);
}

// ---------------------------------------------------------------------------
// fp16 GEMM (ldmatrix fragments): C[M,N] = A[M,K] * B[N,K]^T, K=768.
// Block 128x128x64h, 256 threads (8 warps, 4x2), warp tile 32x64,
// 3-stage cp.async (96 KB) -> 2 CTAs/SM; one barrier per iteration.
// MODE 0: QKV -> scatter q/k/vt; q/k CTAs ALSO reduce per-column sum of
//         squares into g_part (l2 partials fused, 128-wide tile indices).
// MODE 3: PROJ -> g_proj (+bias, LN partials)
// ---------------------------------------------------------------------------
template <int MODE>
__global__ __launch_bounds__(256, 2) void tc_gemm(const float* __restrict__ bias) {
    constexpr int BK  = 64;
    constexpr int KK  = 768;
    constexpr int LD  = 768;
    constexpr int T   = KK / BK;             // 12
    constexpr int AW  = 128 * 32;            // 4096 words
    constexpr int BWD = 128 * 32;            // 4096 words
    constexpr int STG = AW + BWD;            // 8192 words (32 KB)
    constexpr int WN  = 64;
    constexpr int NT  = 8;

    extern __shared__ uint32_t smw[];
    const uint32_t smBase = (uint32_t)__cvta_generic_to_shared(smw);

    const int tid  = threadIdx.x;
    const int lane = tid & 31;
    const int w    = tid >> 5;               // 0..7
    const int wm   = w & 3;                  // 0..3
    const int wn   = w >> 2;                 // 0..1
    const int q    = lane >> 2;
    const int lq   = lane & 3;
    const int m0   = blockIdx.y * 128;
    const int n0   = blockIdx.x * 128;

    const __half* gA = (MODE == 0) ? g_t  : g_om;
    const __half* gB = (MODE == 0) ? g_wq : g_wp;

    const __half* aRow = gA + (size_t)m0 * LD;
    const __half* bRow = gB + (size_t)n0 * LD;

    auto loadStage = [&](int it, int s) {
        const __half* aP = aRow + it * BK;
        const __half* bP = bRow + it * BK;
        uint32_t sA = smBase + (uint32_t)(s * STG) * 4u;
        uint32_t sB = sA + AW * 4u;
#pragma unroll
        for (int i = 0; i < 4; i++) {
            int idx = tid + 256 * i;
            int r = idx >> 3, c4 = idx & 7;
            uint32_t dst = sA + (uint32_t)(r * 32 + ((c4 * 4) ^ (4 * (r & 7)))) * 4u;
            cp_async16(dst, aP + (size_t)r * LD + c4 * 8);
        }
#pragma unroll
        for (int i = 0; i < 4; i++) {
            int idx = tid + 256 * i;
            int r = idx >> 3, c4 = idx & 7;
            uint32_t dst = sB + (uint32_t)(r * 32 + ((c4 * 4) ^ (4 * (r & 7)))) * 4u;
            cp_async16(dst, bP + (size_t)r * LD + c4 * 8);
        }
    };

    float acc[2][NT][4];
#pragma unroll
    for (int mt = 0; mt < 2; mt++)
#pragma unroll
        for (int nt = 0; nt < NT; nt++)
#pragma unroll
            for (int k = 0; k < 4; k++) acc[mt][nt][k] = 0.f;

    loadStage(0, 0); cp_commit();
    loadStage(1, 1); cp_commit();

    // ldmatrix per-lane constants
    const int lr8 = lane & 7;
    const int swr = 4 * lr8;
    const int aRowL = wm * 32 + lr8 + ((lane >> 3) & 1) * 8;   // + mt*16
    const int kqA   = lane >> 4;                               // 0/1
    const int bRowL = wn * WN + (lane >> 4) * 8 + lr8;         // + p*16
    const int kqB   = (lane >> 3) & 1;

    for (int it = 0; it < T; ++it) {
        cp_wait<1>();
        __syncthreads();
        if (it + 2 < T) loadStage(it + 2, (it + 2) % 3);
        cp_commit();

        const uint32_t aAddr = smBase + (uint32_t)((it % 3) * STG) * 4u;
        const uint32_t bAddr = aAddr + AW * 4u;
#pragma unroll
        for (int ks = 0; ks < 4; ks++) {
            const int wA = ((ks * 2 + kqA) * 4) ^ swr;
            const int wB = ((ks * 2 + kqB) * 4) ^ swr;
            uint32_t a[2][4];
#pragma unroll
            for (int mt = 0; mt < 2; mt++)
                ldsm4(a[mt], aAddr + (uint32_t)((aRowL + mt * 16) * 32 + wA) * 4u);
            uint32_t b[NT][2];
#pragma unroll
            for (int p = 0; p < NT / 2; p++) {
                uint32_t tmp[4];
                ldsm4(tmp, bAddr + (uint32_t)((bRowL + p * 16) * 32 + wB) * 4u);
                b[2 * p][0] = tmp[0]; b[2 * p][1] = tmp[1];
                b[2 * p + 1][0] = tmp[2]; b[2 * p + 1][1] = tmp[3];
            }
#pragma unroll
            for (int mt = 0; mt < 2; mt++)
#pragma unroll
                for (int nt = 0; nt < NT; nt++)
                    mma_f16(acc[mt][nt], a[mt], b[nt]);
        }
    }

    // ---------------- epilogue ----------------
    if constexpr (MODE == 3) {
        float sums[2][2] = {{0.f, 0.f}, {0.f, 0.f}};
        float sqs [2][2] = {{0.f, 0.f}, {0.f, 0.f}};
#pragma unroll
        for (int mt = 0; mt < 2; mt++)
#pragma unroll
            for (int nt = 0; nt < NT; nt++) {
                int r = m0 + wm * 32 + mt * 16 + q;
                int c = n0 + wn * WN + nt * 8 + lq * 2;
                float2 bb = *reinterpret_cast<const float2*>(bias + c);
                float2 v0 = {acc[mt][nt][0] + bb.x, acc[mt][nt][1] + bb.y};
                float2 v1 = {acc[mt][nt][2] + bb.x, acc[mt][nt][3] + bb.y};
                *reinterpret_cast<float2*>(g_proj + (size_t)r * DIM + c) = v0;
                *reinterpret_cast<float2*>(g_proj + (size_t)(r + 8) * DIM + c) = v1;
                sums[mt][0] += v0.x + v0.y;
                sqs [mt][0] += v0.x * v0.x + v0.y * v0.y;
                sums[mt][1] += v1.x + v1.y;
                sqs [mt][1] += v1.x * v1.x + v1.y * v1.y;
            }
#pragma unroll
        for (int mt = 0; mt < 2; mt++)
#pragma unroll
            for (int h = 0; h < 2; h++) {
                sums[mt][h] += __shfl_xor_sync(0xFFFFFFFF, sums[mt][h], 1);
                sums[mt][h] += __shfl_xor_sync(0xFFFFFFFF, sums[mt][h], 2);
                sqs[mt][h]  += __shfl_xor_sync(0xFFFFFFFF, sqs[mt][h], 1);
                sqs[mt][h]  += __shfl_xor_sync(0xFFFFFFFF, sqs[mt][h], 2);
            }
        float* sSum = reinterpret_cast<float*>(smw);          // [2][128]
        float* sSq  = sSum + 256;
        __syncthreads();
        if (lq == 0) {
#pragma unroll
            for (int mt = 0; mt < 2; mt++)
#pragma unroll
                for (int h = 0; h < 2; h++) {
                    int r = wm * 32 + mt * 16 + q + h * 8;
                    sSum[wn * 128 + r] = sums[mt][h];
                    sSq [wn * 128 + r] = sqs[mt][h];
                }
        }
        __syncthreads();
        if (tid < 128) {
            float s = sSum[tid] + sSum[128 + tid];
            float qq = sSq[tid] + sSq[128 + tid];
            g_psum[(size_t)(m0 + tid) * 6 + blockIdx.x] = s;
            g_psq [(size_t)(m0 + tid) * 6 + blockIdx.x] = qq;
        }
    } else {
        const int s0 = n0 / 768;
        float ss[NT][2];
#pragma unroll
        for (int nt = 0; nt < NT; nt++) { ss[nt][0] = 0.f; ss[nt][1] = 0.f; }
#pragma unroll
        for (int mt = 0; mt < 2; mt++)
#pragma unroll
            for (int nt = 0; nt < NT; nt++) {
                int r = m0 + wm * 32 + mt * 16 + q;
                int c = n0 + wn * WN + nt * 8 + lq * 2;
                int nl = c - s0 * 768;
                int h = nl / 192, dh = nl % 192;
                int b0i = r >> 10, seq0 = r & 1023;
                int b1i = (r + 8) >> 10, seq1 = (r + 8) & 1023;
                if (s0 == 2) {
                    int z0 = b0i * 4 + h, z1 = b1i * 4 + h;
                    g_vt[((size_t)z0 * 192 + dh) * 1024 + seq0]     = __float2half_rn(acc[mt][nt][0]);
                    g_vt[((size_t)z0 * 192 + dh + 1) * 1024 + seq0] = __float2half_rn(acc[mt][nt][1]);
                    g_vt[((size_t)z1 * 192 + dh) * 1024 + seq1]     = __float2half_rn(acc[mt][nt][2]);
                    g_vt[((size_t)z1 * 192 + dh + 1) * 1024 + seq1] = __float2half_rn(acc[mt][nt][3]);
                } else {
                    __half* dst = (s0 == 0) ? g_q : g_k;
                    uint32_t p0 = pack_h2(acc[mt][nt][0], acc[mt][nt][1]);
                    uint32_t p1 = pack_h2(acc[mt][nt][2], acc[mt][nt][3]);
                    *reinterpret_cast<uint32_t*>(
                        dst + ((size_t)(b0i * 4 + h) * 1024 + seq0) * 192 + dh) = p0;
                    *reinterpret_cast<uint32_t*>(
                        dst + ((size_t)(b1i * 4 + h) * 1024 + seq1) * 192 + dh) = p1;
                    ss[nt][0] += acc[mt][nt][0] * acc[mt][nt][0]
                               + acc[mt][nt][2] * acc[mt][nt][2];
                    ss[nt][1] += acc[mt][nt][1] * acc[mt][nt][1]
                               + acc[mt][nt][3] * acc[mt][nt][3];
                }
            }
        if (s0 < 2) {
#pragma unroll
            for (int nt = 0; nt < NT; nt++)
#pragma unroll
                for (int j = 0; j < 2; j++) {
                    ss[nt][j] += __shfl_xor_sync(0xFFFFFFFF, ss[nt][j], 4);
                    ss[nt][j] += __shfl_xor_sync(0xFFFFFFFF, ss[nt][j], 8);
                    ss[nt][j] += __shfl_xor_sync(0xFFFFFFFF, ss[nt][j], 16);
                }
            float* sSq = reinterpret_cast<float*>(smw);      // [4][128]
            __syncthreads();
            if (q == 0) {
#pragma unroll
                for (int nt = 0; nt < NT; nt++) {
                    int cl = wn * WN + nt * 8 + lq * 2;      // 0..127
                    sSq[wm * 128 + cl]     = ss[nt][0];
                    sSq[wm * 128 + cl + 1] = ss[nt][1];
                }
            }
            __syncthreads();
            if (tid < 128) {
                float tot = sSq[tid] + sSq[128 + tid] + sSq[256 + tid] + sSq[384 + tid];
                int nl = n0 + tid - s0 * 768;
                int h = nl / 192, dh = nl % 192;
                int z = (m0 >> 10) * 4 + h;
                int chunk = (m0 & 1023) >> 7;
                g_part[(((size_t)s0 * BH + z) * 8 + chunk) * DHd + dh] = tot;
            }
        }
    }
}

// ---------------------------------------------------------------------------
// Flash attention (fp16, ldmatrix fragments, 2 CTAs/SM). Q is scaled
// in-smem by g_inv (combined ivq*ivk) right after its cp.async completes,
// replacing the former l2_scale kernel.
// ---------------------------------------------------------------------------
constexpr int FS_Q   = 0;
constexpr int FS_KV  = 6144;
constexpr int FS_P   = 24576;
constexpr int FS_RED = 28672;
constexpr int FS_TOT = 28928;

__global__ __launch_bounds__(256, 2) void flash_attn(const float* __restrict__ temp) {
    extern __shared__ uint32_t smw[];
    const uint32_t smBase = (uint32_t)__cvta_generic_to_shared(smw);

    const int tid  = threadIdx.x;
    const int lane = tid & 31;
    const int w    = tid >> 5;       // 0..7
    const int wm   = w & 1;
    const int wn   = w >> 1;         // 0..3
    const int q    = lane >> 2;
    const int lq   = lane & 3;
    const int z    = blockIdx.y;
    const int m0   = blockIdx.x * 64;

    const __half* Qz = g_q  + (size_t)z * HW * DHd;
    const __half* Kz = g_k  + (size_t)z * HW * DHd;
    const __half* Vz = g_vt + (size_t)z * DHd * HW;
    const float ts = temp[z & 3];

    // Q load: 3 panels [64][64 halves]
#pragma unroll
    for (int i = 0; i < 6; i++) {
        int idx = tid + 256 * i;
        int c4 = idx & 7, r = (idx >> 3) & 63, p = idx >> 9;
        uint32_t dst = smBase + (uint32_t)(FS_Q + p * 2048 + r * 32 +
                                           ((c4 * 4) ^ (4 * (r & 7)))) * 4u;
        cp_async16(dst, Qz + (size_t)(m0 + r) * 192 + p * 64 + c4 * 8);
    }
    cp_commit();

    auto issuePanel = [&](int g) {
        int t = g / 5, i = g % 5, buf = g % 3;
        uint32_t base = smBase + (uint32_t)(FS_KV + buf * 6144) * 4u;
        if (i < 3) {               // K panel: 128 rows x 64 halves
#pragma unroll
            for (int j = 0; j < 4; j++) {
                int idx = tid + 256 * j;
                int c4 = idx & 7, r = idx >> 3;
                cp_async16(base + (uint32_t)(r * 32 + ((c4 * 4) ^ (4 * (r & 7)))) * 4u,
                           Kz + (size_t)(t * 128 + r) * 192 + i * 64 + c4 * 8);
            }
        } else {                   // V panel: 192 dh-rows x 64 seq halves
            int pv = i - 3;
#pragma unroll
            for (int j = 0; j < 6; j++) {
                int idx = tid + 256 * j;
                int c4 = idx & 7, r = idx >> 3;
                cp_async16(base + (uint32_t)(r * 32 + ((c4 * 4) ^ (4 * (r & 7)))) * 4u,
                           Vz + (size_t)r * 1024 + t * 128 + pv * 64 + c4 * 8);
            }
        }
    };
    issuePanel(0); cp_commit();
    issuePanel(1); cp_commit();

    // ---- fused l2 scale of Q (in smem), replaces l2_scale kernel ----
    cp_wait<2>();                    // Q group complete (panels may be pending)
    __syncthreads();                 // cross-thread visibility of Q tile
    {
        const float* invz = g_inv + (size_t)z * DHd;
#pragma unroll
        for (int i = 0; i < 24; i++) {
            int idx = tid + 256 * i;                 // < 6144, each word once
            int p = idx >> 11, rem = idx & 2047;
            int r = rem >> 5, wc = rem & 31;
            uint32_t addr = (uint32_t)(FS_Q + p * 2048 + r * 32 +
                                       ((((wc >> 2) * 4) ^ (4 * (r & 7))) | (wc & 3)));
            uint32_t word = smw[addr];
            __half2 h2v = *reinterpret_cast<__half2*>(&word);
            float2 v = __half22float2(h2v);
            int dh = p * 64 + wc * 2;
            smw[addr] = pack_h2(v.x * invz[dh], v.y * invz[dh + 1]);
        }
    }
    // loop's first __syncthreads orders these writes before ldmatrix reads

    constexpr float L2E = 1.4426950408889634f;
    float m_run[2][2] = {{-1e30f, -1e30f}, {-1e30f, -1e30f}};
    float l_run[2][2] = {{0.f, 0.f}, {0.f, 0.f}};
    float acc_o[2][6][4];
#pragma unroll
    for (int mt = 0; mt < 2; mt++)
#pragma unroll
        for (int nt = 0; nt < 6; nt++)
#pragma unroll
            for (int k = 0; k < 4; k++) acc_o[mt][nt][k] = 0.f;

    const int sw = 4 * q;
    float* sRed = reinterpret_cast<float*>(smw + FS_RED);

    // ldmatrix per-lane constants
    const int lr8 = lane & 7;
    const int swr = 4 * lr8;
    const int aRowL = wm * 32 + lr8 + ((lane >> 3) & 1) * 8;   // + mt*16
    const int kqA   = lane >> 4;
    const int bRowL1 = wn * 32 + (lane >> 4) * 8 + lr8;        // phase1 + p*16
    const int bRowL2 = wn * 48 + (lane >> 4) * 8 + lr8;        // phase2 + p*16
    const int kqB   = (lane >> 3) & 1;

    for (int t = 0; t < 8; t++) {
        float acc_s[2][4][4];
#pragma unroll
        for (int mt = 0; mt < 2; mt++)
#pragma unroll
            for (int nt = 0; nt < 4; nt++)
#pragma unroll
                for (int k = 0; k < 4; k++) acc_s[mt][nt][k] = 0.f;

        // ---------- phase 1: S = Q K^T ----------
        for (int pp = 0; pp < 3; pp++) {
            int g = t * 5 + pp;
            cp_wait<1>();
            __syncthreads();
            if (g + 2 < 40) issuePanel(g + 2);
            cp_commit();
            const uint32_t aAddr = smBase + (uint32_t)(FS_Q + pp * 2048) * 4u;
            const uint32_t bAddr = smBase + (uint32_t)(FS_KV + (g % 3) * 6144) * 4u;
#pragma unroll
            for (int ks = 0; ks < 4; ks++) {
                const int wA = ((ks * 2 + kqA) * 4) ^ swr;
                const int wB = ((ks * 2 + kqB) * 4) ^ swr;
                uint32_t a[2][4];
#pragma unroll
                for (int mt = 0; mt < 2; mt++)
                    ldsm4(a[mt], aAddr + (uint32_t)((aRowL + mt * 16) * 32 + wA) * 4u);
                uint32_t b[4][2];
#pragma unroll
                for (int p = 0; p < 2; p++) {
                    uint32_t tmp[4];
                    ldsm4(tmp, bAddr + (uint32_t)((bRowL1 + p * 16) * 32 + wB) * 4u);
                    b[2 * p][0] = tmp[0]; b[2 * p][1] = tmp[1];
                    b[2 * p + 1][0] = tmp[2]; b[2 * p + 1][1] = tmp[3];
                }
#pragma unroll
                for (int mt = 0; mt < 2; mt++)
#pragma unroll
                    for (int nt = 0; nt < 4; nt++)
                        mma_f16(acc_s[mt][nt], a[mt], b[nt]);
            }
        }

        // ---------- online softmax ----------
        float tmax[2][2], corr[2][2], rsum[2][2];
        {
            float rmax[2][2] = {{-1e30f, -1e30f}, {-1e30f, -1e30f}};
#pragma unroll
            for (int mt = 0; mt < 2; mt++)
#pragma unroll
                for (int nt = 0; nt < 4; nt++)
#pragma unroll
                    for (int j = 0; j < 4; j++) {
                        float v = acc_s[mt][nt][j] * ts;
                        acc_s[mt][nt][j] = v;
                        rmax[mt][j >> 1] = fmaxf(rmax[mt][j >> 1], v);
                    }
#pragma unroll
            for (int mt = 0; mt < 2; mt++)
#pragma unroll
                for (int h2 = 0; h2 < 2; h2++) {
                    float v = rmax[mt][h2];
                    v = fmaxf(v, __shfl_xor_sync(0xFFFFFFFF, v, 1));
                    v = fmaxf(v, __shfl_xor_sync(0xFFFFFFFF, v, 2));
                    rmax[mt][h2] = v;
                }
            if (lq == 0) {
#pragma unroll
                for (int mt = 0; mt < 2; mt++)
#pragma unroll
                    for (int h2 = 0; h2 < 2; h2++)
                        sRed[wn * 64 + wm * 32 + mt * 16 + q + h2 * 8] = rmax[mt][h2];
            }
            __syncthreads();
#pragma unroll
            for (int mt = 0; mt < 2; mt++)
#pragma unroll
                for (int h2 = 0; h2 < 2; h2++) {
                    int rr = wm * 32 + mt * 16 + q + h2 * 8;
                    tmax[mt][h2] = fmaxf(fmaxf(sRed[rr], sRed[64 + rr]),
                                         fmaxf(sRed[128 + rr], sRed[192 + rr]));
                }
        }
#pragma unroll
        for (int mt = 0; mt < 2; mt++)
#pragma unroll
            for (int h2 = 0; h2 < 2; h2++) {
                float nm = fmaxf(m_run[mt][h2], tmax[mt][h2]);
                corr[mt][h2] = exp2f((m_run[mt][h2] - nm) * L2E);
                m_run[mt][h2] = nm;
                rsum[mt][h2] = 0.f;
            }
#pragma unroll
        for (int mt = 0; mt < 2; mt++)
#pragma unroll
            for (int nt = 0; nt < 4; nt++)
#pragma unroll
                for (int j = 0; j < 4; j++) {
                    float pv = exp2f((acc_s[mt][nt][j] - m_run[mt][j >> 1]) * L2E);
                    acc_s[mt][nt][j] = pv;
                    rsum[mt][j >> 1] += pv;
                }
#pragma unroll
        for (int mt = 0; mt < 2; mt++)
#pragma unroll
            for (int h2 = 0; h2 < 2; h2++) {
                float v = rsum[mt][h2];
                v += __shfl_xor_sync(0xFFFFFFFF, v, 1);
                v += __shfl_xor_sync(0xFFFFFFFF, v, 2);
                rsum[mt][h2] = v;
            }
        __syncthreads();
        if (lq == 0) {
#pragma unroll
            for (int mt = 0; mt < 2; mt++)
#pragma unroll
                for (int h2 = 0; h2 < 2; h2++)
                    sRed[wn * 64 + wm * 32 + mt * 16 + q + h2 * 8] = rsum[mt][h2];
        }
        __syncthreads();
#pragma unroll
        for (int mt = 0; mt < 2; mt++)
#pragma unroll
            for (int h2 = 0; h2 < 2; h2++) {
                int rr = wm * 32 + mt * 16 + q + h2 * 8;
                float tsum = sRed[rr] + sRed[64 + rr] + sRed[128 + rr] + sRed[192 + rr];
                l_run[mt][h2] = l_run[mt][h2] * corr[mt][h2] + tsum;
            }
#pragma unroll
        for (int mt = 0; mt < 2; mt++)
#pragma unroll
            for (int nt = 0; nt < 6; nt++) {
                acc_o[mt][nt][0] *= corr[mt][0];
                acc_o[mt][nt][1] *= corr[mt][0];
                acc_o[mt][nt][2] *= corr[mt][1];
                acc_o[mt][nt][3] *= corr[mt][1];
            }
        // store P (fp16 half2 pairs)
#pragma unroll
        for (int mt = 0; mt < 2; mt++)
#pragma unroll
            for (int nt = 0; nt < 4; nt++) {
                int r0 = wm * 32 + mt * 16 + q;
                int wbase = (wn & 1) * 16 + nt * 4 + lq;
                uint32_t* pp2 = smw + FS_P + (wn >> 1) * 2048;
                pp2[r0 * 32 + (wbase ^ sw)]       = pack_h2(acc_s[mt][nt][0], acc_s[mt][nt][1]);
                pp2[(r0 + 8) * 32 + (wbase ^ sw)] = pack_h2(acc_s[mt][nt][2], acc_s[mt][nt][3]);
            }
        __syncthreads();

        // ---------- phase 2: O += P V ----------
        for (int pv = 0; pv < 2; pv++) {
            int g = t * 5 + 3 + pv;
            cp_wait<1>();
            __syncthreads();
            if (g + 2 < 40) issuePanel(g + 2);
            cp_commit();
            const uint32_t aAddr = smBase + (uint32_t)(FS_P + pv * 2048) * 4u;
            const uint32_t bAddr = smBase + (uint32_t)(FS_KV + (g % 3) * 6144) * 4u;
#pragma unroll
            for (int ks = 0; ks < 4; ks++) {
                const int wA = ((ks * 2 + kqA) * 4) ^ swr;
                const int wB = ((ks * 2 + kqB) * 4) ^ swr;
                uint32_t a[2][4];
#pragma unroll
                for (int mt = 0; mt < 2; mt++)
                    ldsm4(a[mt], aAddr + (uint32_t)((aRowL + mt * 16) * 32 + wA) * 4u);
                uint32_t b[6][2];
#pragma unroll
                for (int p = 0; p < 3; p++) {
                    uint32_t tmp[4];
                    ldsm4(tmp, bAddr + (uint32_t)((bRowL2 + p * 16) * 32 + wB) * 4u);
                    b[2 * p][0] = tmp[0]; b[2 * p][1] = tmp[1];
                    b[2 * p + 1][0] = tmp[2]; b[2 * p + 1][1] = tmp[3];
                }
#pragma unroll
                for (int mt = 0; mt < 2; mt++)
#pragma unroll
                    for (int nt = 0; nt < 6; nt++)
                        mma_f16(acc_o[mt][nt], a[mt], b[nt]);
            }
        }
    }

    // ---------- epilogue: O /= l, merged-head fp16 store ----------
    int b = z >> 2, h = z & 3;
    float inv[2][2];
#pragma unroll
    for (int mt = 0; mt < 2; mt++)
#pragma unroll
        for (int h2 = 0; h2 < 2; h2++) inv[mt][h2] = 1.f / l_run[mt][h2];
#pragma unroll
    for (int mt = 0; mt < 2; mt++)
#pragma unroll
        for (int nt = 0; nt < 6; nt++) {
            int rl = wm * 32 + mt * 16 + q;
            int col = wn * 48 + nt * 8 + 2 * lq;
            uint32_t p0 = pack_h2(acc_o[mt][nt][0] * inv[mt][0],
                                  acc_o[mt][nt][1] * inv[mt][0]);
            uint32_t p1 = pack_h2(acc_o[mt][nt][2] * inv[mt][1],
                                  acc_o[mt][nt][3] * inv[mt][1]);
            *reinterpret_cast<uint32_t*>(
                g_om + ((size_t)(b * HW + m0 + rl)) * DIM + h * DHd + col) = p0;
            *reinterpret_cast<uint32_t*>(
                g_om + ((size_t)(b * HW + m0 + rl + 8)) * DIM + h * DHd + col) = p1;
        }
}

// ---------------------------------------------------------------------------
// Producers / elementwise
// ---------------------------------------------------------------------------
__global__ void permute_t(const float* __restrict__ x,
                          const float* __restrict__ pos) {
    __shared__ float tile[32][33];
    int bz = blockIdx.z, hw0 = blockIdx.y * 32, cd0 = blockIdx.x * 32;
    int tx = threadIdx.x, ty = threadIdx.y;
#pragma unroll
    for (int k = 0; k < 4; k++) {
        int cd = cd0 + ty + 8 * k;
        tile[ty + 8 * k][tx] = x[((size_t)bz * 768 + cd) * 1024 + hw0 + tx];
    }
    __syncthreads();
#pragma unroll
    for (int k = 0; k < 4; k++) {
        int hw = hw0 + ty + 8 * k;
        int cd = cd0 + tx;
        g_t[((size_t)bz * 1024 + hw) * 768 + cd] =
            __float2half_rn(tile[tx][ty + 8 * k] + pos[(size_t)hw * 768 + cd]);
    }
}

__global__ void cvt_weights(const float* __restrict__ qkv_w,
                            const float* __restrict__ proj_w) {
    int i = blockIdx.x * 256 + threadIdx.x;
    if (i < 3 * DIM * DIM) g_wq[i] = __float2half_rn(qkv_w[i]);
    if (i < DIM * DIM)     g_wp[i] = __float2half_rn(proj_w[i]);
}

__global__ void l2_inv() {
    int z = blockIdx.x;
    int col = threadIdx.x;
    float sq = 0.f, sk = 0.f;
#pragma unroll
    for (int c = 0; c < 8; c++) {
        sq += g_part[((size_t)z * 8 + c) * DHd + col];
        sk += g_part[(((size_t)BH + z) * 8 + c) * DHd + col];
    }
    float ivq = 1.f / fmaxf(sqrtf(sq), 1e-12f);
    float ivk = 1.f / fmaxf(sqrtf(sk), 1e-12f);
    g_inv[(size_t)z * DHd + col] = ivq * ivk;
}

// LN apply + residual + layout restore; per-row stats computed from LN
// partials in-block (ln_combine fused).
__global__ void ln_apply(const float* __restrict__ x,
                         const float* __restrict__ gamma,
                         const float* __restrict__ beta) {
    __shared__ float tile[32][33];
    __shared__ float smu[32], srs[32];
    int bz = blockIdx.z, hw0 = blockIdx.y * 32, cd0 = blockIdx.x * 32;
    int tx = threadIdx.x, ty = threadIdx.y;

    if (ty == 0) {
        int row = bz * 1024 + hw0 + tx;
        float s = 0.f, qq = 0.f;
#pragma unroll
        for (int i = 0; i < 6; i++) {
            s  += g_psum[(size_t)row * 6 + i];
            qq += g_psq [(size_t)row * 6 + i];
        }
        float mu = s * (1.f / DIM);
        float var = fmaxf(qq * (1.f / DIM) - mu * mu, 0.f);
        smu[tx] = mu;
        srs[tx] = rsqrtf(var + 1e-5f);
    }
    __syncthreads();

#pragma unroll
    for (int k = 0; k < 4; k++) {
        int hwl = ty + 8 * k;
        int row = bz * 1024 + hw0 + hwl;
        int cd = cd0 + tx;
        float v = g_proj[(size_t)row * 768 + cd];
        tile[hwl][tx] = (v - smu[hwl]) * srs[hwl] * gamma[cd] + beta[cd];
    }
    __syncthreads();
#pragma unroll
    for (int k = 0; k < 4; k++) {
        int cd = cd0 + ty + 8 * k;
        int hw = hw0 + tx;
        size_t oi = ((size_t)bz * 768 + cd) * 1024 + hw;
        g_y[oi] = tile[tx][ty + 8 * k] + x[oi];
    }
}

__global__ __launch_bounds__(1024) void dwconv(const float* __restrict__ dw_w,
                                               const float* __restrict__ dw_b) {
    __shared__ float tile[3][34][34];
    __shared__ float wsh[27];
    int bcd = blockIdx.x;
    int d  = bcd & 7;
    int bc = bcd >> 3;
    int c  = bc % Cc;
    int tid = threadIdx.x;

    if (tid < 27) wsh[tid] = dw_w[c * 27 + tid];

    for (int idx = tid; idx < 3 * 34 * 34; idx += 1024) {
        int pl = idx / 1156;
        int r  = (idx - pl * 1156) / 34;
        int cc = idx - pl * 1156 - r * 34;
        int dd = d - 1 + pl, hh = r - 1, ww = cc - 1;
        float val = 0.f;
        if (dd >= 0 && dd < Dd && hh >= 0 && hh < Hh && ww >= 0 && ww < Ww)
            val = g_y[(bc * Dd + dd) * HW + hh * Ww + ww];
        tile[pl][r][cc] = val;
    }
    __syncthreads();

    int h = tid >> 5, w = tid & 31;
    float s = 0.f;
#pragma unroll
    for (int pl = 0; pl < 3; pl++)
#pragma unroll
        for (int i = 0; i < 3; i++)
#pragma unroll
            for (int j = 0; j < 3; j++)
                s += tile[pl][h + i][w + j] * wsh[pl * 9 + i * 3 + j];
    g_z[bcd * HW + tid] = s + dw_b[c];
}

__global__ __launch_bounds__(128) void pwconv(const float* __restrict__ pw_w,
                                              const float* __restrict__ pw_b,
                                              float* __restrict__ out) {
    __shared__ float wsh[Cc * Cc];
    int b = blockIdx.y;
    int pos = blockIdx.x * 128 + threadIdx.x;
    constexpr int SP = Dd * HW;

    for (int i = threadIdx.x; i < Cc * Cc; i += 128) wsh[i] = pw_w[i];
    __syncthreads();

    float acc[Cc];
#pragma unroll
    for (int co = 0; co < Cc; co++) acc[co] = 0.f;

    const float* zb = g_z + b * Cc * SP + pos;
    for (int ci = 0; ci < Cc; ci++) {
        float zv = zb[ci * SP];
#pragma unroll
        for (int co = 0; co < Cc; co++) acc[co] += zv * wsh[co * Cc + ci];
    }

    const float* yb = g_y + b * Cc * SP + pos;
    float* ob = out + b * Cc * SP + pos;
#pragma unroll
    for (int co = 0; co < Cc; co++)
        ob[co * SP] = yb[co * SP] + acc[co] + pw_b[co];
}

// ---------------------------------------------------------------------------
// Launch
// ---------------------------------------------------------------------------
extern "C" void kernel_launch(void* const* d_in, const int* in_sizes, int n_in,
                              void* d_out, int out_size) {
    const float* x      = (const float*)d_in[0];
    const float* pos    = (const float*)d_in[1];
    const float* qkv_w  = (const float*)d_in[2];
    const float* proj_w = (const float*)d_in[3];
    const float* proj_b = (const float*)d_in[4];
    const float* temp   = (const float*)d_in[5];
    const float* ln_g   = (const float*)d_in[6];
    const float* ln_b   = (const float*)d_in[7];
    const float* dw_w   = (const float*)d_in[8];
    const float* dw_b   = (const float*)d_in[9];
    const float* pw_w   = (const float*)d_in[10];
    const float* pw_b   = (const float*)d_in[11];
    float* out = (float*)d_out;

    constexpr int SMEMG = 3 * 8192 * 4;              // 96 KB (2 CTAs/SM)
    constexpr int FSMEM = FS_TOT * 4;                // 113 KB
    cudaFuncSetAttribute(tc_gemm<0>, cudaFuncAttributeMaxDynamicSharedMemorySize, SMEMG);
    cudaFuncSetAttribute(tc_gemm<3>, cudaFuncAttributeMaxDynamicSharedMemorySize, SMEMG);
    cudaFuncSetAttribute(flash_attn, cudaFuncAttributeMaxDynamicSharedMemorySize, FSMEM);

    permute_t<<<dim3(24, 32, 8), dim3(32, 8)>>>(x, pos);
    cvt_weights<<<(3 * DIM * DIM + 255) / 256, 256>>>(qkv_w, proj_w);
    tc_gemm<0><<<dim3(18, 64, 1), 256, SMEMG>>>(nullptr);
    l2_inv<<<32, 192>>>();
    flash_attn<<<dim3(16, 32), 256, FSMEM>>>(temp);
    tc_gemm<3><<<dim3(6, 64, 1), 256, SMEMG>>>(proj_b);
    ln_apply<<<dim3(24, 32, 8), dim3(32, 8)>>>(x, ln_g, ln_b);
    dwconv<<<Bn * Cc * Dd, 1024>>>(dw_w, dw_b);
    pwconv<<<dim3(64, Bn, 1), 128>>>(pw_w, pw_b, out);
}